// round 9
// baseline (speedup 1.0000x reference)
#include <cuda_runtime.h>
#include <cuda_bf16.h>
#include <math.h>
#include <stdint.h>

// Problem dims
#define Bz 32
#define Sz 128
#define Ez 512
#define Hz 1024
#define Gz 4096   // 4*H
#define Lz 128
#define Vz 32000
#define TDz 126   // S-2
#define NBLK 128  // persistent grid size

// ---------------- scratch (device globals; no runtime allocation) ----------------
__device__ float g_Pe[(size_t)Sz * Bz * Gz];
__device__ float g_hse[(Sz + 1) * Bz * Hz];
__device__ float g_Pd[(size_t)4096 * Gz];          // padded to 4096 rows
__device__ float g_hsd[(TDz + 1) * Bz * Hz];
__device__ unsigned g_bar;
// bf16 split buffers
__device__ __nv_bfloat16 g_Whi[(size_t)Vz * Hz];
__device__ __nv_bfloat16 g_Wlo[(size_t)Vz * Hz];
__device__ __nv_bfloat16 g_Ahi[4096 * Hz];
__device__ __nv_bfloat16 g_Alo[4096 * Hz];
__device__ __nv_bfloat16 g_Xeh[4096 * Ez];
__device__ __nv_bfloat16 g_Xel[4096 * Ez];
__device__ __nv_bfloat16 g_Xdh[4096 * Ez];         // rows >= 4032 stay zero (BSS)
__device__ __nv_bfloat16 g_Xdl[4096 * Ez];
__device__ __nv_bfloat16 g_Wieh[Gz * Ez];
__device__ __nv_bfloat16 g_Wiel[Gz * Ez];
__device__ __nv_bfloat16 g_Widh[Gz * Ez];
__device__ __nv_bfloat16 g_Widl[Gz * Ez];

// ---------------- f32x2 helpers ----------------
__device__ __forceinline__ unsigned long long pk2(float x, float y) {
    unsigned long long r;
    asm("mov.b64 %0, {%1,%2};" : "=l"(r) : "f"(x), "f"(y));
    return r;
}
__device__ __forceinline__ float2 upk2(unsigned long long v) {
    float2 r;
    asm("mov.b64 {%0,%1}, %2;" : "=f"(r.x), "=f"(r.y) : "l"(v));
    return r;
}
__device__ __forceinline__ unsigned long long ffma2(unsigned long long a, unsigned long long b,
                                                    unsigned long long c) {
    unsigned long long d;
    asm("fma.rn.f32x2 %0, %1, %2, %3;" : "=l"(d) : "l"(a), "l"(b), "l"(c));
    return d;
}
__device__ __forceinline__ float sigm(float x) { return 1.0f / (1.0f + expf(-x)); }

__device__ __forceinline__ uint32_t smem_u32(const void* p) {
    uint32_t a;
    asm("{ .reg .u64 t; cvta.to.shared.u64 t, %1; cvt.u32.u64 %0, t; }" : "=r"(a) : "l"(p));
    return a;
}

// ---------------- mma.sync + cp.async helpers (compute_103-safe PTX) ----------------
#define LDSM4(d, addr) \
    asm volatile("ldmatrix.sync.aligned.m8n8.x4.shared.b16 {%0,%1,%2,%3}, [%4];" \
        : "=r"((d)[0]), "=r"((d)[1]), "=r"((d)[2]), "=r"((d)[3]) : "r"(addr))

#define MMA16816(c, a, b) \
    asm volatile("mma.sync.aligned.m16n8k16.row.col.f32.bf16.bf16.f32 " \
        "{%0,%1,%2,%3}, {%4,%5,%6,%7}, {%8,%9}, {%0,%1,%2,%3};" \
        : "+f"((c)[0]), "+f"((c)[1]), "+f"((c)[2]), "+f"((c)[3]) \
        : "r"((a)[0]), "r"((a)[1]), "r"((a)[2]), "r"((a)[3]), "r"((b)[0]), "r"((b)[1]))

#define CP_ASYNC16(smaddr, gptr) \
    asm volatile("cp.async.cg.shared.global [%0], [%1], 16;" :: "r"(smaddr), "l"(gptr))
#define CP_ASYNC4(smaddr, gptr) \
    asm volatile("cp.async.ca.shared.global [%0], [%1], 4;" :: "r"(smaddr), "l"(gptr))
#define CP_COMMIT() asm volatile("cp.async.commit_group;" ::: "memory")
#define CP_WAIT0()  asm volatile("cp.async.wait_group 0;" ::: "memory")

// ---------------- grid barrier (release-RED + acquire poll) ----------------
__device__ __forceinline__ void grid_sync_(unsigned target) {
    __syncthreads();
    if (threadIdx.x == 0) {
        asm volatile("red.release.gpu.global.add.u32 [%0], %1;" :: "l"(&g_bar), "r"(1u) : "memory");
        unsigned v;
        do {
            asm volatile("ld.global.acquire.gpu.u32 %0, [%1];" : "=r"(v) : "l"(&g_bar));
        } while (v < target);
    }
    __syncthreads();
}

// ---------------- init ----------------
__global__ void init_kernel(float* __restrict__ h0, int n) {
    int i = blockIdx.x * blockDim.x + threadIdx.x;
    int stride = gridDim.x * blockDim.x;
    for (; i < n; i += stride) h0[i] = 0.0f;
    if (blockIdx.x == 0 && threadIdx.x == 0) g_bar = 0u;
}

// ---------------- embedding gather fused with bf16 hi/lo split ----------------
__global__ void embed_split_kernel(const int* __restrict__ tokens, const float* __restrict__ emb,
                                   __nv_bfloat16* __restrict__ hi, __nv_bfloat16* __restrict__ lo,
                                   int T, int toff) {
    int total4 = T * Bz * (Ez / 4);
    int i = blockIdx.x * blockDim.x + threadIdx.x;
    int stride = gridDim.x * blockDim.x;
    const int E4 = Ez / 4;
    for (; i < total4; i += stride) {
        int e4 = i % E4;
        int r  = i / E4;
        int b  = r % Bz;
        int t  = r / Bz;
        int tok = tokens[b * Sz + t + toff];
        float4 v = ((const float4*)(emb + (size_t)tok * Ez))[e4];
        __nv_bfloat16 h0 = __float2bfloat16(v.x);
        __nv_bfloat16 h1 = __float2bfloat16(v.y);
        __nv_bfloat16 h2 = __float2bfloat16(v.z);
        __nv_bfloat16 h3 = __float2bfloat16(v.w);
        __nv_bfloat162 ha; ha.x = h0; ha.y = h1;
        __nv_bfloat162 hb; hb.x = h2; hb.y = h3;
        ((__nv_bfloat162*)hi)[i * 2]     = ha;
        ((__nv_bfloat162*)hi)[i * 2 + 1] = hb;
        __nv_bfloat162 la, lb;
        la.x = __float2bfloat16(v.x - __bfloat162float(h0));
        la.y = __float2bfloat16(v.y - __bfloat162float(h1));
        lb.x = __float2bfloat16(v.z - __bfloat162float(h2));
        lb.y = __float2bfloat16(v.w - __bfloat162float(h3));
        ((__nv_bfloat162*)lo)[i * 2]     = la;
        ((__nv_bfloat162*)lo)[i * 2 + 1] = lb;
    }
}

// ---------------- generic bf16 hi/lo split ----------------
__global__ void convert_w_kernel(const float* __restrict__ W, __nv_bfloat16* __restrict__ hi,
                                 __nv_bfloat16* __restrict__ lo, int n4) {
    int i = blockIdx.x * blockDim.x + threadIdx.x;
    int stride = gridDim.x * blockDim.x;
    for (; i < n4; i += stride) {
        float4 v = ((const float4*)W)[i];
        __nv_bfloat16 h0 = __float2bfloat16(v.x);
        __nv_bfloat16 h1 = __float2bfloat16(v.y);
        __nv_bfloat16 h2 = __float2bfloat16(v.z);
        __nv_bfloat16 h3 = __float2bfloat16(v.w);
        __nv_bfloat162 ha; ha.x = h0; ha.y = h1;
        __nv_bfloat162 hb; hb.x = h2; hb.y = h3;
        ((__nv_bfloat162*)hi)[i * 2]     = ha;
        ((__nv_bfloat162*)hi)[i * 2 + 1] = hb;
        __nv_bfloat162 la, lb;
        la.x = __float2bfloat16(v.x - __bfloat162float(h0));
        la.y = __float2bfloat16(v.y - __bfloat162float(h1));
        lb.x = __float2bfloat16(v.z - __bfloat162float(h2));
        lb.y = __float2bfloat16(v.w - __bfloat162float(h3));
        ((__nv_bfloat162*)lo)[i * 2]     = la;
        ((__nv_bfloat162*)lo)[i * 2 + 1] = lb;
    }
}

// A row m (= t*Bz+b) = hsd[(m+32)*Hz + k]; rows >= 4032 zero-padded
__global__ void convert_a_kernel(const float* __restrict__ hsd, __nv_bfloat16* __restrict__ hi,
                                 __nv_bfloat16* __restrict__ lo) {
    int n4 = 4096 * Hz / 4;
    int i = blockIdx.x * blockDim.x + threadIdx.x;
    int stride = gridDim.x * blockDim.x;
    for (; i < n4; i += stride) {
        int e = i * 4;
        int m = e >> 10;
        int k = e & 1023;
        float4 v = make_float4(0.f, 0.f, 0.f, 0.f);
        if (m < TDz * Bz) v = *(const float4*)(hsd + (size_t)(m + 32) * Hz + k);
        __nv_bfloat16 h0 = __float2bfloat16(v.x);
        __nv_bfloat16 h1 = __float2bfloat16(v.y);
        __nv_bfloat16 h2 = __float2bfloat16(v.z);
        __nv_bfloat16 h3 = __float2bfloat16(v.w);
        __nv_bfloat162 ha; ha.x = h0; ha.y = h1;
        __nv_bfloat162 hb; hb.x = h2; hb.y = h3;
        ((__nv_bfloat162*)hi)[i * 2]     = ha;
        ((__nv_bfloat162*)hi)[i * 2 + 1] = hb;
        __nv_bfloat162 la, lb;
        la.x = __float2bfloat16(v.x - __bfloat162float(h0));
        la.y = __float2bfloat16(v.y - __bfloat162float(h1));
        lb.x = __float2bfloat16(v.z - __bfloat162float(h2));
        lb.y = __float2bfloat16(v.w - __bfloat162float(h3));
        ((__nv_bfloat162*)lo)[i * 2]     = la;
        ((__nv_bfloat162*)lo)[i * 2 + 1] = lb;
    }
}

// ---------------- bf16 3-split mma GEMM (cp.async, occupancy 2) ----------------
#define SSTR   80
#define SA_HI  0
#define SA_LO  10240
#define SB_HI  20480
#define SB_LO  30720
#define STAGE  40960
#define SBIAS  (2 * STAGE)
#define SMEM_MMA (2 * STAGE + 512)

template <int KDIM, int MODE>
__global__ __launch_bounds__(256, 2)
void mma3_kernel(const __nv_bfloat16* __restrict__ Ahi, const __nv_bfloat16* __restrict__ Alo,
                 const __nv_bfloat16* __restrict__ Whi, const __nv_bfloat16* __restrict__ Wlo,
                 const float* __restrict__ bias1, const float* __restrict__ bias2,
                 float* __restrict__ out, int Nout) {
    extern __shared__ char smem[];
    const uint32_t sbase = smem_u32(smem);
    const int tid = threadIdx.x;
    const int w = tid >> 5, lane = tid & 31;
    const int mtile = blockIdx.x;
    const int ntile = blockIdx.y;
    const int wm = (w & 1) * 64;
    const int wn = (w >> 1) * 32;

    if (tid < 128) {
        float bv = bias1[ntile * 128 + tid];
        if (MODE == 1) bv += bias2[ntile * 128 + tid];
        ((float*)(smem + SBIAS))[tid] = bv;
    }

    const int row = tid >> 2;
    const int ko  = (tid & 3) * 8;
    const __nv_bfloat16* gA0h = Ahi + (size_t)(mtile * 128 + row) * KDIM + ko;
    const __nv_bfloat16* gA1h = Ahi + (size_t)(mtile * 128 + row + 64) * KDIM + ko;
    const __nv_bfloat16* gA0l = Alo + (size_t)(mtile * 128 + row) * KDIM + ko;
    const __nv_bfloat16* gA1l = Alo + (size_t)(mtile * 128 + row + 64) * KDIM + ko;
    const __nv_bfloat16* gB0h = Whi + (size_t)(ntile * 128 + row) * KDIM + ko;
    const __nv_bfloat16* gB1h = Whi + (size_t)(ntile * 128 + row + 64) * KDIM + ko;
    const __nv_bfloat16* gB0l = Wlo + (size_t)(ntile * 128 + row) * KDIM + ko;
    const __nv_bfloat16* gB1l = Wlo + (size_t)(ntile * 128 + row + 64) * KDIM + ko;
    const uint32_t s0 = sbase + row * SSTR + ko * 2;
    const uint32_t s1 = sbase + (row + 64) * SSTR + ko * 2;

    const uint32_t aLane = sbase + (uint32_t)(wm + (lane & 15)) * SSTR + (uint32_t)(lane >> 4) * 16;
    const uint32_t bLane = sbase + (uint32_t)(wn + (lane & 7) + ((lane >> 4) << 3)) * SSTR +
                           (uint32_t)((lane >> 3) & 1) * 16;

    float acc[4][4][4];
#pragma unroll
    for (int i = 0; i < 4; i++)
#pragma unroll
        for (int j = 0; j < 4; j++)
#pragma unroll
            for (int q = 0; q < 4; q++) acc[i][j][q] = 0.f;

    CP_ASYNC16(s0 + SA_HI, gA0h); CP_ASYNC16(s1 + SA_HI, gA1h);
    CP_ASYNC16(s0 + SA_LO, gA0l); CP_ASYNC16(s1 + SA_LO, gA1l);
    CP_ASYNC16(s0 + SB_HI, gB0h); CP_ASYNC16(s1 + SB_HI, gB1h);
    CP_ASYNC16(s0 + SB_LO, gB0l); CP_ASYNC16(s1 + SB_LO, gB1l);
    CP_COMMIT();
    CP_WAIT0();
    __syncthreads();

    const int NT = KDIM / 32;
    for (int kt = 0; kt < NT; kt++) {
        const uint32_t stg = (uint32_t)(kt & 1) * STAGE;

        if (kt < NT - 1) {
            const uint32_t nstg = (uint32_t)((kt + 1) & 1) * STAGE;
            const int go = (kt + 1) * 32;
            CP_ASYNC16(s0 + nstg + SA_HI, gA0h + go); CP_ASYNC16(s1 + nstg + SA_HI, gA1h + go);
            CP_ASYNC16(s0 + nstg + SA_LO, gA0l + go); CP_ASYNC16(s1 + nstg + SA_LO, gA1l + go);
            CP_ASYNC16(s0 + nstg + SB_HI, gB0h + go); CP_ASYNC16(s1 + nstg + SB_HI, gB1h + go);
            CP_ASYNC16(s0 + nstg + SB_LO, gB0l + go); CP_ASYNC16(s1 + nstg + SB_LO, gB1l + go);
            CP_COMMIT();
        }

#pragma unroll
        for (int ks = 0; ks < 2; ks++) {
            const uint32_t kofs = (uint32_t)ks * 32;
            uint32_t bH[4][2], bL[4][2];
#pragma unroll
            for (int nb2 = 0; nb2 < 2; nb2++) {
                uint32_t bd = stg + bLane + (uint32_t)nb2 * (16 * SSTR) + kofs;
                uint32_t t4[4];
                LDSM4(t4, bd + SB_HI);
                bH[nb2 * 2][0] = t4[0]; bH[nb2 * 2][1] = t4[1];
                bH[nb2 * 2 + 1][0] = t4[2]; bH[nb2 * 2 + 1][1] = t4[3];
                LDSM4(t4, bd + SB_LO);
                bL[nb2 * 2][0] = t4[0]; bL[nb2 * 2][1] = t4[1];
                bL[nb2 * 2 + 1][0] = t4[2]; bL[nb2 * 2 + 1][1] = t4[3];
            }
#pragma unroll
            for (int ma = 0; ma < 4; ma++) {
                uint32_t ad = stg + aLane + (uint32_t)ma * (16 * SSTR) + kofs;
                uint32_t aH[4], aL[4];
                LDSM4(aH, ad + SA_HI);
                LDSM4(aL, ad + SA_LO);
#pragma unroll
                for (int nb = 0; nb < 4; nb++) {
                    MMA16816(acc[ma][nb], aH, bH[nb]);
                    MMA16816(acc[ma][nb], aH, bL[nb]);
                    MMA16816(acc[ma][nb], aL, bH[nb]);
                }
            }
        }

        CP_WAIT0();
        __syncthreads();
    }

    const float* sb = (const float*)(smem + SBIAS);
#pragma unroll
    for (int ma = 0; ma < 4; ma++) {
        const int m0 = mtile * 128 + wm + ma * 16 + (lane >> 2);
#pragma unroll
        for (int nb = 0; nb < 4; nb++) {
            const int cl = wn + nb * 8 + (lane & 3) * 2;
            const float b0v = sb[cl], b1v = sb[cl + 1];
            const size_t col = (size_t)(ntile * 128 + cl);
            if (MODE == 0) {
                if (m0 < TDz * Bz) {
                    int orow = (m0 & 31) * TDz + (m0 >> 5);
                    float2 v;
                    v.x = acc[ma][nb][0] + b0v;
                    v.y = acc[ma][nb][1] + b1v;
                    *(float2*)(out + (size_t)orow * Nout + col) = v;
                }
                const int m1 = m0 + 8;
                if (m1 < TDz * Bz) {
                    int orow = (m1 & 31) * TDz + (m1 >> 5);
                    float2 v;
                    v.x = acc[ma][nb][2] + b0v;
                    v.y = acc[ma][nb][3] + b1v;
                    *(float2*)(out + (size_t)orow * Nout + col) = v;
                }
            } else {
                float2 v;
                v.x = acc[ma][nb][0] + b0v;
                v.y = acc[ma][nb][1] + b1v;
                *(float2*)(out + (size_t)m0 * Nout + col) = v;
                v.x = acc[ma][nb][2] + b0v;
                v.y = acc[ma][nb][3] + b1v;
                *(float2*)(out + (size_t)(m0 + 8) * Nout + col) = v;
            }
        }
    }
}

// ---------------- persistent LSTM building blocks ----------------
__device__ __forceinline__ void load_w(const float* __restrict__ Whh, int u, int lane,
                                       unsigned long long (&w2)[4][8][2]) {
#pragma unroll
    for (int r = 0; r < 4; r++) {
        const float4* wr = (const float4*)(Whh + (size_t)(r * Hz + u) * Hz);
#pragma unroll
        for (int j = 0; j < 8; j++) {
            float4 v = wr[j * 32 + lane];
            w2[r][j][0] = pk2(v.x, v.y);
            w2[r][j][1] = pk2(v.z, v.w);
        }
    }
}

// dot over register-resident h
__device__ __forceinline__ void dot4r(const unsigned long long (&w2)[4][8][2],
                                      const ulonglong2 (&hv)[8],
                                      unsigned long long (&acc)[4]) {
#pragma unroll
    for (int r = 0; r < 4; r++) acc[r] = 0ull;
#pragma unroll
    for (int j = 0; j < 8; j++) {
#pragma unroll
        for (int r = 0; r < 4; r++) {
            acc[r] = ffma2(w2[r][j][0], hv[j].x, acc[r]);
            acc[r] = ffma2(w2[r][j][1], hv[j].y, acc[r]);
        }
    }
}

__device__ __forceinline__ float reduce4(const unsigned long long (&acc)[4], int lane) {
    float2 p0 = upk2(acc[0]); float v0 = p0.x + p0.y;
    float2 p1 = upk2(acc[1]); float v1 = p1.x + p1.y;
    float2 p2 = upk2(acc[2]); float v2 = p2.x + p2.y;
    float2 p3 = upk2(acc[3]); float v3 = p3.x + p3.y;
    v0 += __shfl_xor_sync(0xffffffffu, v0, 1);
    v1 += __shfl_xor_sync(0xffffffffu, v1, 1);
    v2 += __shfl_xor_sync(0xffffffffu, v2, 1);
    v3 += __shfl_xor_sync(0xffffffffu, v3, 1);
    float a  = (lane & 1) ? v1 : v0;
    float bb = (lane & 1) ? v3 : v2;
    a  += __shfl_xor_sync(0xffffffffu, a, 2);
    bb += __shfl_xor_sync(0xffffffffu, bb, 2);
    float m = (lane & 2) ? bb : a;
    m += __shfl_xor_sync(0xffffffffu, m, 4);
    m += __shfl_xor_sync(0xffffffffu, m, 8);
    m += __shfl_xor_sync(0xffffffffu, m, 16);
    return m;
}

__device__ __forceinline__ float lstm_step_p(
    const unsigned long long (&w2)[4][8][2],
    const float* __restrict__ P, const float* __restrict__ hin,
    float* __restrict__ hout, float creg,
    float* __restrict__ sgf, float* __restrict__ sPf, uint32_t sPf_addr,
    int u0, int tid, int w, int lane)
{
    // P prefetch via cp.async (consumed only in the epilogue)
#pragma unroll
    for (int k = 0; k < 4; k++) {
        int idx = tid + k * 256;
        int b = idx >> 5, c = idx & 31;
        CP_ASYNC4(sPf_addr + (uint32_t)(b * 33 + c) * 4,
                  P + (size_t)b * Gz + (c >> 3) * Hz + u0 + (c & 7));
    }
    CP_COMMIT();

    const ulonglong2* h4 = (const ulonglong2*)hin;
    ulonglong2 hv[8];
#pragma unroll
    for (int j = 0; j < 8; j++) hv[j] = h4[j * 32 + lane];      // batch 0

    unsigned long long acc[2][4];
    dot4r(w2, hv, acc[0]);
#pragma unroll
    for (int j = 0; j < 8; j++) hv[j] = h4[256 + j * 32 + lane]; // prefetch batch 1

#pragma unroll 2
    for (int b = 1; b < Bz; b++) {
        // reduce previous batch (its shfl-chain latency overlaps hv prefetch LDGs)
        float m = reduce4(acc[(b - 1) & 1], lane);
        if (lane < 4) sgf[w * 132 + (b - 1) * 4 + lane] = m;
        // consume prefetched h
        dot4r(w2, hv, acc[b & 1]);
        // prefetch next batch
        if (b + 1 < Bz) {
#pragma unroll
            for (int j = 0; j < 8; j++) hv[j] = h4[(b + 1) * 256 + j * 32 + lane];
        }
    }
    {
        float m = reduce4(acc[(Bz - 1) & 1], lane);
        if (lane < 4) sgf[w * 132 + (Bz - 1) * 4 + lane] = m;
    }
    CP_WAIT0();
    __syncthreads();

    int ul = tid & 7, b = tid >> 3;
    float gi = sgf[ul * 132 + b * 4 + 0] + sPf[b * 33 +  0 + ul];
    float gf = sgf[ul * 132 + b * 4 + 1] + sPf[b * 33 +  8 + ul];
    float gg = sgf[ul * 132 + b * 4 + 2] + sPf[b * 33 + 16 + ul];
    float go = sgf[ul * 132 + b * 4 + 3] + sPf[b * 33 + 24 + ul];
    float cc = sigm(gf) * creg + sigm(gi) * tanhf(gg);
    float hh = sigm(go) * tanhf(cc);
    hout[b * Hz + u0 + ul] = hh;
    return cc;
}

__device__ void latent_dev(int b, int tid,
                           const int* __restrict__ tokens, const float* __restrict__ hs,
                           const float* __restrict__ Wmu, const float* __restrict__ bmu,
                           const float* __restrict__ Wlv, const float* __restrict__ blv,
                           const float* __restrict__ eps,
                           const float* __restrict__ Wl2h, const float* __restrict__ bl2h,
                           float* __restrict__ out_mean, float* __restrict__ out_lv,
                           float* __restrict__ hd0,
                           int* __restrict__ scnt, float* __restrict__ smean,
                           float* __restrict__ slv, float* __restrict__ szv) {
    int cnt = 0;
    if (tid < Sz) cnt = (tokens[b * Sz + tid] != 0) ? 1 : 0;
    scnt[tid] = cnt;
    __syncthreads();
    for (int off = 128; off >= 1; off >>= 1) {
        if (tid < off) scnt[tid] += scnt[tid + off];
        __syncthreads();
    }
    int last = scnt[0] - 1;
    if (last < 0) last = 0;

    const float* lh = hs + (size_t)(last + 1) * Bz * Hz + (size_t)b * Hz;
    {
        int j = tid & 127;
        const float* Wr = ((tid < 128) ? Wmu : Wlv) + (size_t)j * Hz;
        float acc = 0.f;
        const float4* l4 = (const float4*)lh;
        const float4* w4 = (const float4*)Wr;
#pragma unroll 4
        for (int k = 0; k < Hz / 4; k++) {
            float4 a = l4[k];
            float4 ww = w4[k];
            acc += a.x * ww.x + a.y * ww.y + a.z * ww.z + a.w * ww.w;
        }
        if (tid < 128) smean[j] = acc + bmu[j];
        else           slv[j]   = acc + blv[j];
    }
    __syncthreads();

    if (tid < 128) {
        float m = smean[tid];
        float lv = slv[tid];
        out_mean[b * Lz + tid] = m;
        out_lv[b * Lz + tid] = lv;
        szv[tid] = m + eps[b * Lz + tid] * expf(0.5f * lv);
    }
    __syncthreads();

#pragma unroll
    for (int r = 0; r < 4; r++) {
        int u = tid + r * 256;
        float acc = bl2h[u];
        const float* wr = Wl2h + (size_t)u * Lz;
#pragma unroll 4
        for (int l = 0; l < Lz; l++) acc += szv[l] * wr[l];
        hd0[b * Hz + u] = acc;
    }
}

__global__ __launch_bounds__(256, 1)
void lstm_persistent(const float* __restrict__ Whh_e, const float* __restrict__ Whh_d,
                     const float* __restrict__ Pe, const float* __restrict__ Pd,
                     float* __restrict__ hse, float* __restrict__ hsd,
                     const int* __restrict__ tokens,
                     const float* __restrict__ Wmu, const float* __restrict__ bmu,
                     const float* __restrict__ Wlv, const float* __restrict__ blv,
                     const float* __restrict__ eps,
                     const float* __restrict__ Wl2h, const float* __restrict__ bl2h,
                     float* __restrict__ out_mean, float* __restrict__ out_lv) {
    const int tid = threadIdx.x;
    const int w = tid >> 5;
    const int lane = tid & 31;
    const int u0 = blockIdx.x * 8;
    const int u = u0 + w;

    __shared__ float sgf[8 * 132];
    __shared__ float sPf[32 * 33];
    __shared__ int   scnt[256];
    __shared__ float smean[128], slvs[128], szv[128];
    const uint32_t sPf_addr = smem_u32(sPf);

    unsigned long long w2[4][8][2];
    load_w(Whh_e, u, lane, w2);

    float creg = 0.f;
    unsigned epoch = 0;

    for (int t = 0; t < Sz; t++) {
        creg = lstm_step_p(w2, Pe + (size_t)t * Bz * Gz,
                           hse + (size_t)t * Bz * Hz,
                           hse + (size_t)(t + 1) * Bz * Hz,
                           creg, sgf, sPf, sPf_addr, u0, tid, w, lane);
        epoch++;
        grid_sync_(epoch * NBLK);
    }

    load_w(Whh_d, u, lane, w2);
    if (blockIdx.x < 32) {
        latent_dev(blockIdx.x, tid, tokens, hse, Wmu, bmu, Wlv, blv, eps,
                   Wl2h, bl2h, out_mean, out_lv, hsd,
                   scnt, smean, slvs, szv);
    }
    epoch++;
    grid_sync_(epoch * NBLK);

    creg = 0.f;
    for (int t = 0; t < TDz; t++) {
        creg = lstm_step_p(w2, Pd + (size_t)t * Bz * Gz,
                           hsd + (size_t)t * Bz * Hz,
                           hsd + (size_t)(t + 1) * Bz * Hz,
                           creg, sgf, sPf, sPf_addr, u0, tid, w, lane);
        if (t < TDz - 1) {
            epoch++;
            grid_sync_(epoch * NBLK);
        }
    }
}

// ---------------- launch ----------------
extern "C" void kernel_launch(void* const* d_in, const int* in_sizes, int n_in,
                              void* d_out, int out_size) {
    const int*   tokens  = (const int*)d_in[0];
    const float* emb_enc = (const float*)d_in[1];
    const float* Wih_e   = (const float*)d_in[2];
    const float* Whh_e   = (const float*)d_in[3];
    const float* bih_e   = (const float*)d_in[4];
    const float* bhh_e   = (const float*)d_in[5];
    const float* W_mu    = (const float*)d_in[6];
    const float* b_mu    = (const float*)d_in[7];
    const float* W_lv    = (const float*)d_in[8];
    const float* b_lv    = (const float*)d_in[9];
    const float* emb_dec = (const float*)d_in[10];
    const float* W_l2h   = (const float*)d_in[11];
    const float* b_l2h   = (const float*)d_in[12];
    const float* Wih_d   = (const float*)d_in[13];
    const float* Whh_d   = (const float*)d_in[14];
    const float* bih_d   = (const float*)d_in[15];
    const float* bhh_d   = (const float*)d_in[16];
    const float* W_out   = (const float*)d_in[17];
    const float* b_out   = (const float*)d_in[18];
    const float* epsv    = (const float*)d_in[19];

    float* out = (float*)d_out;
    const size_t LOGITS = (size_t)Bz * TDz * Vz;
    float* out_logits = out;
    float* out_mean   = out + LOGITS;
    float* out_lv     = out + LOGITS + (size_t)Bz * Lz;

    float *p_Pe, *p_hse, *p_Pd, *p_hsd;
    __nv_bfloat16 *p_Whi, *p_Wlo, *p_Ahi, *p_Alo;
    __nv_bfloat16 *p_Xeh, *p_Xel, *p_Xdh, *p_Xdl;
    __nv_bfloat16 *p_Wieh, *p_Wiel, *p_Widh, *p_Widl;
    cudaGetSymbolAddress((void**)&p_Pe,  g_Pe);
    cudaGetSymbolAddress((void**)&p_hse, g_hse);
    cudaGetSymbolAddress((void**)&p_Pd,  g_Pd);
    cudaGetSymbolAddress((void**)&p_hsd, g_hsd);
    cudaGetSymbolAddress((void**)&p_Whi, g_Whi);
    cudaGetSymbolAddress((void**)&p_Wlo, g_Wlo);
    cudaGetSymbolAddress((void**)&p_Ahi, g_Ahi);
    cudaGetSymbolAddress((void**)&p_Alo, g_Alo);
    cudaGetSymbolAddress((void**)&p_Xeh, g_Xeh);
    cudaGetSymbolAddress((void**)&p_Xel, g_Xel);
    cudaGetSymbolAddress((void**)&p_Xdh, g_Xdh);
    cudaGetSymbolAddress((void**)&p_Xdl, g_Xdl);
    cudaGetSymbolAddress((void**)&p_Wieh, g_Wieh);
    cudaGetSymbolAddress((void**)&p_Wiel, g_Wiel);
    cudaGetSymbolAddress((void**)&p_Widh, g_Widh);
    cudaGetSymbolAddress((void**)&p_Widl, g_Widl);

    cudaFuncSetAttribute(mma3_kernel<512, 1>, cudaFuncAttributeMaxDynamicSharedMemorySize, SMEM_MMA);
    cudaFuncSetAttribute(mma3_kernel<1024, 0>, cudaFuncAttributeMaxDynamicSharedMemorySize, SMEM_MMA);

    // 1) zero encoder h0 slot; reset grid barrier
    init_kernel<<<64, 256>>>(p_hse, Bz * Hz);

    // 2) embeddings fused with bf16 split
    embed_split_kernel<<<1024, 256>>>(tokens, emb_enc, p_Xeh, p_Xel, Sz, 0);
    embed_split_kernel<<<1024, 256>>>(tokens, emb_dec, p_Xdh, p_Xdl, TDz, 1);

    // 2b) Wih bf16 splits
    convert_w_kernel<<<1024, 256>>>(Wih_e, p_Wieh, p_Wiel, Gz * Ez / 4);
    convert_w_kernel<<<1024, 256>>>(Wih_d, p_Widh, p_Widl, Gz * Ez / 4);

    // 3) input projections via bf16 3-split mma (K=512)
    {
        dim3 grid(32, 32);
        mma3_kernel<512, 1><<<grid, 256, SMEM_MMA>>>(p_Xeh, p_Xel, p_Wieh, p_Wiel,
                                                     bih_e, bhh_e, p_Pe, Gz);
        mma3_kernel<512, 1><<<grid, 256, SMEM_MMA>>>(p_Xdh, p_Xdl, p_Widh, p_Widl,
                                                     bih_d, bhh_d, p_Pd, Gz);
    }

    // 3b) W_out bf16 split
    convert_w_kernel<<<4096, 256>>>(W_out, p_Whi, p_Wlo, (int)((size_t)Vz * Hz / 4));

    // 4+5+6) recurrences + latent head, one persistent kernel
    lstm_persistent<<<NBLK, 256>>>(Whh_e, Whh_d, p_Pe, p_Pd, p_hse, p_hsd,
                                   tokens, W_mu, b_mu, W_lv, b_lv, epsv,
                                   W_l2h, b_l2h, out_mean, out_lv);

    // 6b) hd bf16 split
    convert_a_kernel<<<1024, 256>>>(p_hsd, p_Ahi, p_Alo);

    // 7) logits via bf16 3-split mma (K=1024)
    {
        dim3 grid(32, 250);
        mma3_kernel<1024, 0><<<grid, 256, SMEM_MMA>>>(p_Ahi, p_Alo, p_Whi, p_Wlo,
                                                      b_out, b_out, out_logits, Vz);
    }
}

// round 11
// speedup vs baseline: 1.0677x; 1.0677x over previous
#include <cuda_runtime.h>
#include <cuda_bf16.h>
#include <math.h>
#include <stdint.h>

// Problem dims
#define Bz 32
#define Sz 128
#define Ez 512
#define Hz 1024
#define Gz 4096   // 4*H
#define Lz 128
#define Vz 32000
#define TDz 126   // S-2
#define NBLK 128  // persistent grid size

// ---------------- scratch (device globals; no runtime allocation) ----------------
__device__ float g_Pe[(size_t)Sz * Bz * Gz];
__device__ float g_hse[(Sz + 1) * Bz * Hz];
__device__ float g_Pd[(size_t)4096 * Gz];          // padded to 4096 rows
__device__ float g_hsd[(TDz + 1) * Bz * Hz];
__device__ unsigned g_bar;
// bf16 split buffers
__device__ __nv_bfloat16 g_Whi[(size_t)Vz * Hz];
__device__ __nv_bfloat16 g_Wlo[(size_t)Vz * Hz];
__device__ __nv_bfloat16 g_Ahi[4096 * Hz];
__device__ __nv_bfloat16 g_Alo[4096 * Hz];
__device__ __nv_bfloat16 g_Xeh[4096 * Ez];
__device__ __nv_bfloat16 g_Xel[4096 * Ez];
__device__ __nv_bfloat16 g_Xdh[4096 * Ez];         // rows >= 4032 stay zero (BSS)
__device__ __nv_bfloat16 g_Xdl[4096 * Ez];
__device__ __nv_bfloat16 g_Wieh[Gz * Ez];
__device__ __nv_bfloat16 g_Wiel[Gz * Ez];
__device__ __nv_bfloat16 g_Widh[Gz * Ez];
__device__ __nv_bfloat16 g_Widl[Gz * Ez];

// ---------------- f32x2 helpers ----------------
__device__ __forceinline__ unsigned long long pk2(float x, float y) {
    unsigned long long r;
    asm("mov.b64 %0, {%1,%2};" : "=l"(r) : "f"(x), "f"(y));
    return r;
}
__device__ __forceinline__ float2 upk2(unsigned long long v) {
    float2 r;
    asm("mov.b64 {%0,%1}, %2;" : "=f"(r.x), "=f"(r.y) : "l"(v));
    return r;
}
__device__ __forceinline__ unsigned long long ffma2(unsigned long long a, unsigned long long b,
                                                    unsigned long long c) {
    unsigned long long d;
    asm("fma.rn.f32x2 %0, %1, %2, %3;" : "=l"(d) : "l"(a), "l"(b), "l"(c));
    return d;
}
__device__ __forceinline__ float sigm(float x) { return 1.0f / (1.0f + expf(-x)); }

__device__ __forceinline__ uint32_t smem_u32(const void* p) {
    uint32_t a;
    asm("{ .reg .u64 t; cvta.to.shared.u64 t, %1; cvt.u32.u64 %0, t; }" : "=r"(a) : "l"(p));
    return a;
}

// ---------------- mma.sync + cp.async helpers (compute_103-safe PTX) ----------------
#define LDSM4(d, addr) \
    asm volatile("ldmatrix.sync.aligned.m8n8.x4.shared.b16 {%0,%1,%2,%3}, [%4];" \
        : "=r"((d)[0]), "=r"((d)[1]), "=r"((d)[2]), "=r"((d)[3]) : "r"(addr))

#define MMA16816(c, a, b) \
    asm volatile("mma.sync.aligned.m16n8k16.row.col.f32.bf16.bf16.f32 " \
        "{%0,%1,%2,%3}, {%4,%5,%6,%7}, {%8,%9}, {%0,%1,%2,%3};" \
        : "+f"((c)[0]), "+f"((c)[1]), "+f"((c)[2]), "+f"((c)[3]) \
        : "r"((a)[0]), "r"((a)[1]), "r"((a)[2]), "r"((a)[3]), "r"((b)[0]), "r"((b)[1]))

#define CP_ASYNC16(smaddr, gptr) \
    asm volatile("cp.async.cg.shared.global [%0], [%1], 16;" :: "r"(smaddr), "l"(gptr))
#define CP_COMMIT() asm volatile("cp.async.commit_group;" ::: "memory")
#define CP_WAIT0()  asm volatile("cp.async.wait_group 0;" ::: "memory")

// ---------------- grid barrier ----------------
__device__ __forceinline__ void grid_sync_(unsigned target) {
    __syncthreads();
    if (threadIdx.x == 0) {
        __threadfence();
        atomicAdd(&g_bar, 1u);
        unsigned v;
        do {
            asm volatile("ld.global.acquire.gpu.u32 %0, [%1];" : "=r"(v) : "l"(&g_bar));
        } while (v < target);
    }
    __syncthreads();
}

// ---------------- init ----------------
__global__ void init_kernel(float* __restrict__ h0, int n) {
    int i = blockIdx.x * blockDim.x + threadIdx.x;
    int stride = gridDim.x * blockDim.x;
    for (; i < n; i += stride) h0[i] = 0.0f;
    if (blockIdx.x == 0 && threadIdx.x == 0) g_bar = 0u;
}

// ---------------- embedding gather fused with bf16 hi/lo split ----------------
__global__ void embed_split_kernel(const int* __restrict__ tokens, const float* __restrict__ emb,
                                   __nv_bfloat16* __restrict__ hi, __nv_bfloat16* __restrict__ lo,
                                   int T, int toff) {
    int total4 = T * Bz * (Ez / 4);
    int i = blockIdx.x * blockDim.x + threadIdx.x;
    int stride = gridDim.x * blockDim.x;
    const int E4 = Ez / 4;
    for (; i < total4; i += stride) {
        int e4 = i % E4;
        int r  = i / E4;
        int b  = r % Bz;
        int t  = r / Bz;
        int tok = tokens[b * Sz + t + toff];
        float4 v = ((const float4*)(emb + (size_t)tok * Ez))[e4];
        __nv_bfloat16 h0 = __float2bfloat16(v.x);
        __nv_bfloat16 h1 = __float2bfloat16(v.y);
        __nv_bfloat16 h2 = __float2bfloat16(v.z);
        __nv_bfloat16 h3 = __float2bfloat16(v.w);
        __nv_bfloat162 ha; ha.x = h0; ha.y = h1;
        __nv_bfloat162 hb; hb.x = h2; hb.y = h3;
        ((__nv_bfloat162*)hi)[i * 2]     = ha;
        ((__nv_bfloat162*)hi)[i * 2 + 1] = hb;
        __nv_bfloat162 la, lb;
        la.x = __float2bfloat16(v.x - __bfloat162float(h0));
        la.y = __float2bfloat16(v.y - __bfloat162float(h1));
        lb.x = __float2bfloat16(v.z - __bfloat162float(h2));
        lb.y = __float2bfloat16(v.w - __bfloat162float(h3));
        ((__nv_bfloat162*)lo)[i * 2]     = la;
        ((__nv_bfloat162*)lo)[i * 2 + 1] = lb;
    }
}

// ---------------- generic bf16 hi/lo split ----------------
__global__ void convert_w_kernel(const float* __restrict__ W, __nv_bfloat16* __restrict__ hi,
                                 __nv_bfloat16* __restrict__ lo, int n4) {
    int i = blockIdx.x * blockDim.x + threadIdx.x;
    int stride = gridDim.x * blockDim.x;
    for (; i < n4; i += stride) {
        float4 v = ((const float4*)W)[i];
        __nv_bfloat16 h0 = __float2bfloat16(v.x);
        __nv_bfloat16 h1 = __float2bfloat16(v.y);
        __nv_bfloat16 h2 = __float2bfloat16(v.z);
        __nv_bfloat16 h3 = __float2bfloat16(v.w);
        __nv_bfloat162 ha; ha.x = h0; ha.y = h1;
        __nv_bfloat162 hb; hb.x = h2; hb.y = h3;
        ((__nv_bfloat162*)hi)[i * 2]     = ha;
        ((__nv_bfloat162*)hi)[i * 2 + 1] = hb;
        __nv_bfloat162 la, lb;
        la.x = __float2bfloat16(v.x - __bfloat162float(h0));
        la.y = __float2bfloat16(v.y - __bfloat162float(h1));
        lb.x = __float2bfloat16(v.z - __bfloat162float(h2));
        lb.y = __float2bfloat16(v.w - __bfloat162float(h3));
        ((__nv_bfloat162*)lo)[i * 2]     = la;
        ((__nv_bfloat162*)lo)[i * 2 + 1] = lb;
    }
}

// A row m (= t*Bz+b) = hsd[(m+32)*Hz + k]; rows >= 4032 zero-padded
__global__ void convert_a_kernel(const float* __restrict__ hsd, __nv_bfloat16* __restrict__ hi,
                                 __nv_bfloat16* __restrict__ lo) {
    int n4 = 4096 * Hz / 4;
    int i = blockIdx.x * blockDim.x + threadIdx.x;
    int stride = gridDim.x * blockDim.x;
    for (; i < n4; i += stride) {
        int e = i * 4;
        int m = e >> 10;
        int k = e & 1023;
        float4 v = make_float4(0.f, 0.f, 0.f, 0.f);
        if (m < TDz * Bz) v = *(const float4*)(hsd + (size_t)(m + 32) * Hz + k);
        __nv_bfloat16 h0 = __float2bfloat16(v.x);
        __nv_bfloat16 h1 = __float2bfloat16(v.y);
        __nv_bfloat16 h2 = __float2bfloat16(v.z);
        __nv_bfloat16 h3 = __float2bfloat16(v.w);
        __nv_bfloat162 ha; ha.x = h0; ha.y = h1;
        __nv_bfloat162 hb; hb.x = h2; hb.y = h3;
        ((__nv_bfloat162*)hi)[i * 2]     = ha;
        ((__nv_bfloat162*)hi)[i * 2 + 1] = hb;
        __nv_bfloat162 la, lb;
        la.x = __float2bfloat16(v.x - __bfloat162float(h0));
        la.y = __float2bfloat16(v.y - __bfloat162float(h1));
        lb.x = __float2bfloat16(v.z - __bfloat162float(h2));
        lb.y = __float2bfloat16(v.w - __bfloat162float(h3));
        ((__nv_bfloat162*)lo)[i * 2]     = la;
        ((__nv_bfloat162*)lo)[i * 2 + 1] = lb;
    }
}

// ---------------- bf16 3-split mma GEMM (cp.async, occupancy 2) ----------------
#define SSTR   80
#define SA_HI  0
#define SA_LO  10240
#define SB_HI  20480
#define SB_LO  30720
#define STAGE  40960
#define SBIAS  (2 * STAGE)
#define SMEM_MMA (2 * STAGE + 512)

template <int KDIM, int MODE>
__global__ __launch_bounds__(256, 2)
void mma3_kernel(const __nv_bfloat16* __restrict__ Ahi, const __nv_bfloat16* __restrict__ Alo,
                 const __nv_bfloat16* __restrict__ Whi, const __nv_bfloat16* __restrict__ Wlo,
                 const float* __restrict__ bias1, const float* __restrict__ bias2,
                 float* __restrict__ out, int Nout) {
    extern __shared__ char smem[];
    const uint32_t sbase = smem_u32(smem);
    const int tid = threadIdx.x;
    const int w = tid >> 5, lane = tid & 31;
    const int mtile = blockIdx.x;
    const int ntile = blockIdx.y;
    const int wm = (w & 1) * 64;
    const int wn = (w >> 1) * 32;

    if (tid < 128) {
        float bv = bias1[ntile * 128 + tid];
        if (MODE == 1) bv += bias2[ntile * 128 + tid];
        ((float*)(smem + SBIAS))[tid] = bv;
    }

    const int row = tid >> 2;
    const int ko  = (tid & 3) * 8;
    const __nv_bfloat16* gA0h = Ahi + (size_t)(mtile * 128 + row) * KDIM + ko;
    const __nv_bfloat16* gA1h = Ahi + (size_t)(mtile * 128 + row + 64) * KDIM + ko;
    const __nv_bfloat16* gA0l = Alo + (size_t)(mtile * 128 + row) * KDIM + ko;
    const __nv_bfloat16* gA1l = Alo + (size_t)(mtile * 128 + row + 64) * KDIM + ko;
    const __nv_bfloat16* gB0h = Whi + (size_t)(ntile * 128 + row) * KDIM + ko;
    const __nv_bfloat16* gB1h = Whi + (size_t)(ntile * 128 + row + 64) * KDIM + ko;
    const __nv_bfloat16* gB0l = Wlo + (size_t)(ntile * 128 + row) * KDIM + ko;
    const __nv_bfloat16* gB1l = Wlo + (size_t)(ntile * 128 + row + 64) * KDIM + ko;
    const uint32_t s0 = sbase + row * SSTR + ko * 2;
    const uint32_t s1 = sbase + (row + 64) * SSTR + ko * 2;

    const uint32_t aLane = sbase + (uint32_t)(wm + (lane & 15)) * SSTR + (uint32_t)(lane >> 4) * 16;
    const uint32_t bLane = sbase + (uint32_t)(wn + (lane & 7) + ((lane >> 4) << 3)) * SSTR +
                           (uint32_t)((lane >> 3) & 1) * 16;

    float acc[4][4][4];
#pragma unroll
    for (int i = 0; i < 4; i++)
#pragma unroll
        for (int j = 0; j < 4; j++)
#pragma unroll
            for (int q = 0; q < 4; q++) acc[i][j][q] = 0.f;

    CP_ASYNC16(s0 + SA_HI, gA0h); CP_ASYNC16(s1 + SA_HI, gA1h);
    CP_ASYNC16(s0 + SA_LO, gA0l); CP_ASYNC16(s1 + SA_LO, gA1l);
    CP_ASYNC16(s0 + SB_HI, gB0h); CP_ASYNC16(s1 + SB_HI, gB1h);
    CP_ASYNC16(s0 + SB_LO, gB0l); CP_ASYNC16(s1 + SB_LO, gB1l);
    CP_COMMIT();
    CP_WAIT0();
    __syncthreads();

    const int NT = KDIM / 32;
    for (int kt = 0; kt < NT; kt++) {
        const uint32_t stg = (uint32_t)(kt & 1) * STAGE;

        if (kt < NT - 1) {
            const uint32_t nstg = (uint32_t)((kt + 1) & 1) * STAGE;
            const int go = (kt + 1) * 32;
            CP_ASYNC16(s0 + nstg + SA_HI, gA0h + go); CP_ASYNC16(s1 + nstg + SA_HI, gA1h + go);
            CP_ASYNC16(s0 + nstg + SA_LO, gA0l + go); CP_ASYNC16(s1 + nstg + SA_LO, gA1l + go);
            CP_ASYNC16(s0 + nstg + SB_HI, gB0h + go); CP_ASYNC16(s1 + nstg + SB_HI, gB1h + go);
            CP_ASYNC16(s0 + nstg + SB_LO, gB0l + go); CP_ASYNC16(s1 + nstg + SB_LO, gB1l + go);
            CP_COMMIT();
        }

#pragma unroll
        for (int ks = 0; ks < 2; ks++) {
            const uint32_t kofs = (uint32_t)ks * 32;
            uint32_t bH[4][2], bL[4][2];
#pragma unroll
            for (int nb2 = 0; nb2 < 2; nb2++) {
                uint32_t bd = stg + bLane + (uint32_t)nb2 * (16 * SSTR) + kofs;
                uint32_t t4[4];
                LDSM4(t4, bd + SB_HI);
                bH[nb2 * 2][0] = t4[0]; bH[nb2 * 2][1] = t4[1];
                bH[nb2 * 2 + 1][0] = t4[2]; bH[nb2 * 2 + 1][1] = t4[3];
                LDSM4(t4, bd + SB_LO);
                bL[nb2 * 2][0] = t4[0]; bL[nb2 * 2][1] = t4[1];
                bL[nb2 * 2 + 1][0] = t4[2]; bL[nb2 * 2 + 1][1] = t4[3];
            }
#pragma unroll
            for (int ma = 0; ma < 4; ma++) {
                uint32_t ad = stg + aLane + (uint32_t)ma * (16 * SSTR) + kofs;
                uint32_t aH[4], aL[4];
                LDSM4(aH, ad + SA_HI);
                LDSM4(aL, ad + SA_LO);
#pragma unroll
                for (int nb = 0; nb < 4; nb++) {
                    MMA16816(acc[ma][nb], aH, bH[nb]);
                    MMA16816(acc[ma][nb], aH, bL[nb]);
                    MMA16816(acc[ma][nb], aL, bH[nb]);
                }
            }
        }

        CP_WAIT0();
        __syncthreads();
    }

    const float* sb = (const float*)(smem + SBIAS);
#pragma unroll
    for (int ma = 0; ma < 4; ma++) {
        const int m0 = mtile * 128 + wm + ma * 16 + (lane >> 2);
#pragma unroll
        for (int nb = 0; nb < 4; nb++) {
            const int cl = wn + nb * 8 + (lane & 3) * 2;
            const float b0v = sb[cl], b1v = sb[cl + 1];
            const size_t col = (size_t)(ntile * 128 + cl);
            if (MODE == 0) {
                if (m0 < TDz * Bz) {
                    int orow = (m0 & 31) * TDz + (m0 >> 5);
                    float2 v;
                    v.x = acc[ma][nb][0] + b0v;
                    v.y = acc[ma][nb][1] + b1v;
                    *(float2*)(out + (size_t)orow * Nout + col) = v;
                }
                const int m1 = m0 + 8;
                if (m1 < TDz * Bz) {
                    int orow = (m1 & 31) * TDz + (m1 >> 5);
                    float2 v;
                    v.x = acc[ma][nb][2] + b0v;
                    v.y = acc[ma][nb][3] + b1v;
                    *(float2*)(out + (size_t)orow * Nout + col) = v;
                }
            } else {
                float2 v;
                v.x = acc[ma][nb][0] + b0v;
                v.y = acc[ma][nb][1] + b1v;
                *(float2*)(out + (size_t)m0 * Nout + col) = v;
                v.x = acc[ma][nb][2] + b0v;
                v.y = acc[ma][nb][3] + b1v;
                *(float2*)(out + (size_t)(m0 + 8) * Nout + col) = v;
            }
        }
    }
}

// ---------------- persistent LSTM building blocks ----------------
__device__ __forceinline__ void load_w(const float* __restrict__ Whh, int u, int lane,
                                       unsigned long long (&w2)[4][8][2]) {
#pragma unroll
    for (int r = 0; r < 4; r++) {
        const float4* wr = (const float4*)(Whh + (size_t)(r * Hz + u) * Hz);
#pragma unroll
        for (int j = 0; j < 8; j++) {
            float4 v = wr[j * 32 + lane];
            w2[r][j][0] = pk2(v.x, v.y);
            w2[r][j][1] = pk2(v.z, v.w);
        }
    }
}

// dot over register-resident h
__device__ __forceinline__ void dot4r(const unsigned long long (&w2)[4][8][2],
                                      const ulonglong2 (&hv)[8],
                                      unsigned long long (&acc)[4]) {
#pragma unroll
    for (int r = 0; r < 4; r++) acc[r] = 0ull;
#pragma unroll
    for (int j = 0; j < 8; j++) {
#pragma unroll
        for (int r = 0; r < 4; r++) {
            acc[r] = ffma2(w2[r][j][0], hv[j].x, acc[r]);
            acc[r] = ffma2(w2[r][j][1], hv[j].y, acc[r]);
        }
    }
}

__device__ __forceinline__ float reduce4(const unsigned long long (&acc)[4], int lane) {
    float2 p0 = upk2(acc[0]); float v0 = p0.x + p0.y;
    float2 p1 = upk2(acc[1]); float v1 = p1.x + p1.y;
    float2 p2 = upk2(acc[2]); float v2 = p2.x + p2.y;
    float2 p3 = upk2(acc[3]); float v3 = p3.x + p3.y;
    v0 += __shfl_xor_sync(0xffffffffu, v0, 1);
    v1 += __shfl_xor_sync(0xffffffffu, v1, 1);
    v2 += __shfl_xor_sync(0xffffffffu, v2, 1);
    v3 += __shfl_xor_sync(0xffffffffu, v3, 1);
    float a  = (lane & 1) ? v1 : v0;
    float bb = (lane & 1) ? v3 : v2;
    a  += __shfl_xor_sync(0xffffffffu, a, 2);
    bb += __shfl_xor_sync(0xffffffffu, bb, 2);
    float m = (lane & 2) ? bb : a;
    m += __shfl_xor_sync(0xffffffffu, m, 4);
    m += __shfl_xor_sync(0xffffffffu, m, 8);
    m += __shfl_xor_sync(0xffffffffu, m, 16);
    return m;
}

// one LSTM step: per-batch pipeline = loads(b) -> reduce(b-1) -> dot(b)
__device__ __forceinline__ float lstm_step_p(
    const unsigned long long (&w2)[4][8][2],
    const float* __restrict__ P, const float* __restrict__ hin,
    float* __restrict__ hout, float creg,
    float* __restrict__ sgf, float* __restrict__ sPf,
    int u0, int tid, int w, int lane)
{
    // P gate prefetch into smem (consumed in the epilogue)
#pragma unroll
    for (int k = 0; k < 4; k++) {
        int idx = tid + k * 256;
        int b = idx >> 5, c = idx & 31;
        sPf[b * 33 + c] = P[(size_t)b * Gz + (c >> 3) * Hz + u0 + (c & 7)];
    }

    const ulonglong2* h4 = (const ulonglong2*)hin;
    ulonglong2 hv[8];
#pragma unroll
    for (int j = 0; j < 8; j++) hv[j] = h4[j * 32 + lane];    // batch 0 loads

    unsigned long long acc[2][4];
    dot4r(w2, hv, acc[0]);

#pragma unroll 2
    for (int b = 1; b < Bz; b++) {
        // 1) issue batch b's loads
#pragma unroll
        for (int j = 0; j < 8; j++) hv[j] = h4[b * 256 + j * 32 + lane];
        // 2) reduce batch b-1 while those LDGs are in flight
        float m = reduce4(acc[(b - 1) & 1], lane);
        if (lane < 4) sgf[w * 132 + (b - 1) * 4 + lane] = m;
        // 3) consume batch b's loads (latency now mostly hidden)
        dot4r(w2, hv, acc[b & 1]);
    }
    {
        float m = reduce4(acc[(Bz - 1) & 1], lane);
        if (lane < 4) sgf[w * 132 + (Bz - 1) * 4 + lane] = m;
    }
    __syncthreads();

    int ul = tid & 7, b = tid >> 3;
    float gi = sgf[ul * 132 + b * 4 + 0] + sPf[b * 33 +  0 + ul];
    float gf = sgf[ul * 132 + b * 4 + 1] + sPf[b * 33 +  8 + ul];
    float gg = sgf[ul * 132 + b * 4 + 2] + sPf[b * 33 + 16 + ul];
    float go = sgf[ul * 132 + b * 4 + 3] + sPf[b * 33 + 24 + ul];
    float cc = sigm(gf) * creg + sigm(gi) * tanhf(gg);
    float hh = sigm(go) * tanhf(cc);
    hout[b * Hz + u0 + ul] = hh;
    return cc;
}

__device__ void latent_dev(int b, int tid,
                           const int* __restrict__ tokens, const float* __restrict__ hs,
                           const float* __restrict__ Wmu, const float* __restrict__ bmu,
                           const float* __restrict__ Wlv, const float* __restrict__ blv,
                           const float* __restrict__ eps,
                           const float* __restrict__ Wl2h, const float* __restrict__ bl2h,
                           float* __restrict__ out_mean, float* __restrict__ out_lv,
                           float* __restrict__ hd0,
                           int* __restrict__ scnt, float* __restrict__ smean,
                           float* __restrict__ slv, float* __restrict__ szv) {
    int cnt = 0;
    if (tid < Sz) cnt = (tokens[b * Sz + tid] != 0) ? 1 : 0;
    scnt[tid] = cnt;
    __syncthreads();
    for (int off = 128; off >= 1; off >>= 1) {
        if (tid < off) scnt[tid] += scnt[tid + off];
        __syncthreads();
    }
    int last = scnt[0] - 1;
    if (last < 0) last = 0;

    const float* lh = hs + (size_t)(last + 1) * Bz * Hz + (size_t)b * Hz;
    {
        int j = tid & 127;
        const float* Wr = ((tid < 128) ? Wmu : Wlv) + (size_t)j * Hz;
        float acc = 0.f;
        const float4* l4 = (const float4*)lh;
        const float4* w4 = (const float4*)Wr;
#pragma unroll 4
        for (int k = 0; k < Hz / 4; k++) {
            float4 a = l4[k];
            float4 ww = w4[k];
            acc += a.x * ww.x + a.y * ww.y + a.z * ww.z + a.w * ww.w;
        }
        if (tid < 128) smean[j] = acc + bmu[j];
        else           slv[j]   = acc + blv[j];
    }
    __syncthreads();

    if (tid < 128) {
        float m = smean[tid];
        float lv = slv[tid];
        out_mean[b * Lz + tid] = m;
        out_lv[b * Lz + tid] = lv;
        szv[tid] = m + eps[b * Lz + tid] * expf(0.5f * lv);
    }
    __syncthreads();

#pragma unroll
    for (int r = 0; r < 4; r++) {
        int u = tid + r * 256;
        float acc = bl2h[u];
        const float* wr = Wl2h + (size_t)u * Lz;
#pragma unroll 4
        for (int l = 0; l < Lz; l++) acc += szv[l] * wr[l];
        hd0[b * Hz + u] = acc;
    }
}

__global__ __launch_bounds__(256, 1)
void lstm_persistent(const float* __restrict__ Whh_e, const float* __restrict__ Whh_d,
                     const float* __restrict__ Pe, const float* __restrict__ Pd,
                     float* __restrict__ hse, float* __restrict__ hsd,
                     const int* __restrict__ tokens,
                     const float* __restrict__ Wmu, const float* __restrict__ bmu,
                     const float* __restrict__ Wlv, const float* __restrict__ blv,
                     const float* __restrict__ eps,
                     const float* __restrict__ Wl2h, const float* __restrict__ bl2h,
                     float* __restrict__ out_mean, float* __restrict__ out_lv) {
    const int tid = threadIdx.x;
    const int w = tid >> 5;
    const int lane = tid & 31;
    const int u0 = blockIdx.x * 8;
    const int u = u0 + w;

    __shared__ float sgf[8 * 132];
    __shared__ float sPf[32 * 33];
    __shared__ int   scnt[256];
    __shared__ float smean[128], slvs[128], szv[128];

    unsigned long long w2[4][8][2];
    load_w(Whh_e, u, lane, w2);

    float creg = 0.f;
    unsigned epoch = 0;

    for (int t = 0; t < Sz; t++) {
        creg = lstm_step_p(w2, Pe + (size_t)t * Bz * Gz,
                           hse + (size_t)t * Bz * Hz,
                           hse + (size_t)(t + 1) * Bz * Hz,
                           creg, sgf, sPf, u0, tid, w, lane);
        epoch++;
        grid_sync_(epoch * NBLK);
    }

    load_w(Whh_d, u, lane, w2);
    if (blockIdx.x < 32) {
        latent_dev(blockIdx.x, tid, tokens, hse, Wmu, bmu, Wlv, blv, eps,
                   Wl2h, bl2h, out_mean, out_lv, hsd,
                   scnt, smean, slvs, szv);
    }
    epoch++;
    grid_sync_(epoch * NBLK);

    creg = 0.f;
    for (int t = 0; t < TDz; t++) {
        creg = lstm_step_p(w2, Pd + (size_t)t * Bz * Gz,
                           hsd + (size_t)t * Bz * Hz,
                           hsd + (size_t)(t + 1) * Bz * Hz,
                           creg, sgf, sPf, u0, tid, w, lane);
        if (t < TDz - 1) {
            epoch++;
            grid_sync_(epoch * NBLK);
        }
    }
}

// ---------------- launch ----------------
extern "C" void kernel_launch(void* const* d_in, const int* in_sizes, int n_in,
                              void* d_out, int out_size) {
    const int*   tokens  = (const int*)d_in[0];
    const float* emb_enc = (const float*)d_in[1];
    const float* Wih_e   = (const float*)d_in[2];
    const float* Whh_e   = (const float*)d_in[3];
    const float* bih_e   = (const float*)d_in[4];
    const float* bhh_e   = (const float*)d_in[5];
    const float* W_mu    = (const float*)d_in[6];
    const float* b_mu    = (const float*)d_in[7];
    const float* W_lv    = (const float*)d_in[8];
    const float* b_lv    = (const float*)d_in[9];
    const float* emb_dec = (const float*)d_in[10];
    const float* W_l2h   = (const float*)d_in[11];
    const float* b_l2h   = (const float*)d_in[12];
    const float* Wih_d   = (const float*)d_in[13];
    const float* Whh_d   = (const float*)d_in[14];
    const float* bih_d   = (const float*)d_in[15];
    const float* bhh_d   = (const float*)d_in[16];
    const float* W_out   = (const float*)d_in[17];
    const float* b_out   = (const float*)d_in[18];
    const float* epsv    = (const float*)d_in[19];

    float* out = (float*)d_out;
    const size_t LOGITS = (size_t)Bz * TDz * Vz;
    float* out_logits = out;
    float* out_mean   = out + LOGITS;
    float* out_lv     = out + LOGITS + (size_t)Bz * Lz;

    float *p_Pe, *p_hse, *p_Pd, *p_hsd;
    __nv_bfloat16 *p_Whi, *p_Wlo, *p_Ahi, *p_Alo;
    __nv_bfloat16 *p_Xeh, *p_Xel, *p_Xdh, *p_Xdl;
    __nv_bfloat16 *p_Wieh, *p_Wiel, *p_Widh, *p_Widl;
    cudaGetSymbolAddress((void**)&p_Pe,  g_Pe);
    cudaGetSymbolAddress((void**)&p_hse, g_hse);
    cudaGetSymbolAddress((void**)&p_Pd,  g_Pd);
    cudaGetSymbolAddress((void**)&p_hsd, g_hsd);
    cudaGetSymbolAddress((void**)&p_Whi, g_Whi);
    cudaGetSymbolAddress((void**)&p_Wlo, g_Wlo);
    cudaGetSymbolAddress((void**)&p_Ahi, g_Ahi);
    cudaGetSymbolAddress((void**)&p_Alo, g_Alo);
    cudaGetSymbolAddress((void**)&p_Xeh, g_Xeh);
    cudaGetSymbolAddress((void**)&p_Xel, g_Xel);
    cudaGetSymbolAddress((void**)&p_Xdh, g_Xdh);
    cudaGetSymbolAddress((void**)&p_Xdl, g_Xdl);
    cudaGetSymbolAddress((void**)&p_Wieh, g_Wieh);
    cudaGetSymbolAddress((void**)&p_Wiel, g_Wiel);
    cudaGetSymbolAddress((void**)&p_Widh, g_Widh);
    cudaGetSymbolAddress((void**)&p_Widl, g_Widl);

    cudaFuncSetAttribute(mma3_kernel<512, 1>, cudaFuncAttributeMaxDynamicSharedMemorySize, SMEM_MMA);
    cudaFuncSetAttribute(mma3_kernel<1024, 0>, cudaFuncAttributeMaxDynamicSharedMemorySize, SMEM_MMA);

    // 1) zero encoder h0 slot; reset grid barrier
    init_kernel<<<64, 256>>>(p_hse, Bz * Hz);

    // 2) embeddings fused with bf16 split
    embed_split_kernel<<<1024, 256>>>(tokens, emb_enc, p_Xeh, p_Xel, Sz, 0);
    embed_split_kernel<<<1024, 256>>>(tokens, emb_dec, p_Xdh, p_Xdl, TDz, 1);

    // 2b) Wih bf16 splits
    convert_w_kernel<<<1024, 256>>>(Wih_e, p_Wieh, p_Wiel, Gz * Ez / 4);
    convert_w_kernel<<<1024, 256>>>(Wih_d, p_Widh, p_Widl, Gz * Ez / 4);

    // 3) input projections via bf16 3-split mma (K=512)
    {
        dim3 grid(32, 32);
        mma3_kernel<512, 1><<<grid, 256, SMEM_MMA>>>(p_Xeh, p_Xel, p_Wieh, p_Wiel,
                                                     bih_e, bhh_e, p_Pe, Gz);
        mma3_kernel<512, 1><<<grid, 256, SMEM_MMA>>>(p_Xdh, p_Xdl, p_Widh, p_Widl,
                                                     bih_d, bhh_d, p_Pd, Gz);
    }

    // 3b) W_out bf16 split
    convert_w_kernel<<<4096, 256>>>(W_out, p_Whi, p_Wlo, (int)((size_t)Vz * Hz / 4));

    // 4+5+6) recurrences + latent head, one persistent kernel
    lstm_persistent<<<NBLK, 256>>>(Whh_e, Whh_d, p_Pe, p_Pd, p_hse, p_hsd,
                                   tokens, W_mu, b_mu, W_lv, b_lv, epsv,
                                   W_l2h, b_l2h, out_mean, out_lv);

    // 6b) hd bf16 split
    convert_a_kernel<<<1024, 256>>>(p_hsd, p_Ahi, p_Alo);

    // 7) logits via bf16 3-split mma (K=1024)
    {
        dim3 grid(32, 250);
        mma3_kernel<1024, 0><<<grid, 256, SMEM_MMA>>>(p_Ahi, p_Alo, p_Whi, p_Wlo,
                                                      b_out, b_out, out_logits, Vz);
    }
}

// round 12
// speedup vs baseline: 1.1133x; 1.0426x over previous
#include <cuda_runtime.h>
#include <cuda_bf16.h>
#include <math.h>
#include <stdint.h>

// Problem dims
#define Bz 32
#define Sz 128
#define Ez 512
#define Hz 1024
#define Gz 4096   // 4*H
#define Lz 128
#define Vz 32000
#define TDz 126   // S-2
#define NBLK 128  // persistent grid size

// ---------------- scratch (device globals; no runtime allocation) ----------------
__device__ float g_Pe[(size_t)Sz * Bz * Gz];
__device__ float g_hse[(Sz + 1) * Bz * Hz];
__device__ float g_Pd[(size_t)4096 * Gz];          // padded to 4096 rows
__device__ float g_hsd[(TDz + 1) * Bz * Hz];
__device__ unsigned g_bar;
// bf16 split buffers
__device__ __nv_bfloat16 g_Whi[(size_t)Vz * Hz];
__device__ __nv_bfloat16 g_Wlo[(size_t)Vz * Hz];
__device__ __nv_bfloat16 g_Ahi[4096 * Hz];
__device__ __nv_bfloat16 g_Alo[4096 * Hz];
__device__ __nv_bfloat16 g_Xeh[4096 * Ez];
__device__ __nv_bfloat16 g_Xel[4096 * Ez];
__device__ __nv_bfloat16 g_Xdh[4096 * Ez];         // rows >= 4032 stay zero (BSS)
__device__ __nv_bfloat16 g_Xdl[4096 * Ez];
__device__ __nv_bfloat16 g_Wieh[Gz * Ez];
__device__ __nv_bfloat16 g_Wiel[Gz * Ez];
__device__ __nv_bfloat16 g_Widh[Gz * Ez];
__device__ __nv_bfloat16 g_Widl[Gz * Ez];

// ---------------- f32x2 helpers ----------------
__device__ __forceinline__ unsigned long long pk2(float x, float y) {
    unsigned long long r;
    asm("mov.b64 %0, {%1,%2};" : "=l"(r) : "f"(x), "f"(y));
    return r;
}
__device__ __forceinline__ float2 upk2(unsigned long long v) {
    float2 r;
    asm("mov.b64 {%0,%1}, %2;" : "=f"(r.x), "=f"(r.y) : "l"(v));
    return r;
}
__device__ __forceinline__ unsigned long long ffma2(unsigned long long a, unsigned long long b,
                                                    unsigned long long c) {
    unsigned long long d;
    asm("fma.rn.f32x2 %0, %1, %2, %3;" : "=l"(d) : "l"(a), "l"(b), "l"(c));
    return d;
}
__device__ __forceinline__ float sigm(float x) { return 1.0f / (1.0f + expf(-x)); }

__device__ __forceinline__ uint32_t smem_u32(const void* p) {
    uint32_t a;
    asm("{ .reg .u64 t; cvta.to.shared.u64 t, %1; cvt.u32.u64 %0, t; }" : "=r"(a) : "l"(p));
    return a;
}

// ---------------- mma.sync + cp.async helpers (compute_103-safe PTX) ----------------
#define LDSM4(d, addr) \
    asm volatile("ldmatrix.sync.aligned.m8n8.x4.shared.b16 {%0,%1,%2,%3}, [%4];" \
        : "=r"((d)[0]), "=r"((d)[1]), "=r"((d)[2]), "=r"((d)[3]) : "r"(addr))

#define MMA16816(c, a, b) \
    asm volatile("mma.sync.aligned.m16n8k16.row.col.f32.bf16.bf16.f32 " \
        "{%0,%1,%2,%3}, {%4,%5,%6,%7}, {%8,%9}, {%0,%1,%2,%3};" \
        : "+f"((c)[0]), "+f"((c)[1]), "+f"((c)[2]), "+f"((c)[3]) \
        : "r"((a)[0]), "r"((a)[1]), "r"((a)[2]), "r"((a)[3]), "r"((b)[0]), "r"((b)[1]))

#define CP_ASYNC16(smaddr, gptr) \
    asm volatile("cp.async.cg.shared.global [%0], [%1], 16;" :: "r"(smaddr), "l"(gptr))
#define CP_COMMIT() asm volatile("cp.async.commit_group;" ::: "memory")
#define CP_WAIT0()  asm volatile("cp.async.wait_group 0;" ::: "memory")

// ---------------- grid barrier ----------------
__device__ __forceinline__ void grid_sync_(unsigned target) {
    __syncthreads();
    if (threadIdx.x == 0) {
        __threadfence();
        atomicAdd(&g_bar, 1u);
        unsigned v;
        do {
            asm volatile("ld.global.acquire.gpu.u32 %0, [%1];" : "=r"(v) : "l"(&g_bar));
        } while (v < target);
    }
    __syncthreads();
}

// ---------------- init ----------------
__global__ void init_kernel(float* __restrict__ h0, int n) {
    int i = blockIdx.x * blockDim.x + threadIdx.x;
    int stride = gridDim.x * blockDim.x;
    for (; i < n; i += stride) h0[i] = 0.0f;
    if (blockIdx.x == 0 && threadIdx.x == 0) g_bar = 0u;
}

// ---------------- embedding gather fused with bf16 hi/lo split ----------------
__global__ void embed_split_kernel(const int* __restrict__ tokens, const float* __restrict__ emb,
                                   __nv_bfloat16* __restrict__ hi, __nv_bfloat16* __restrict__ lo,
                                   int T, int toff) {
    int total4 = T * Bz * (Ez / 4);
    int i = blockIdx.x * blockDim.x + threadIdx.x;
    int stride = gridDim.x * blockDim.x;
    const int E4 = Ez / 4;
    for (; i < total4; i += stride) {
        int e4 = i % E4;
        int r  = i / E4;
        int b  = r % Bz;
        int t  = r / Bz;
        int tok = tokens[b * Sz + t + toff];
        float4 v = ((const float4*)(emb + (size_t)tok * Ez))[e4];
        __nv_bfloat16 h0 = __float2bfloat16(v.x);
        __nv_bfloat16 h1 = __float2bfloat16(v.y);
        __nv_bfloat16 h2 = __float2bfloat16(v.z);
        __nv_bfloat16 h3 = __float2bfloat16(v.w);
        __nv_bfloat162 ha; ha.x = h0; ha.y = h1;
        __nv_bfloat162 hb; hb.x = h2; hb.y = h3;
        ((__nv_bfloat162*)hi)[i * 2]     = ha;
        ((__nv_bfloat162*)hi)[i * 2 + 1] = hb;
        __nv_bfloat162 la, lb;
        la.x = __float2bfloat16(v.x - __bfloat162float(h0));
        la.y = __float2bfloat16(v.y - __bfloat162float(h1));
        lb.x = __float2bfloat16(v.z - __bfloat162float(h2));
        lb.y = __float2bfloat16(v.w - __bfloat162float(h3));
        ((__nv_bfloat162*)lo)[i * 2]     = la;
        ((__nv_bfloat162*)lo)[i * 2 + 1] = lb;
    }
}

// ---------------- generic bf16 hi/lo split ----------------
__global__ void convert_w_kernel(const float* __restrict__ W, __nv_bfloat16* __restrict__ hi,
                                 __nv_bfloat16* __restrict__ lo, int n4) {
    int i = blockIdx.x * blockDim.x + threadIdx.x;
    int stride = gridDim.x * blockDim.x;
    for (; i < n4; i += stride) {
        float4 v = ((const float4*)W)[i];
        __nv_bfloat16 h0 = __float2bfloat16(v.x);
        __nv_bfloat16 h1 = __float2bfloat16(v.y);
        __nv_bfloat16 h2 = __float2bfloat16(v.z);
        __nv_bfloat16 h3 = __float2bfloat16(v.w);
        __nv_bfloat162 ha; ha.x = h0; ha.y = h1;
        __nv_bfloat162 hb; hb.x = h2; hb.y = h3;
        ((__nv_bfloat162*)hi)[i * 2]     = ha;
        ((__nv_bfloat162*)hi)[i * 2 + 1] = hb;
        __nv_bfloat162 la, lb;
        la.x = __float2bfloat16(v.x - __bfloat162float(h0));
        la.y = __float2bfloat16(v.y - __bfloat162float(h1));
        lb.x = __float2bfloat16(v.z - __bfloat162float(h2));
        lb.y = __float2bfloat16(v.w - __bfloat162float(h3));
        ((__nv_bfloat162*)lo)[i * 2]     = la;
        ((__nv_bfloat162*)lo)[i * 2 + 1] = lb;
    }
}

// A row m (= t*Bz+b) = hsd[(m+32)*Hz + k]; rows >= 4032 zero-padded
__global__ void convert_a_kernel(const float* __restrict__ hsd, __nv_bfloat16* __restrict__ hi,
                                 __nv_bfloat16* __restrict__ lo) {
    int n4 = 4096 * Hz / 4;
    int i = blockIdx.x * blockDim.x + threadIdx.x;
    int stride = gridDim.x * blockDim.x;
    for (; i < n4; i += stride) {
        int e = i * 4;
        int m = e >> 10;
        int k = e & 1023;
        float4 v = make_float4(0.f, 0.f, 0.f, 0.f);
        if (m < TDz * Bz) v = *(const float4*)(hsd + (size_t)(m + 32) * Hz + k);
        __nv_bfloat16 h0 = __float2bfloat16(v.x);
        __nv_bfloat16 h1 = __float2bfloat16(v.y);
        __nv_bfloat16 h2 = __float2bfloat16(v.z);
        __nv_bfloat16 h3 = __float2bfloat16(v.w);
        __nv_bfloat162 ha; ha.x = h0; ha.y = h1;
        __nv_bfloat162 hb; hb.x = h2; hb.y = h3;
        ((__nv_bfloat162*)hi)[i * 2]     = ha;
        ((__nv_bfloat162*)hi)[i * 2 + 1] = hb;
        __nv_bfloat162 la, lb;
        la.x = __float2bfloat16(v.x - __bfloat162float(h0));
        la.y = __float2bfloat16(v.y - __bfloat162float(h1));
        lb.x = __float2bfloat16(v.z - __bfloat162float(h2));
        lb.y = __float2bfloat16(v.w - __bfloat162float(h3));
        ((__nv_bfloat162*)lo)[i * 2]     = la;
        ((__nv_bfloat162*)lo)[i * 2 + 1] = lb;
    }
}

// ---------------- bf16 3-split mma GEMM (cp.async, occupancy 2) ----------------
#define SSTR   80
#define SA_HI  0
#define SA_LO  10240
#define SB_HI  20480
#define SB_LO  30720
#define STAGE  40960
#define SBIAS  (2 * STAGE)
#define SMEM_MMA (2 * STAGE + 512)

template <int KDIM, int MODE>
__global__ __launch_bounds__(256, 2)
void mma3_kernel(const __nv_bfloat16* __restrict__ Ahi, const __nv_bfloat16* __restrict__ Alo,
                 const __nv_bfloat16* __restrict__ Whi, const __nv_bfloat16* __restrict__ Wlo,
                 const float* __restrict__ bias1, const float* __restrict__ bias2,
                 float* __restrict__ out, int Nout) {
    extern __shared__ char smem[];
    const uint32_t sbase = smem_u32(smem);
    const int tid = threadIdx.x;
    const int w = tid >> 5, lane = tid & 31;
    const int mtile = blockIdx.x;
    const int ntile = blockIdx.y;
    const int wm = (w & 1) * 64;
    const int wn = (w >> 1) * 32;

    if (tid < 128) {
        float bv = bias1[ntile * 128 + tid];
        if (MODE == 1) bv += bias2[ntile * 128 + tid];
        ((float*)(smem + SBIAS))[tid] = bv;
    }

    const int row = tid >> 2;
    const int ko  = (tid & 3) * 8;
    const __nv_bfloat16* gA0h = Ahi + (size_t)(mtile * 128 + row) * KDIM + ko;
    const __nv_bfloat16* gA1h = Ahi + (size_t)(mtile * 128 + row + 64) * KDIM + ko;
    const __nv_bfloat16* gA0l = Alo + (size_t)(mtile * 128 + row) * KDIM + ko;
    const __nv_bfloat16* gA1l = Alo + (size_t)(mtile * 128 + row + 64) * KDIM + ko;
    const __nv_bfloat16* gB0h = Whi + (size_t)(ntile * 128 + row) * KDIM + ko;
    const __nv_bfloat16* gB1h = Whi + (size_t)(ntile * 128 + row + 64) * KDIM + ko;
    const __nv_bfloat16* gB0l = Wlo + (size_t)(ntile * 128 + row) * KDIM + ko;
    const __nv_bfloat16* gB1l = Wlo + (size_t)(ntile * 128 + row + 64) * KDIM + ko;
    const uint32_t s0 = sbase + row * SSTR + ko * 2;
    const uint32_t s1 = sbase + (row + 64) * SSTR + ko * 2;

    const uint32_t aLane = sbase + (uint32_t)(wm + (lane & 15)) * SSTR + (uint32_t)(lane >> 4) * 16;
    const uint32_t bLane = sbase + (uint32_t)(wn + (lane & 7) + ((lane >> 4) << 3)) * SSTR +
                           (uint32_t)((lane >> 3) & 1) * 16;

    float acc[4][4][4];
#pragma unroll
    for (int i = 0; i < 4; i++)
#pragma unroll
        for (int j = 0; j < 4; j++)
#pragma unroll
            for (int q = 0; q < 4; q++) acc[i][j][q] = 0.f;

    CP_ASYNC16(s0 + SA_HI, gA0h); CP_ASYNC16(s1 + SA_HI, gA1h);
    CP_ASYNC16(s0 + SA_LO, gA0l); CP_ASYNC16(s1 + SA_LO, gA1l);
    CP_ASYNC16(s0 + SB_HI, gB0h); CP_ASYNC16(s1 + SB_HI, gB1h);
    CP_ASYNC16(s0 + SB_LO, gB0l); CP_ASYNC16(s1 + SB_LO, gB1l);
    CP_COMMIT();
    CP_WAIT0();
    __syncthreads();

    const int NT = KDIM / 32;
    for (int kt = 0; kt < NT; kt++) {
        const uint32_t stg = (uint32_t)(kt & 1) * STAGE;

        if (kt < NT - 1) {
            const uint32_t nstg = (uint32_t)((kt + 1) & 1) * STAGE;
            const int go = (kt + 1) * 32;
            CP_ASYNC16(s0 + nstg + SA_HI, gA0h + go); CP_ASYNC16(s1 + nstg + SA_HI, gA1h + go);
            CP_ASYNC16(s0 + nstg + SA_LO, gA0l + go); CP_ASYNC16(s1 + nstg + SA_LO, gA1l + go);
            CP_ASYNC16(s0 + nstg + SB_HI, gB0h + go); CP_ASYNC16(s1 + nstg + SB_HI, gB1h + go);
            CP_ASYNC16(s0 + nstg + SB_LO, gB0l + go); CP_ASYNC16(s1 + nstg + SB_LO, gB1l + go);
            CP_COMMIT();
        }

#pragma unroll
        for (int ks = 0; ks < 2; ks++) {
            const uint32_t kofs = (uint32_t)ks * 32;
            uint32_t bH[4][2], bL[4][2];
#pragma unroll
            for (int nb2 = 0; nb2 < 2; nb2++) {
                uint32_t bd = stg + bLane + (uint32_t)nb2 * (16 * SSTR) + kofs;
                uint32_t t4[4];
                LDSM4(t4, bd + SB_HI);
                bH[nb2 * 2][0] = t4[0]; bH[nb2 * 2][1] = t4[1];
                bH[nb2 * 2 + 1][0] = t4[2]; bH[nb2 * 2 + 1][1] = t4[3];
                LDSM4(t4, bd + SB_LO);
                bL[nb2 * 2][0] = t4[0]; bL[nb2 * 2][1] = t4[1];
                bL[nb2 * 2 + 1][0] = t4[2]; bL[nb2 * 2 + 1][1] = t4[3];
            }
#pragma unroll
            for (int ma = 0; ma < 4; ma++) {
                uint32_t ad = stg + aLane + (uint32_t)ma * (16 * SSTR) + kofs;
                uint32_t aH[4], aL[4];
                LDSM4(aH, ad + SA_HI);
                LDSM4(aL, ad + SA_LO);
#pragma unroll
                for (int nb = 0; nb < 4; nb++) {
                    MMA16816(acc[ma][nb], aH, bH[nb]);
                    MMA16816(acc[ma][nb], aH, bL[nb]);
                    MMA16816(acc[ma][nb], aL, bH[nb]);
                }
            }
        }

        CP_WAIT0();
        __syncthreads();
    }

    const float* sb = (const float*)(smem + SBIAS);
#pragma unroll
    for (int ma = 0; ma < 4; ma++) {
        const int m0 = mtile * 128 + wm + ma * 16 + (lane >> 2);
#pragma unroll
        for (int nb = 0; nb < 4; nb++) {
            const int cl = wn + nb * 8 + (lane & 3) * 2;
            const float b0v = sb[cl], b1v = sb[cl + 1];
            const size_t col = (size_t)(ntile * 128 + cl);
            if (MODE == 0) {
                if (m0 < TDz * Bz) {
                    int orow = (m0 & 31) * TDz + (m0 >> 5);
                    float2 v;
                    v.x = acc[ma][nb][0] + b0v;
                    v.y = acc[ma][nb][1] + b1v;
                    *(float2*)(out + (size_t)orow * Nout + col) = v;
                }
                const int m1 = m0 + 8;
                if (m1 < TDz * Bz) {
                    int orow = (m1 & 31) * TDz + (m1 >> 5);
                    float2 v;
                    v.x = acc[ma][nb][2] + b0v;
                    v.y = acc[ma][nb][3] + b1v;
                    *(float2*)(out + (size_t)orow * Nout + col) = v;
                }
            } else {
                float2 v;
                v.x = acc[ma][nb][0] + b0v;
                v.y = acc[ma][nb][1] + b1v;
                *(float2*)(out + (size_t)m0 * Nout + col) = v;
                v.x = acc[ma][nb][2] + b0v;
                v.y = acc[ma][nb][3] + b1v;
                *(float2*)(out + (size_t)(m0 + 8) * Nout + col) = v;
            }
        }
    }
}

// ---------------- persistent LSTM (512 threads: unit = 2 warps, k-split) ----------------
// Warp w: unit ul = w>>1, k-half kh = w&1 (k in [kh*512, kh*512+512)).
// Per-warp weights: 4 gates x 512 k / 32 lanes = 64 floats (32 packed regs).
__device__ __forceinline__ void load_w(const float* __restrict__ Whh, int u, int lane, int kh,
                                       unsigned long long (&w2)[4][4][2]) {
#pragma unroll
    for (int r = 0; r < 4; r++) {
        const float4* wr = (const float4*)(Whh + (size_t)(r * Hz + u) * Hz);
#pragma unroll
        for (int j = 0; j < 4; j++) {
            float4 v = wr[kh * 128 + j * 32 + lane];
            w2[r][j][0] = pk2(v.x, v.y);
            w2[r][j][1] = pk2(v.z, v.w);
        }
    }
}

__device__ __forceinline__ void dot4r(const unsigned long long (&w2)[4][4][2],
                                      const ulonglong2 (&hv)[4],
                                      unsigned long long (&acc)[4]) {
#pragma unroll
    for (int r = 0; r < 4; r++) acc[r] = 0ull;
#pragma unroll
    for (int j = 0; j < 4; j++) {
#pragma unroll
        for (int r = 0; r < 4; r++) {
            acc[r] = ffma2(w2[r][j][0], hv[j].x, acc[r]);
            acc[r] = ffma2(w2[r][j][1], hv[j].y, acc[r]);
        }
    }
}

__device__ __forceinline__ float reduce4(const unsigned long long (&acc)[4], int lane) {
    float2 p0 = upk2(acc[0]); float v0 = p0.x + p0.y;
    float2 p1 = upk2(acc[1]); float v1 = p1.x + p1.y;
    float2 p2 = upk2(acc[2]); float v2 = p2.x + p2.y;
    float2 p3 = upk2(acc[3]); float v3 = p3.x + p3.y;
    v0 += __shfl_xor_sync(0xffffffffu, v0, 1);
    v1 += __shfl_xor_sync(0xffffffffu, v1, 1);
    v2 += __shfl_xor_sync(0xffffffffu, v2, 1);
    v3 += __shfl_xor_sync(0xffffffffu, v3, 1);
    float a  = (lane & 1) ? v1 : v0;
    float bb = (lane & 1) ? v3 : v2;
    a  += __shfl_xor_sync(0xffffffffu, a, 2);
    bb += __shfl_xor_sync(0xffffffffu, bb, 2);
    float m = (lane & 2) ? bb : a;
    m += __shfl_xor_sync(0xffffffffu, m, 4);
    m += __shfl_xor_sync(0xffffffffu, m, 8);
    m += __shfl_xor_sync(0xffffffffu, m, 16);
    return m;
}

// one LSTM step (512 threads). sgf[w][b][g] holds per-k-half partial gate sums.
__device__ __forceinline__ float lstm_step_p(
    const unsigned long long (&w2)[4][4][2],
    const float* __restrict__ P, const float* __restrict__ hin,
    float* __restrict__ hout, float creg,
    float* __restrict__ sgf, float* __restrict__ sPf,
    int u0, int tid, int w, int lane, int kh)
{
    // P gate prefetch into smem (consumed in the epilogue)
#pragma unroll
    for (int k = 0; k < 2; k++) {
        int idx = tid + k * 512;
        int b = idx >> 5, c = idx & 31;
        sPf[b * 33 + c] = P[(size_t)b * Gz + (c >> 3) * Hz + u0 + (c & 7)];
    }

    const ulonglong2* h4 = (const ulonglong2*)hin;
    const int hoff = kh * 128;          // k-half offset in 16B units
    ulonglong2 hv[4];
#pragma unroll
    for (int j = 0; j < 4; j++) hv[j] = h4[hoff + j * 32 + lane];   // batch 0

    unsigned long long acc[2][4];
    dot4r(w2, hv, acc[0]);

#pragma unroll 2
    for (int b = 1; b < Bz; b++) {
#pragma unroll
        for (int j = 0; j < 4; j++) hv[j] = h4[b * 256 + hoff + j * 32 + lane];
        float m = reduce4(acc[(b - 1) & 1], lane);
        if (lane < 4) sgf[w * 132 + (b - 1) * 4 + lane] = m;
        dot4r(w2, hv, acc[b & 1]);
    }
    {
        float m = reduce4(acc[(Bz - 1) & 1], lane);
        if (lane < 4) sgf[w * 132 + (Bz - 1) * 4 + lane] = m;
    }
    __syncthreads();

    // epilogue: threads 0..255 -> (ul = tid&7, b = tid>>3); sum the two k-half partials
    float newc = creg;
    if (tid < 256) {
        int ul = tid & 7, b = tid >> 3;
        const float* g0 = sgf + (2 * ul) * 132 + b * 4;
        const float* g1 = sgf + (2 * ul + 1) * 132 + b * 4;
        float gi = g0[0] + g1[0] + sPf[b * 33 +  0 + ul];
        float gf = g0[1] + g1[1] + sPf[b * 33 +  8 + ul];
        float gg = g0[2] + g1[2] + sPf[b * 33 + 16 + ul];
        float go = g0[3] + g1[3] + sPf[b * 33 + 24 + ul];
        float cc = sigm(gf) * creg + sigm(gi) * tanhf(gg);
        float hh = sigm(go) * tanhf(cc);
        hout[b * Hz + u0 + ul] = hh;
        newc = cc;
    }
    return newc;
}

// latent head, 512-thread version
__device__ void latent_dev(int b, int tid,
                           const int* __restrict__ tokens, const float* __restrict__ hs,
                           const float* __restrict__ Wmu, const float* __restrict__ bmu,
                           const float* __restrict__ Wlv, const float* __restrict__ blv,
                           const float* __restrict__ eps,
                           const float* __restrict__ Wl2h, const float* __restrict__ bl2h,
                           float* __restrict__ out_mean, float* __restrict__ out_lv,
                           float* __restrict__ hd0,
                           int* __restrict__ scnt, float* __restrict__ smean,
                           float* __restrict__ slv, float* __restrict__ szv) {
    int cnt = 0;
    if (tid < Sz) cnt = (tokens[b * Sz + tid] != 0) ? 1 : 0;
    scnt[tid] = cnt;
    __syncthreads();
    for (int off = 256; off >= 1; off >>= 1) {
        if (tid < off) scnt[tid] += scnt[tid + off];
        __syncthreads();
    }
    int last = scnt[0] - 1;
    if (last < 0) last = 0;

    const float* lh = hs + (size_t)(last + 1) * Bz * Hz + (size_t)b * Hz;
    if (tid < 256) {
        int j = tid & 127;
        const float* Wr = ((tid < 128) ? Wmu : Wlv) + (size_t)j * Hz;
        float acc = 0.f;
        const float4* l4 = (const float4*)lh;
        const float4* w4 = (const float4*)Wr;
#pragma unroll 4
        for (int k = 0; k < Hz / 4; k++) {
            float4 a = l4[k];
            float4 ww = w4[k];
            acc += a.x * ww.x + a.y * ww.y + a.z * ww.z + a.w * ww.w;
        }
        if (tid < 128) smean[j] = acc + bmu[j];
        else           slv[j]   = acc + blv[j];
    }
    __syncthreads();

    if (tid < 128) {
        float m = smean[tid];
        float lv = slv[tid];
        out_mean[b * Lz + tid] = m;
        out_lv[b * Lz + tid] = lv;
        szv[tid] = m + eps[b * Lz + tid] * expf(0.5f * lv);
    }
    __syncthreads();

#pragma unroll
    for (int r = 0; r < 2; r++) {
        int u = tid + r * 512;
        float acc = bl2h[u];
        const float* wr = Wl2h + (size_t)u * Lz;
#pragma unroll 4
        for (int l = 0; l < Lz; l++) acc += szv[l] * wr[l];
        hd0[b * Hz + u] = acc;
    }
}

__global__ __launch_bounds__(512, 1)
void lstm_persistent(const float* __restrict__ Whh_e, const float* __restrict__ Whh_d,
                     const float* __restrict__ Pe, const float* __restrict__ Pd,
                     float* __restrict__ hse, float* __restrict__ hsd,
                     const int* __restrict__ tokens,
                     const float* __restrict__ Wmu, const float* __restrict__ bmu,
                     const float* __restrict__ Wlv, const float* __restrict__ blv,
                     const float* __restrict__ eps,
                     const float* __restrict__ Wl2h, const float* __restrict__ bl2h,
                     float* __restrict__ out_mean, float* __restrict__ out_lv) {
    const int tid = threadIdx.x;
    const int w = tid >> 5;
    const int lane = tid & 31;
    const int ul = w >> 1;
    const int kh = w & 1;
    const int u0 = blockIdx.x * 8;
    const int u = u0 + ul;

    __shared__ float sgf[16 * 132];
    __shared__ float sPf[32 * 33];
    __shared__ int   scnt[512];
    __shared__ float smean[128], slvs[128], szv[128];

    unsigned long long w2[4][4][2];
    load_w(Whh_e, u, lane, kh, w2);

    float creg = 0.f;
    unsigned epoch = 0;

    for (int t = 0; t < Sz; t++) {
        creg = lstm_step_p(w2, Pe + (size_t)t * Bz * Gz,
                           hse + (size_t)t * Bz * Hz,
                           hse + (size_t)(t + 1) * Bz * Hz,
                           creg, sgf, sPf, u0, tid, w, lane, kh);
        epoch++;
        grid_sync_(epoch * NBLK);
    }

    load_w(Whh_d, u, lane, kh, w2);
    if (blockIdx.x < 32) {
        latent_dev(blockIdx.x, tid, tokens, hse, Wmu, bmu, Wlv, blv, eps,
                   Wl2h, bl2h, out_mean, out_lv, hsd,
                   scnt, smean, slvs, szv);
    }
    epoch++;
    grid_sync_(epoch * NBLK);

    creg = 0.f;
    for (int t = 0; t < TDz; t++) {
        creg = lstm_step_p(w2, Pd + (size_t)t * Bz * Gz,
                           hsd + (size_t)t * Bz * Hz,
                           hsd + (size_t)(t + 1) * Bz * Hz,
                           creg, sgf, sPf, u0, tid, w, lane, kh);
        if (t < TDz - 1) {
            epoch++;
            grid_sync_(epoch * NBLK);
        }
    }
}

// ---------------- launch ----------------
extern "C" void kernel_launch(void* const* d_in, const int* in_sizes, int n_in,
                              void* d_out, int out_size) {
    const int*   tokens  = (const int*)d_in[0];
    const float* emb_enc = (const float*)d_in[1];
    const float* Wih_e   = (const float*)d_in[2];
    const float* Whh_e   = (const float*)d_in[3];
    const float* bih_e   = (const float*)d_in[4];
    const float* bhh_e   = (const float*)d_in[5];
    const float* W_mu    = (const float*)d_in[6];
    const float* b_mu    = (const float*)d_in[7];
    const float* W_lv    = (const float*)d_in[8];
    const float* b_lv    = (const float*)d_in[9];
    const float* emb_dec = (const float*)d_in[10];
    const float* W_l2h   = (const float*)d_in[11];
    const float* b_l2h   = (const float*)d_in[12];
    const float* Wih_d   = (const float*)d_in[13];
    const float* Whh_d   = (const float*)d_in[14];
    const float* bih_d   = (const float*)d_in[15];
    const float* bhh_d   = (const float*)d_in[16];
    const float* W_out   = (const float*)d_in[17];
    const float* b_out   = (const float*)d_in[18];
    const float* epsv    = (const float*)d_in[19];

    float* out = (float*)d_out;
    const size_t LOGITS = (size_t)Bz * TDz * Vz;
    float* out_logits = out;
    float* out_mean   = out + LOGITS;
    float* out_lv     = out + LOGITS + (size_t)Bz * Lz;

    float *p_Pe, *p_hse, *p_Pd, *p_hsd;
    __nv_bfloat16 *p_Whi, *p_Wlo, *p_Ahi, *p_Alo;
    __nv_bfloat16 *p_Xeh, *p_Xel, *p_Xdh, *p_Xdl;
    __nv_bfloat16 *p_Wieh, *p_Wiel, *p_Widh, *p_Widl;
    cudaGetSymbolAddress((void**)&p_Pe,  g_Pe);
    cudaGetSymbolAddress((void**)&p_hse, g_hse);
    cudaGetSymbolAddress((void**)&p_Pd,  g_Pd);
    cudaGetSymbolAddress((void**)&p_hsd, g_hsd);
    cudaGetSymbolAddress((void**)&p_Whi, g_Whi);
    cudaGetSymbolAddress((void**)&p_Wlo, g_Wlo);
    cudaGetSymbolAddress((void**)&p_Ahi, g_Ahi);
    cudaGetSymbolAddress((void**)&p_Alo, g_Alo);
    cudaGetSymbolAddress((void**)&p_Xeh, g_Xeh);
    cudaGetSymbolAddress((void**)&p_Xel, g_Xel);
    cudaGetSymbolAddress((void**)&p_Xdh, g_Xdh);
    cudaGetSymbolAddress((void**)&p_Xdl, g_Xdl);
    cudaGetSymbolAddress((void**)&p_Wieh, g_Wieh);
    cudaGetSymbolAddress((void**)&p_Wiel, g_Wiel);
    cudaGetSymbolAddress((void**)&p_Widh, g_Widh);
    cudaGetSymbolAddress((void**)&p_Widl, g_Widl);

    cudaFuncSetAttribute(mma3_kernel<512, 1>, cudaFuncAttributeMaxDynamicSharedMemorySize, SMEM_MMA);
    cudaFuncSetAttribute(mma3_kernel<1024, 0>, cudaFuncAttributeMaxDynamicSharedMemorySize, SMEM_MMA);

    // 1) zero encoder h0 slot; reset grid barrier
    init_kernel<<<64, 256>>>(p_hse, Bz * Hz);

    // 2) embeddings fused with bf16 split
    embed_split_kernel<<<1024, 256>>>(tokens, emb_enc, p_Xeh, p_Xel, Sz, 0);
    embed_split_kernel<<<1024, 256>>>(tokens, emb_dec, p_Xdh, p_Xdl, TDz, 1);

    // 2b) Wih bf16 splits
    convert_w_kernel<<<1024, 256>>>(Wih_e, p_Wieh, p_Wiel, Gz * Ez / 4);
    convert_w_kernel<<<1024, 256>>>(Wih_d, p_Widh, p_Widl, Gz * Ez / 4);

    // 3) input projections via bf16 3-split mma (K=512)
    {
        dim3 grid(32, 32);
        mma3_kernel<512, 1><<<grid, 256, SMEM_MMA>>>(p_Xeh, p_Xel, p_Wieh, p_Wiel,
                                                     bih_e, bhh_e, p_Pe, Gz);
        mma3_kernel<512, 1><<<grid, 256, SMEM_MMA>>>(p_Xdh, p_Xdl, p_Widh, p_Widl,
                                                     bih_d, bhh_d, p_Pd, Gz);
    }

    // 3b) W_out bf16 split
    convert_w_kernel<<<4096, 256>>>(W_out, p_Whi, p_Wlo, (int)((size_t)Vz * Hz / 4));

    // 4+5+6) recurrences + latent head, one persistent kernel (512 threads)
    lstm_persistent<<<NBLK, 512>>>(Whh_e, Whh_d, p_Pe, p_Pd, p_hse, p_hsd,
                                   tokens, W_mu, b_mu, W_lv, b_lv, epsv,
                                   W_l2h, b_l2h, out_mean, out_lv);

    // 6b) hd bf16 split
    convert_a_kernel<<<1024, 256>>>(p_hsd, p_Ahi, p_Alo);

    // 7) logits via bf16 3-split mma (K=1024)
    {
        dim3 grid(32, 250);
        mma3_kernel<1024, 0><<<grid, 256, SMEM_MMA>>>(p_Ahi, p_Alo, p_Whi, p_Wlo,
                                                      b_out, b_out, out_logits, Vz);
    }
}

// round 13
// speedup vs baseline: 1.2819x; 1.1514x over previous
#include <cuda_runtime.h>
#include <cuda_bf16.h>
#include <cuda_fp16.h>
#include <math.h>
#include <stdint.h>

// Problem dims
#define Bz 32
#define Sz 128
#define Ez 512
#define Hz 1024
#define Gz 4096   // 4*H
#define Lz 128
#define Vz 32000
#define TDz 126   // S-2
#define NBLK 128  // persistent grid size

// ---------------- scratch (device globals; no runtime allocation) ----------------
__device__ float g_Pe[(size_t)Sz * Bz * Gz];
__device__ float g_hse[(Sz + 1) * Bz * Hz];
__device__ float g_Pd[(size_t)4096 * Gz];          // padded to 4096 rows
__device__ float g_hsd[(TDz + 1) * Bz * Hz];
__device__ unsigned g_bar;
// fp16 buffers for the tensor-core GEMMs (A 2-split, W single)
__device__ __half g_Wh[(size_t)Vz * Hz];
__device__ __half g_Ahi[4096 * Hz];
__device__ __half g_Alo[4096 * Hz];
__device__ __half g_Xeh[4096 * Ez];
__device__ __half g_Xel[4096 * Ez];
__device__ __half g_Xdh[4096 * Ez];                // rows >= 4032 stay zero (BSS)
__device__ __half g_Xdl[4096 * Ez];
__device__ __half g_Wieh[Gz * Ez];
__device__ __half g_Widh[Gz * Ez];

// ---------------- f32x2 helpers ----------------
__device__ __forceinline__ unsigned long long pk2(float x, float y) {
    unsigned long long r;
    asm("mov.b64 %0, {%1,%2};" : "=l"(r) : "f"(x), "f"(y));
    return r;
}
__device__ __forceinline__ float2 upk2(unsigned long long v) {
    float2 r;
    asm("mov.b64 {%0,%1}, %2;" : "=f"(r.x), "=f"(r.y) : "l"(v));
    return r;
}
__device__ __forceinline__ unsigned long long ffma2(unsigned long long a, unsigned long long b,
                                                    unsigned long long c) {
    unsigned long long d;
    asm("fma.rn.f32x2 %0, %1, %2, %3;" : "=l"(d) : "l"(a), "l"(b), "l"(c));
    return d;
}
__device__ __forceinline__ float sigm(float x) { return 1.0f / (1.0f + expf(-x)); }

__device__ __forceinline__ uint32_t smem_u32(const void* p) {
    uint32_t a;
    asm("{ .reg .u64 t; cvta.to.shared.u64 t, %1; cvt.u32.u64 %0, t; }" : "=r"(a) : "l"(p));
    return a;
}

// ---------------- mma.sync + cp.async helpers (compute_103-safe PTX) ----------------
#define LDSM4(d, addr) \
    asm volatile("ldmatrix.sync.aligned.m8n8.x4.shared.b16 {%0,%1,%2,%3}, [%4];" \
        : "=r"((d)[0]), "=r"((d)[1]), "=r"((d)[2]), "=r"((d)[3]) : "r"(addr))

#define MMAH16816(c, a, b) \
    asm volatile("mma.sync.aligned.m16n8k16.row.col.f32.f16.f16.f32 " \
        "{%0,%1,%2,%3}, {%4,%5,%6,%7}, {%8,%9}, {%0,%1,%2,%3};" \
        : "+f"((c)[0]), "+f"((c)[1]), "+f"((c)[2]), "+f"((c)[3]) \
        : "r"((a)[0]), "r"((a)[1]), "r"((a)[2]), "r"((a)[3]), "r"((b)[0]), "r"((b)[1]))

#define CP_ASYNC16(smaddr, gptr) \
    asm volatile("cp.async.cg.shared.global [%0], [%1], 16;" :: "r"(smaddr), "l"(gptr))
#define CP_COMMIT() asm volatile("cp.async.commit_group;" ::: "memory")
#define CP_WAIT0()  asm volatile("cp.async.wait_group 0;" ::: "memory")

// ---------------- grid barrier ----------------
__device__ __forceinline__ void grid_sync_(unsigned target) {
    __syncthreads();
    if (threadIdx.x == 0) {
        __threadfence();
        atomicAdd(&g_bar, 1u);
        unsigned v;
        do {
            asm volatile("ld.global.acquire.gpu.u32 %0, [%1];" : "=r"(v) : "l"(&g_bar));
        } while (v < target);
    }
    __syncthreads();
}

// ---------------- init ----------------
__global__ void init_kernel(float* __restrict__ h0, int n) {
    int i = blockIdx.x * blockDim.x + threadIdx.x;
    int stride = gridDim.x * blockDim.x;
    for (; i < n; i += stride) h0[i] = 0.0f;
    if (blockIdx.x == 0 && threadIdx.x == 0) g_bar = 0u;
}

// ---------------- embedding gather fused with fp16 hi/lo split ----------------
__global__ void embed_split_kernel(const int* __restrict__ tokens, const float* __restrict__ emb,
                                   __half* __restrict__ hi, __half* __restrict__ lo,
                                   int T, int toff) {
    int total4 = T * Bz * (Ez / 4);
    int i = blockIdx.x * blockDim.x + threadIdx.x;
    int stride = gridDim.x * blockDim.x;
    const int E4 = Ez / 4;
    for (; i < total4; i += stride) {
        int e4 = i % E4;
        int r  = i / E4;
        int b  = r % Bz;
        int t  = r / Bz;
        int tok = tokens[b * Sz + t + toff];
        float4 v = ((const float4*)(emb + (size_t)tok * Ez))[e4];
        __half h0 = __float2half_rn(v.x);
        __half h1 = __float2half_rn(v.y);
        __half h2 = __float2half_rn(v.z);
        __half h3 = __float2half_rn(v.w);
        __half2 ha; ha.x = h0; ha.y = h1;
        __half2 hb; hb.x = h2; hb.y = h3;
        ((__half2*)hi)[i * 2]     = ha;
        ((__half2*)hi)[i * 2 + 1] = hb;
        __half2 la, lb;
        la.x = __float2half_rn(v.x - __half2float(h0));
        la.y = __float2half_rn(v.y - __half2float(h1));
        lb.x = __float2half_rn(v.z - __half2float(h2));
        lb.y = __float2half_rn(v.w - __half2float(h3));
        ((__half2*)lo)[i * 2]     = la;
        ((__half2*)lo)[i * 2 + 1] = lb;
    }
}

// ---------------- single fp16 convert (W side) ----------------
__global__ void convert_w_kernel(const float* __restrict__ W, __half* __restrict__ out, int n4) {
    int i = blockIdx.x * blockDim.x + threadIdx.x;
    int stride = gridDim.x * blockDim.x;
    for (; i < n4; i += stride) {
        float4 v = ((const float4*)W)[i];
        __half2 a; a.x = __float2half_rn(v.x); a.y = __float2half_rn(v.y);
        __half2 b; b.x = __float2half_rn(v.z); b.y = __float2half_rn(v.w);
        ((__half2*)out)[i * 2]     = a;
        ((__half2*)out)[i * 2 + 1] = b;
    }
}

// A row m (= t*Bz+b) = hsd[(m+32)*Hz + k]; rows >= 4032 zero-padded; fp16 hi/lo split
__global__ void convert_a_kernel(const float* __restrict__ hsd, __half* __restrict__ hi,
                                 __half* __restrict__ lo) {
    int n4 = 4096 * Hz / 4;
    int i = blockIdx.x * blockDim.x + threadIdx.x;
    int stride = gridDim.x * blockDim.x;
    for (; i < n4; i += stride) {
        int e = i * 4;
        int m = e >> 10;
        int k = e & 1023;
        float4 v = make_float4(0.f, 0.f, 0.f, 0.f);
        if (m < TDz * Bz) v = *(const float4*)(hsd + (size_t)(m + 32) * Hz + k);
        __half h0 = __float2half_rn(v.x);
        __half h1 = __float2half_rn(v.y);
        __half h2 = __float2half_rn(v.z);
        __half h3 = __float2half_rn(v.w);
        __half2 ha; ha.x = h0; ha.y = h1;
        __half2 hb; hb.x = h2; hb.y = h3;
        ((__half2*)hi)[i * 2]     = ha;
        ((__half2*)hi)[i * 2 + 1] = hb;
        __half2 la, lb;
        la.x = __float2half_rn(v.x - __half2float(h0));
        la.y = __float2half_rn(v.y - __half2float(h1));
        lb.x = __float2half_rn(v.z - __half2float(h2));
        lb.y = __float2half_rn(v.w - __half2float(h3));
        ((__half2*)lo)[i * 2]     = la;
        ((__half2*)lo)[i * 2 + 1] = lb;
    }
}

// ---------------- fp16 2-term mma GEMM (A 2-split, W single; cp.async, occ 2) ----------------
// C = (Ahi + Alo) @ Wh^T + bias; block tile 128x128, warp 64x32.
// MODE 0: logits — out[(b*TD+t)*Nout + n], guard m < TDz*Bz
// MODE 1: proj   — out[m*Nout + n] = acc + bias1[n] + bias2[n]
#define SSTR   80
#define SA_HI  0
#define SA_LO  10240
#define SB_H   20480
#define STAGE  30720
#define SBIAS  (2 * STAGE)
#define SMEM_MMA (2 * STAGE + 512)

template <int KDIM, int MODE>
__global__ __launch_bounds__(256, 2)
void mma2_kernel(const __half* __restrict__ Ahi, const __half* __restrict__ Alo,
                 const __half* __restrict__ Wh,
                 const float* __restrict__ bias1, const float* __restrict__ bias2,
                 float* __restrict__ out, int Nout) {
    extern __shared__ char smem[];
    const uint32_t sbase = smem_u32(smem);
    const int tid = threadIdx.x;
    const int w = tid >> 5, lane = tid & 31;
    const int mtile = blockIdx.x;
    const int ntile = blockIdx.y;
    const int wm = (w & 1) * 64;
    const int wn = (w >> 1) * 32;

    if (tid < 128) {
        float bv = bias1[ntile * 128 + tid];
        if (MODE == 1) bv += bias2[ntile * 128 + tid];
        ((float*)(smem + SBIAS))[tid] = bv;
    }

    const int row = tid >> 2;
    const int ko  = (tid & 3) * 8;
    const __half* gA0h = Ahi + (size_t)(mtile * 128 + row) * KDIM + ko;
    const __half* gA1h = Ahi + (size_t)(mtile * 128 + row + 64) * KDIM + ko;
    const __half* gA0l = Alo + (size_t)(mtile * 128 + row) * KDIM + ko;
    const __half* gA1l = Alo + (size_t)(mtile * 128 + row + 64) * KDIM + ko;
    const __half* gB0  = Wh + (size_t)(ntile * 128 + row) * KDIM + ko;
    const __half* gB1  = Wh + (size_t)(ntile * 128 + row + 64) * KDIM + ko;
    const uint32_t s0 = sbase + row * SSTR + ko * 2;
    const uint32_t s1 = sbase + (row + 64) * SSTR + ko * 2;

    const uint32_t aLane = sbase + (uint32_t)(wm + (lane & 15)) * SSTR + (uint32_t)(lane >> 4) * 16;
    const uint32_t bLane = sbase + (uint32_t)(wn + (lane & 7) + ((lane >> 4) << 3)) * SSTR +
                           (uint32_t)((lane >> 3) & 1) * 16;

    float acc[4][4][4];
#pragma unroll
    for (int i = 0; i < 4; i++)
#pragma unroll
        for (int j = 0; j < 4; j++)
#pragma unroll
            for (int q = 0; q < 4; q++) acc[i][j][q] = 0.f;

    // prologue: stage 0
    CP_ASYNC16(s0 + SA_HI, gA0h); CP_ASYNC16(s1 + SA_HI, gA1h);
    CP_ASYNC16(s0 + SA_LO, gA0l); CP_ASYNC16(s1 + SA_LO, gA1l);
    CP_ASYNC16(s0 + SB_H,  gB0);  CP_ASYNC16(s1 + SB_H,  gB1);
    CP_COMMIT();
    CP_WAIT0();
    __syncthreads();

    const int NT = KDIM / 32;
    for (int kt = 0; kt < NT; kt++) {
        const uint32_t stg = (uint32_t)(kt & 1) * STAGE;

        if (kt < NT - 1) {
            const uint32_t nstg = (uint32_t)((kt + 1) & 1) * STAGE;
            const int go = (kt + 1) * 32;
            CP_ASYNC16(s0 + nstg + SA_HI, gA0h + go); CP_ASYNC16(s1 + nstg + SA_HI, gA1h + go);
            CP_ASYNC16(s0 + nstg + SA_LO, gA0l + go); CP_ASYNC16(s1 + nstg + SA_LO, gA1l + go);
            CP_ASYNC16(s0 + nstg + SB_H,  gB0 + go);  CP_ASYNC16(s1 + nstg + SB_H,  gB1 + go);
            CP_COMMIT();
        }

#pragma unroll
        for (int ks = 0; ks < 2; ks++) {
            const uint32_t kofs = (uint32_t)ks * 32;
            uint32_t bH[4][2];
#pragma unroll
            for (int nb2 = 0; nb2 < 2; nb2++) {
                uint32_t bd = stg + bLane + (uint32_t)nb2 * (16 * SSTR) + kofs;
                uint32_t t4[4];
                LDSM4(t4, bd + SB_H);
                bH[nb2 * 2][0] = t4[0]; bH[nb2 * 2][1] = t4[1];
                bH[nb2 * 2 + 1][0] = t4[2]; bH[nb2 * 2 + 1][1] = t4[3];
            }
#pragma unroll
            for (int ma = 0; ma < 4; ma++) {
                uint32_t ad = stg + aLane + (uint32_t)ma * (16 * SSTR) + kofs;
                uint32_t aH[4], aL[4];
                LDSM4(aH, ad + SA_HI);
                LDSM4(aL, ad + SA_LO);
#pragma unroll
                for (int nb = 0; nb < 4; nb++) {
                    MMAH16816(acc[ma][nb], aH, bH[nb]);
                    MMAH16816(acc[ma][nb], aL, bH[nb]);
                }
            }
        }

        CP_WAIT0();
        __syncthreads();
    }

    const float* sb = (const float*)(smem + SBIAS);
#pragma unroll
    for (int ma = 0; ma < 4; ma++) {
        const int m0 = mtile * 128 + wm + ma * 16 + (lane >> 2);
#pragma unroll
        for (int nb = 0; nb < 4; nb++) {
            const int cl = wn + nb * 8 + (lane & 3) * 2;
            const float b0v = sb[cl], b1v = sb[cl + 1];
            const size_t col = (size_t)(ntile * 128 + cl);
            if (MODE == 0) {
                if (m0 < TDz * Bz) {
                    int orow = (m0 & 31) * TDz + (m0 >> 5);
                    float2 v;
                    v.x = acc[ma][nb][0] + b0v;
                    v.y = acc[ma][nb][1] + b1v;
                    *(float2*)(out + (size_t)orow * Nout + col) = v;
                }
                const int m1 = m0 + 8;
                if (m1 < TDz * Bz) {
                    int orow = (m1 & 31) * TDz + (m1 >> 5);
                    float2 v;
                    v.x = acc[ma][nb][2] + b0v;
                    v.y = acc[ma][nb][3] + b1v;
                    *(float2*)(out + (size_t)orow * Nout + col) = v;
                }
            } else {
                float2 v;
                v.x = acc[ma][nb][0] + b0v;
                v.y = acc[ma][nb][1] + b1v;
                *(float2*)(out + (size_t)m0 * Nout + col) = v;
                v.x = acc[ma][nb][2] + b0v;
                v.y = acc[ma][nb][3] + b1v;
                *(float2*)(out + (size_t)(m0 + 8) * Nout + col) = v;
            }
        }
    }
}

// ---------------- persistent LSTM (512 threads: unit = 2 warps, k-split) ----------------
__device__ __forceinline__ void load_w(const float* __restrict__ Whh, int u, int lane, int kh,
                                       unsigned long long (&w2)[4][4][2]) {
#pragma unroll
    for (int r = 0; r < 4; r++) {
        const float4* wr = (const float4*)(Whh + (size_t)(r * Hz + u) * Hz);
#pragma unroll
        for (int j = 0; j < 4; j++) {
            float4 v = wr[kh * 128 + j * 32 + lane];
            w2[r][j][0] = pk2(v.x, v.y);
            w2[r][j][1] = pk2(v.z, v.w);
        }
    }
}

__device__ __forceinline__ void dot4r(const unsigned long long (&w2)[4][4][2],
                                      const ulonglong2 (&hv)[4],
                                      unsigned long long (&acc)[4]) {
#pragma unroll
    for (int r = 0; r < 4; r++) acc[r] = 0ull;
#pragma unroll
    for (int j = 0; j < 4; j++) {
#pragma unroll
        for (int r = 0; r < 4; r++) {
            acc[r] = ffma2(w2[r][j][0], hv[j].x, acc[r]);
            acc[r] = ffma2(w2[r][j][1], hv[j].y, acc[r]);
        }
    }
}

__device__ __forceinline__ float reduce4(const unsigned long long (&acc)[4], int lane) {
    float2 p0 = upk2(acc[0]); float v0 = p0.x + p0.y;
    float2 p1 = upk2(acc[1]); float v1 = p1.x + p1.y;
    float2 p2 = upk2(acc[2]); float v2 = p2.x + p2.y;
    float2 p3 = upk2(acc[3]); float v3 = p3.x + p3.y;
    v0 += __shfl_xor_sync(0xffffffffu, v0, 1);
    v1 += __shfl_xor_sync(0xffffffffu, v1, 1);
    v2 += __shfl_xor_sync(0xffffffffu, v2, 1);
    v3 += __shfl_xor_sync(0xffffffffu, v3, 1);
    float a  = (lane & 1) ? v1 : v0;
    float bb = (lane & 1) ? v3 : v2;
    a  += __shfl_xor_sync(0xffffffffu, a, 2);
    bb += __shfl_xor_sync(0xffffffffu, bb, 2);
    float m = (lane & 2) ? bb : a;
    m += __shfl_xor_sync(0xffffffffu, m, 4);
    m += __shfl_xor_sync(0xffffffffu, m, 8);
    m += __shfl_xor_sync(0xffffffffu, m, 16);
    return m;
}

__device__ __forceinline__ float lstm_step_p(
    const unsigned long long (&w2)[4][4][2],
    const float* __restrict__ P, const float* __restrict__ hin,
    float* __restrict__ hout, float creg,
    float* __restrict__ sgf, float* __restrict__ sPf,
    int u0, int tid, int w, int lane, int kh)
{
#pragma unroll
    for (int k = 0; k < 2; k++) {
        int idx = tid + k * 512;
        int b = idx >> 5, c = idx & 31;
        sPf[b * 33 + c] = P[(size_t)b * Gz + (c >> 3) * Hz + u0 + (c & 7)];
    }

    const ulonglong2* h4 = (const ulonglong2*)hin;
    const int hoff = kh * 128;
    ulonglong2 hv[4];
#pragma unroll
    for (int j = 0; j < 4; j++) hv[j] = h4[hoff + j * 32 + lane];

    unsigned long long acc[2][4];
    dot4r(w2, hv, acc[0]);

#pragma unroll 2
    for (int b = 1; b < Bz; b++) {
#pragma unroll
        for (int j = 0; j < 4; j++) hv[j] = h4[b * 256 + hoff + j * 32 + lane];
        float m = reduce4(acc[(b - 1) & 1], lane);
        if (lane < 4) sgf[w * 132 + (b - 1) * 4 + lane] = m;
        dot4r(w2, hv, acc[b & 1]);
    }
    {
        float m = reduce4(acc[(Bz - 1) & 1], lane);
        if (lane < 4) sgf[w * 132 + (Bz - 1) * 4 + lane] = m;
    }
    __syncthreads();

    float newc = creg;
    if (tid < 256) {
        int ul = tid & 7, b = tid >> 3;
        const float* g0 = sgf + (2 * ul) * 132 + b * 4;
        const float* g1 = sgf + (2 * ul + 1) * 132 + b * 4;
        float gi = g0[0] + g1[0] + sPf[b * 33 +  0 + ul];
        float gf = g0[1] + g1[1] + sPf[b * 33 +  8 + ul];
        float gg = g0[2] + g1[2] + sPf[b * 33 + 16 + ul];
        float go = g0[3] + g1[3] + sPf[b * 33 + 24 + ul];
        float cc = sigm(gf) * creg + sigm(gi) * tanhf(gg);
        float hh = sigm(go) * tanhf(cc);
        hout[b * Hz + u0 + ul] = hh;
        newc = cc;
    }
    return newc;
}

__device__ void latent_dev(int b, int tid,
                           const int* __restrict__ tokens, const float* __restrict__ hs,
                           const float* __restrict__ Wmu, const float* __restrict__ bmu,
                           const float* __restrict__ Wlv, const float* __restrict__ blv,
                           const float* __restrict__ eps,
                           const float* __restrict__ Wl2h, const float* __restrict__ bl2h,
                           float* __restrict__ out_mean, float* __restrict__ out_lv,
                           float* __restrict__ hd0,
                           int* __restrict__ scnt, float* __restrict__ smean,
                           float* __restrict__ slv, float* __restrict__ szv) {
    int cnt = 0;
    if (tid < Sz) cnt = (tokens[b * Sz + tid] != 0) ? 1 : 0;
    scnt[tid] = cnt;
    __syncthreads();
    for (int off = 256; off >= 1; off >>= 1) {
        if (tid < off) scnt[tid] += scnt[tid + off];
        __syncthreads();
    }
    int last = scnt[0] - 1;
    if (last < 0) last = 0;

    const float* lh = hs + (size_t)(last + 1) * Bz * Hz + (size_t)b * Hz;
    if (tid < 256) {
        int j = tid & 127;
        const float* Wr = ((tid < 128) ? Wmu : Wlv) + (size_t)j * Hz;
        float acc = 0.f;
        const float4* l4 = (const float4*)lh;
        const float4* w4 = (const float4*)Wr;
#pragma unroll 4
        for (int k = 0; k < Hz / 4; k++) {
            float4 a = l4[k];
            float4 ww = w4[k];
            acc += a.x * ww.x + a.y * ww.y + a.z * ww.z + a.w * ww.w;
        }
        if (tid < 128) smean[j] = acc + bmu[j];
        else           slv[j]   = acc + blv[j];
    }
    __syncthreads();

    if (tid < 128) {
        float m = smean[tid];
        float lv = slv[tid];
        out_mean[b * Lz + tid] = m;
        out_lv[b * Lz + tid] = lv;
        szv[tid] = m + eps[b * Lz + tid] * expf(0.5f * lv);
    }
    __syncthreads();

#pragma unroll
    for (int r = 0; r < 2; r++) {
        int u = tid + r * 512;
        float acc = bl2h[u];
        const float* wr = Wl2h + (size_t)u * Lz;
#pragma unroll 4
        for (int l = 0; l < Lz; l++) acc += szv[l] * wr[l];
        hd0[b * Hz + u] = acc;
    }
}

__global__ __launch_bounds__(512, 1)
void lstm_persistent(const float* __restrict__ Whh_e, const float* __restrict__ Whh_d,
                     const float* __restrict__ Pe, const float* __restrict__ Pd,
                     float* __restrict__ hse, float* __restrict__ hsd,
                     const int* __restrict__ tokens,
                     const float* __restrict__ Wmu, const float* __restrict__ bmu,
                     const float* __restrict__ Wlv, const float* __restrict__ blv,
                     const float* __restrict__ eps,
                     const float* __restrict__ Wl2h, const float* __restrict__ bl2h,
                     float* __restrict__ out_mean, float* __restrict__ out_lv) {
    const int tid = threadIdx.x;
    const int w = tid >> 5;
    const int lane = tid & 31;
    const int ul = w >> 1;
    const int kh = w & 1;
    const int u0 = blockIdx.x * 8;
    const int u = u0 + ul;

    __shared__ float sgf[16 * 132];
    __shared__ float sPf[32 * 33];
    __shared__ int   scnt[512];
    __shared__ float smean[128], slvs[128], szv[128];

    unsigned long long w2[4][4][2];
    load_w(Whh_e, u, lane, kh, w2);

    float creg = 0.f;
    unsigned epoch = 0;

    for (int t = 0; t < Sz; t++) {
        creg = lstm_step_p(w2, Pe + (size_t)t * Bz * Gz,
                           hse + (size_t)t * Bz * Hz,
                           hse + (size_t)(t + 1) * Bz * Hz,
                           creg, sgf, sPf, u0, tid, w, lane, kh);
        epoch++;
        grid_sync_(epoch * NBLK);
    }

    load_w(Whh_d, u, lane, kh, w2);
    if (blockIdx.x < 32) {
        latent_dev(blockIdx.x, tid, tokens, hse, Wmu, bmu, Wlv, blv, eps,
                   Wl2h, bl2h, out_mean, out_lv, hsd,
                   scnt, smean, slvs, szv);
    }
    epoch++;
    grid_sync_(epoch * NBLK);

    creg = 0.f;
    for (int t = 0; t < TDz; t++) {
        creg = lstm_step_p(w2, Pd + (size_t)t * Bz * Gz,
                           hsd + (size_t)t * Bz * Hz,
                           hsd + (size_t)(t + 1) * Bz * Hz,
                           creg, sgf, sPf, u0, tid, w, lane, kh);
        if (t < TDz - 1) {
            epoch++;
            grid_sync_(epoch * NBLK);
        }
    }
}

// ---------------- launch ----------------
extern "C" void kernel_launch(void* const* d_in, const int* in_sizes, int n_in,
                              void* d_out, int out_size) {
    const int*   tokens  = (const int*)d_in[0];
    const float* emb_enc = (const float*)d_in[1];
    const float* Wih_e   = (const float*)d_in[2];
    const float* Whh_e   = (const float*)d_in[3];
    const float* bih_e   = (const float*)d_in[4];
    const float* bhh_e   = (const float*)d_in[5];
    const float* W_mu    = (const float*)d_in[6];
    const float* b_mu    = (const float*)d_in[7];
    const float* W_lv    = (const float*)d_in[8];
    const float* b_lv    = (const float*)d_in[9];
    const float* emb_dec = (const float*)d_in[10];
    const float* W_l2h   = (const float*)d_in[11];
    const float* b_l2h   = (const float*)d_in[12];
    const float* Wih_d   = (const float*)d_in[13];
    const float* Whh_d   = (const float*)d_in[14];
    const float* bih_d   = (const float*)d_in[15];
    const float* bhh_d   = (const float*)d_in[16];
    const float* W_out   = (const float*)d_in[17];
    const float* b_out   = (const float*)d_in[18];
    const float* epsv    = (const float*)d_in[19];

    float* out = (float*)d_out;
    const size_t LOGITS = (size_t)Bz * TDz * Vz;
    float* out_logits = out;
    float* out_mean   = out + LOGITS;
    float* out_lv     = out + LOGITS + (size_t)Bz * Lz;

    float *p_Pe, *p_hse, *p_Pd, *p_hsd;
    __half *p_Wh, *p_Ahi, *p_Alo;
    __half *p_Xeh, *p_Xel, *p_Xdh, *p_Xdl;
    __half *p_Wieh, *p_Widh;
    cudaGetSymbolAddress((void**)&p_Pe,  g_Pe);
    cudaGetSymbolAddress((void**)&p_hse, g_hse);
    cudaGetSymbolAddress((void**)&p_Pd,  g_Pd);
    cudaGetSymbolAddress((void**)&p_hsd, g_hsd);
    cudaGetSymbolAddress((void**)&p_Wh,  g_Wh);
    cudaGetSymbolAddress((void**)&p_Ahi, g_Ahi);
    cudaGetSymbolAddress((void**)&p_Alo, g_Alo);
    cudaGetSymbolAddress((void**)&p_Xeh, g_Xeh);
    cudaGetSymbolAddress((void**)&p_Xel, g_Xel);
    cudaGetSymbolAddress((void**)&p_Xdh, g_Xdh);
    cudaGetSymbolAddress((void**)&p_Xdl, g_Xdl);
    cudaGetSymbolAddress((void**)&p_Wieh, g_Wieh);
    cudaGetSymbolAddress((void**)&p_Widh, g_Widh);

    cudaFuncSetAttribute(mma2_kernel<512, 1>, cudaFuncAttributeMaxDynamicSharedMemorySize, SMEM_MMA);
    cudaFuncSetAttribute(mma2_kernel<1024, 0>, cudaFuncAttributeMaxDynamicSharedMemorySize, SMEM_MMA);

    // 1) zero encoder h0 slot; reset grid barrier
    init_kernel<<<64, 256>>>(p_hse, Bz * Hz);

    // 2) embeddings fused with fp16 split
    embed_split_kernel<<<1024, 256>>>(tokens, emb_enc, p_Xeh, p_Xel, Sz, 0);
    embed_split_kernel<<<1024, 256>>>(tokens, emb_dec, p_Xdh, p_Xdl, TDz, 1);

    // 2b) Wih fp16 converts (single precision level)
    convert_w_kernel<<<1024, 256>>>(Wih_e, p_Wieh, Gz * Ez / 4);
    convert_w_kernel<<<1024, 256>>>(Wih_d, p_Widh, Gz * Ez / 4);

    // 3) input projections via fp16 2-term mma (K=512)
    {
        dim3 grid(32, 32);
        mma2_kernel<512, 1><<<grid, 256, SMEM_MMA>>>(p_Xeh, p_Xel, p_Wieh,
                                                     bih_e, bhh_e, p_Pe, Gz);
        mma2_kernel<512, 1><<<grid, 256, SMEM_MMA>>>(p_Xdh, p_Xdl, p_Widh,
                                                     bih_d, bhh_d, p_Pd, Gz);
    }

    // 3b) W_out fp16 convert
    convert_w_kernel<<<4096, 256>>>(W_out, p_Wh, (int)((size_t)Vz * Hz / 4));

    // 4+5+6) recurrences + latent head, one persistent kernel (512 threads)
    lstm_persistent<<<NBLK, 512>>>(Whh_e, Whh_d, p_Pe, p_Pd, p_hse, p_hsd,
                                   tokens, W_mu, b_mu, W_lv, b_lv, epsv,
                                   W_l2h, b_l2h, out_mean, out_lv);

    // 6b) hd fp16 split
    convert_a_kernel<<<1024, 256>>>(p_hsd, p_Ahi, p_Alo);

    // 7) logits via fp16 2-term mma (K=1024)
    {
        dim3 grid(32, 250);
        mma2_kernel<1024, 0><<<grid, 256, SMEM_MMA>>>(p_Ahi, p_Alo, p_Wh,
                                                      b_out, b_out, out_logits, Vz);
    }
}

// round 14
// speedup vs baseline: 1.4629x; 1.1412x over previous
#include <cuda_runtime.h>
#include <cuda_bf16.h>
#include <cuda_fp16.h>
#include <math.h>
#include <stdint.h>

// Problem dims
#define Bz 32
#define Sz 128
#define Ez 512
#define Hz 1024
#define Gz 4096   // 4*H
#define Lz 128
#define Vz 32000
#define TDz 126   // S-2
#define NBLK 128  // persistent grid size

// ---------------- scratch (device globals; no runtime allocation) ----------------
__device__ float g_Pe[(size_t)Sz * Bz * Gz];
__device__ float g_hse[(Sz + 1) * Bz * Hz];
__device__ float g_Pd[(size_t)4096 * Gz];          // padded to 4096 rows
__device__ float g_hsd[(TDz + 1) * Bz * Hz];
__device__ unsigned g_bar;
// fp16 buffers
__device__ __half g_Wh[(size_t)Vz * Hz];
__device__ __half g_Ah[4096 * Hz];                 // rows >= 4032 stay zero (BSS, never written)
__device__ __half g_Xeh[4096 * Ez];
__device__ __half g_Xel[4096 * Ez];
__device__ __half g_Xdh[4096 * Ez];                // rows >= 4032 stay zero (BSS)
__device__ __half g_Xdl[4096 * Ez];
__device__ __half g_Wieh[Gz * Ez];
__device__ __half g_Widh[Gz * Ez];

// ---------------- f32x2 helpers ----------------
__device__ __forceinline__ unsigned long long pk2(float x, float y) {
    unsigned long long r;
    asm("mov.b64 %0, {%1,%2};" : "=l"(r) : "f"(x), "f"(y));
    return r;
}
__device__ __forceinline__ float2 upk2(unsigned long long v) {
    float2 r;
    asm("mov.b64 {%0,%1}, %2;" : "=f"(r.x), "=f"(r.y) : "l"(v));
    return r;
}
__device__ __forceinline__ unsigned long long ffma2(unsigned long long a, unsigned long long b,
                                                    unsigned long long c) {
    unsigned long long d;
    asm("fma.rn.f32x2 %0, %1, %2, %3;" : "=l"(d) : "l"(a), "l"(b), "l"(c));
    return d;
}
__device__ __forceinline__ float sigm(float x) { return 1.0f / (1.0f + expf(-x)); }

__device__ __forceinline__ uint32_t smem_u32(const void* p) {
    uint32_t a;
    asm("{ .reg .u64 t; cvta.to.shared.u64 t, %1; cvt.u32.u64 %0, t; }" : "=r"(a) : "l"(p));
    return a;
}

// ---------------- mma.sync + cp.async helpers (compute_103-safe PTX) ----------------
#define LDSM4(d, addr) \
    asm volatile("ldmatrix.sync.aligned.m8n8.x4.shared.b16 {%0,%1,%2,%3}, [%4];" \
        : "=r"((d)[0]), "=r"((d)[1]), "=r"((d)[2]), "=r"((d)[3]) : "r"(addr))

#define MMAH16816(c, a, b) \
    asm volatile("mma.sync.aligned.m16n8k16.row.col.f32.f16.f16.f32 " \
        "{%0,%1,%2,%3}, {%4,%5,%6,%7}, {%8,%9}, {%0,%1,%2,%3};" \
        : "+f"((c)[0]), "+f"((c)[1]), "+f"((c)[2]), "+f"((c)[3]) \
        : "r"((a)[0]), "r"((a)[1]), "r"((a)[2]), "r"((a)[3]), "r"((b)[0]), "r"((b)[1]))

#define CP_ASYNC16(smaddr, gptr) \
    asm volatile("cp.async.cg.shared.global [%0], [%1], 16;" :: "r"(smaddr), "l"(gptr))
#define CP_COMMIT() asm volatile("cp.async.commit_group;" ::: "memory")
#define CP_WAIT0()  asm volatile("cp.async.wait_group 0;" ::: "memory")

// ---------------- grid barrier ----------------
__device__ __forceinline__ void grid_sync_(unsigned target) {
    __syncthreads();
    if (threadIdx.x == 0) {
        __threadfence();
        atomicAdd(&g_bar, 1u);
        unsigned v;
        do {
            asm volatile("ld.global.acquire.gpu.u32 %0, [%1];" : "=r"(v) : "l"(&g_bar));
        } while (v < target);
    }
    __syncthreads();
}

// ---------------- init ----------------
__global__ void init_kernel(float* __restrict__ h0, int n) {
    int i = blockIdx.x * blockDim.x + threadIdx.x;
    int stride = gridDim.x * blockDim.x;
    for (; i < n; i += stride) h0[i] = 0.0f;
    if (blockIdx.x == 0 && threadIdx.x == 0) g_bar = 0u;
}

// ---------------- embedding gather fused with fp16 hi/lo split ----------------
__global__ void embed_split_kernel(const int* __restrict__ tokens, const float* __restrict__ emb,
                                   __half* __restrict__ hi, __half* __restrict__ lo,
                                   int T, int toff) {
    int total4 = T * Bz * (Ez / 4);
    int i = blockIdx.x * blockDim.x + threadIdx.x;
    int stride = gridDim.x * blockDim.x;
    const int E4 = Ez / 4;
    for (; i < total4; i += stride) {
        int e4 = i % E4;
        int r  = i / E4;
        int b  = r % Bz;
        int t  = r / Bz;
        int tok = tokens[b * Sz + t + toff];
        float4 v = ((const float4*)(emb + (size_t)tok * Ez))[e4];
        __half h0 = __float2half_rn(v.x);
        __half h1 = __float2half_rn(v.y);
        __half h2 = __float2half_rn(v.z);
        __half h3 = __float2half_rn(v.w);
        __half2 ha; ha.x = h0; ha.y = h1;
        __half2 hb; hb.x = h2; hb.y = h3;
        ((__half2*)hi)[i * 2]     = ha;
        ((__half2*)hi)[i * 2 + 1] = hb;
        __half2 la, lb;
        la.x = __float2half_rn(v.x - __half2float(h0));
        la.y = __float2half_rn(v.y - __half2float(h1));
        lb.x = __float2half_rn(v.z - __half2float(h2));
        lb.y = __float2half_rn(v.w - __half2float(h3));
        ((__half2*)lo)[i * 2]     = la;
        ((__half2*)lo)[i * 2 + 1] = lb;
    }
}

// ---------------- single fp16 convert (W side) ----------------
__global__ void convert_w_kernel(const float* __restrict__ W, __half* __restrict__ out, int n4) {
    int i = blockIdx.x * blockDim.x + threadIdx.x;
    int stride = gridDim.x * blockDim.x;
    for (; i < n4; i += stride) {
        float4 v = ((const float4*)W)[i];
        __half2 a; a.x = __float2half_rn(v.x); a.y = __float2half_rn(v.y);
        __half2 b; b.x = __float2half_rn(v.z); b.y = __float2half_rn(v.w);
        ((__half2*)out)[i * 2]     = a;
        ((__half2*)out)[i * 2 + 1] = b;
    }
}

// ---------------- fp16 2-term mma GEMM (A 2-split, W single) — input projections ----------------
#define SSTR   80
#define SA_HI  0
#define SA_LO  10240
#define SB_H2  20480
#define STAGE2 30720
#define SBIAS2 (2 * STAGE2)
#define SMEM_MMA2 (2 * STAGE2 + 512)

template <int KDIM>
__global__ __launch_bounds__(256, 2)
void mma2_kernel(const __half* __restrict__ Ahi, const __half* __restrict__ Alo,
                 const __half* __restrict__ Wh,
                 const float* __restrict__ bias1, const float* __restrict__ bias2,
                 float* __restrict__ out, int Nout) {
    extern __shared__ char smem[];
    const uint32_t sbase = smem_u32(smem);
    const int tid = threadIdx.x;
    const int w = tid >> 5, lane = tid & 31;
    const int mtile = blockIdx.x;
    const int ntile = blockIdx.y;
    const int wm = (w & 1) * 64;
    const int wn = (w >> 1) * 32;

    if (tid < 128)
        ((float*)(smem + SBIAS2))[tid] = bias1[ntile * 128 + tid] + bias2[ntile * 128 + tid];

    const int row = tid >> 2;
    const int ko  = (tid & 3) * 8;
    const __half* gA0h = Ahi + (size_t)(mtile * 128 + row) * KDIM + ko;
    const __half* gA1h = Ahi + (size_t)(mtile * 128 + row + 64) * KDIM + ko;
    const __half* gA0l = Alo + (size_t)(mtile * 128 + row) * KDIM + ko;
    const __half* gA1l = Alo + (size_t)(mtile * 128 + row + 64) * KDIM + ko;
    const __half* gB0  = Wh + (size_t)(ntile * 128 + row) * KDIM + ko;
    const __half* gB1  = Wh + (size_t)(ntile * 128 + row + 64) * KDIM + ko;
    const uint32_t s0 = sbase + row * SSTR + ko * 2;
    const uint32_t s1 = sbase + (row + 64) * SSTR + ko * 2;

    const uint32_t aLane = sbase + (uint32_t)(wm + (lane & 15)) * SSTR + (uint32_t)(lane >> 4) * 16;
    const uint32_t bLane = sbase + (uint32_t)(wn + (lane & 7) + ((lane >> 4) << 3)) * SSTR +
                           (uint32_t)((lane >> 3) & 1) * 16;

    float acc[4][4][4];
#pragma unroll
    for (int i = 0; i < 4; i++)
#pragma unroll
        for (int j = 0; j < 4; j++)
#pragma unroll
            for (int q = 0; q < 4; q++) acc[i][j][q] = 0.f;

    CP_ASYNC16(s0 + SA_HI, gA0h); CP_ASYNC16(s1 + SA_HI, gA1h);
    CP_ASYNC16(s0 + SA_LO, gA0l); CP_ASYNC16(s1 + SA_LO, gA1l);
    CP_ASYNC16(s0 + SB_H2, gB0);  CP_ASYNC16(s1 + SB_H2, gB1);
    CP_COMMIT();
    CP_WAIT0();
    __syncthreads();

    const int NT = KDIM / 32;
    for (int kt = 0; kt < NT; kt++) {
        const uint32_t stg = (uint32_t)(kt & 1) * STAGE2;

        if (kt < NT - 1) {
            const uint32_t nstg = (uint32_t)((kt + 1) & 1) * STAGE2;
            const int go = (kt + 1) * 32;
            CP_ASYNC16(s0 + nstg + SA_HI, gA0h + go); CP_ASYNC16(s1 + nstg + SA_HI, gA1h + go);
            CP_ASYNC16(s0 + nstg + SA_LO, gA0l + go); CP_ASYNC16(s1 + nstg + SA_LO, gA1l + go);
            CP_ASYNC16(s0 + nstg + SB_H2, gB0 + go);  CP_ASYNC16(s1 + nstg + SB_H2, gB1 + go);
            CP_COMMIT();
        }

#pragma unroll
        for (int ks = 0; ks < 2; ks++) {
            const uint32_t kofs = (uint32_t)ks * 32;
            uint32_t bH[4][2];
#pragma unroll
            for (int nb2 = 0; nb2 < 2; nb2++) {
                uint32_t bd = stg + bLane + (uint32_t)nb2 * (16 * SSTR) + kofs;
                uint32_t t4[4];
                LDSM4(t4, bd + SB_H2);
                bH[nb2 * 2][0] = t4[0]; bH[nb2 * 2][1] = t4[1];
                bH[nb2 * 2 + 1][0] = t4[2]; bH[nb2 * 2 + 1][1] = t4[3];
            }
#pragma unroll
            for (int ma = 0; ma < 4; ma++) {
                uint32_t ad = stg + aLane + (uint32_t)ma * (16 * SSTR) + kofs;
                uint32_t aH[4], aL[4];
                LDSM4(aH, ad + SA_HI);
                LDSM4(aL, ad + SA_LO);
#pragma unroll
                for (int nb = 0; nb < 4; nb++) {
                    MMAH16816(acc[ma][nb], aH, bH[nb]);
                    MMAH16816(acc[ma][nb], aL, bH[nb]);
                }
            }
        }

        CP_WAIT0();
        __syncthreads();
    }

    const float* sb = (const float*)(smem + SBIAS2);
#pragma unroll
    for (int ma = 0; ma < 4; ma++) {
        const int m0 = mtile * 128 + wm + ma * 16 + (lane >> 2);
#pragma unroll
        for (int nb = 0; nb < 4; nb++) {
            const int cl = wn + nb * 8 + (lane & 3) * 2;
            const float b0v = sb[cl], b1v = sb[cl + 1];
            const size_t col = (size_t)(ntile * 128 + cl);
            float2 v;
            v.x = acc[ma][nb][0] + b0v;
            v.y = acc[ma][nb][1] + b1v;
            *(float2*)(out + (size_t)m0 * Nout + col) = v;
            v.x = acc[ma][nb][2] + b0v;
            v.y = acc[ma][nb][3] + b1v;
            *(float2*)(out + (size_t)(m0 + 8) * Nout + col) = v;
        }
    }
}

// ---------------- fp16 single-term mma GEMM — logits ----------------
#define SA_1   0
#define SB_1   10240
#define STAGE1 20480
#define SBIAS1 (2 * STAGE1)
#define SMEM_MMA1 (2 * STAGE1 + 512)

__global__ __launch_bounds__(256, 2)
void mma1_logits_kernel(const __half* __restrict__ Ah, const __half* __restrict__ Wh,
                        const float* __restrict__ bias, float* __restrict__ out) {
    const int KDIM = Hz;
    extern __shared__ char smem[];
    const uint32_t sbase = smem_u32(smem);
    const int tid = threadIdx.x;
    const int w = tid >> 5, lane = tid & 31;
    const int mtile = blockIdx.x;
    const int ntile = blockIdx.y;
    const int wm = (w & 1) * 64;
    const int wn = (w >> 1) * 32;

    if (tid < 128) ((float*)(smem + SBIAS1))[tid] = bias[ntile * 128 + tid];

    const int row = tid >> 2;
    const int ko  = (tid & 3) * 8;
    const __half* gA0 = Ah + (size_t)(mtile * 128 + row) * KDIM + ko;
    const __half* gA1 = Ah + (size_t)(mtile * 128 + row + 64) * KDIM + ko;
    const __half* gB0 = Wh + (size_t)(ntile * 128 + row) * KDIM + ko;
    const __half* gB1 = Wh + (size_t)(ntile * 128 + row + 64) * KDIM + ko;
    const uint32_t s0 = sbase + row * SSTR + ko * 2;
    const uint32_t s1 = sbase + (row + 64) * SSTR + ko * 2;

    const uint32_t aLane = sbase + (uint32_t)(wm + (lane & 15)) * SSTR + (uint32_t)(lane >> 4) * 16;
    const uint32_t bLane = sbase + (uint32_t)(wn + (lane & 7) + ((lane >> 4) << 3)) * SSTR +
                           (uint32_t)((lane >> 3) & 1) * 16;

    float acc[4][4][4];
#pragma unroll
    for (int i = 0; i < 4; i++)
#pragma unroll
        for (int j = 0; j < 4; j++)
#pragma unroll
            for (int q = 0; q < 4; q++) acc[i][j][q] = 0.f;

    CP_ASYNC16(s0 + SA_1, gA0); CP_ASYNC16(s1 + SA_1, gA1);
    CP_ASYNC16(s0 + SB_1, gB0); CP_ASYNC16(s1 + SB_1, gB1);
    CP_COMMIT();
    CP_WAIT0();
    __syncthreads();

    const int NT = KDIM / 32;
    for (int kt = 0; kt < NT; kt++) {
        const uint32_t stg = (uint32_t)(kt & 1) * STAGE1;

        if (kt < NT - 1) {
            const uint32_t nstg = (uint32_t)((kt + 1) & 1) * STAGE1;
            const int go = (kt + 1) * 32;
            CP_ASYNC16(s0 + nstg + SA_1, gA0 + go); CP_ASYNC16(s1 + nstg + SA_1, gA1 + go);
            CP_ASYNC16(s0 + nstg + SB_1, gB0 + go); CP_ASYNC16(s1 + nstg + SB_1, gB1 + go);
            CP_COMMIT();
        }

#pragma unroll
        for (int ks = 0; ks < 2; ks++) {
            const uint32_t kofs = (uint32_t)ks * 32;
            uint32_t bH[4][2];
#pragma unroll
            for (int nb2 = 0; nb2 < 2; nb2++) {
                uint32_t bd = stg + bLane + (uint32_t)nb2 * (16 * SSTR) + kofs;
                uint32_t t4[4];
                LDSM4(t4, bd + SB_1);
                bH[nb2 * 2][0] = t4[0]; bH[nb2 * 2][1] = t4[1];
                bH[nb2 * 2 + 1][0] = t4[2]; bH[nb2 * 2 + 1][1] = t4[3];
            }
#pragma unroll
            for (int ma = 0; ma < 4; ma++) {
                uint32_t ad = stg + aLane + (uint32_t)ma * (16 * SSTR) + kofs;
                uint32_t aH[4];
                LDSM4(aH, ad + SA_1);
#pragma unroll
                for (int nb = 0; nb < 4; nb++) {
                    MMAH16816(acc[ma][nb], aH, bH[nb]);
                }
            }
        }

        CP_WAIT0();
        __syncthreads();
    }

    const float* sb = (const float*)(smem + SBIAS1);
#pragma unroll
    for (int ma = 0; ma < 4; ma++) {
        const int m0 = mtile * 128 + wm + ma * 16 + (lane >> 2);
#pragma unroll
        for (int nb = 0; nb < 4; nb++) {
            const int cl = wn + nb * 8 + (lane & 3) * 2;
            const float b0v = sb[cl], b1v = sb[cl + 1];
            const size_t col = (size_t)(ntile * 128 + cl);
            if (m0 < TDz * Bz) {
                int orow = (m0 & 31) * TDz + (m0 >> 5);
                float2 v;
                v.x = acc[ma][nb][0] + b0v;
                v.y = acc[ma][nb][1] + b1v;
                *(float2*)(out + (size_t)orow * Vz + col) = v;
            }
            const int m1 = m0 + 8;
            if (m1 < TDz * Bz) {
                int orow = (m1 & 31) * TDz + (m1 >> 5);
                float2 v;
                v.x = acc[ma][nb][2] + b0v;
                v.y = acc[ma][nb][3] + b1v;
                *(float2*)(out + (size_t)orow * Vz + col) = v;
            }
        }
    }
}

// ---------------- persistent LSTM (512 threads: unit = 2 warps, k-split) ----------------
__device__ __forceinline__ void load_w(const float* __restrict__ Whh, int u, int lane, int kh,
                                       unsigned long long (&w2)[4][4][2]) {
#pragma unroll
    for (int r = 0; r < 4; r++) {
        const float4* wr = (const float4*)(Whh + (size_t)(r * Hz + u) * Hz);
#pragma unroll
        for (int j = 0; j < 4; j++) {
            float4 v = wr[kh * 128 + j * 32 + lane];
            w2[r][j][0] = pk2(v.x, v.y);
            w2[r][j][1] = pk2(v.z, v.w);
        }
    }
}

__device__ __forceinline__ void dot4r(const unsigned long long (&w2)[4][4][2],
                                      const ulonglong2 (&hv)[4],
                                      unsigned long long (&acc)[4]) {
#pragma unroll
    for (int r = 0; r < 4; r++) acc[r] = 0ull;
#pragma unroll
    for (int j = 0; j < 4; j++) {
#pragma unroll
        for (int r = 0; r < 4; r++) {
            acc[r] = ffma2(w2[r][j][0], hv[j].x, acc[r]);
            acc[r] = ffma2(w2[r][j][1], hv[j].y, acc[r]);
        }
    }
}

__device__ __forceinline__ float reduce4(const unsigned long long (&acc)[4], int lane) {
    float2 p0 = upk2(acc[0]); float v0 = p0.x + p0.y;
    float2 p1 = upk2(acc[1]); float v1 = p1.x + p1.y;
    float2 p2 = upk2(acc[2]); float v2 = p2.x + p2.y;
    float2 p3 = upk2(acc[3]); float v3 = p3.x + p3.y;
    v0 += __shfl_xor_sync(0xffffffffu, v0, 1);
    v1 += __shfl_xor_sync(0xffffffffu, v1, 1);
    v2 += __shfl_xor_sync(0xffffffffu, v2, 1);
    v3 += __shfl_xor_sync(0xffffffffu, v3, 1);
    float a  = (lane & 1) ? v1 : v0;
    float bb = (lane & 1) ? v3 : v2;
    a  += __shfl_xor_sync(0xffffffffu, a, 2);
    bb += __shfl_xor_sync(0xffffffffu, bb, 2);
    float m = (lane & 2) ? bb : a;
    m += __shfl_xor_sync(0xffffffffu, m, 4);
    m += __shfl_xor_sync(0xffffffffu, m, 8);
    m += __shfl_xor_sync(0xffffffffu, m, 16);
    return m;
}

// one LSTM step; ah_out != nullptr -> also emit fp16 h for the logits GEMM
__device__ __forceinline__ float lstm_step_p(
    const unsigned long long (&w2)[4][4][2],
    const float* __restrict__ P, const float* __restrict__ hin,
    float* __restrict__ hout, __half* __restrict__ ah_out, float creg,
    float* __restrict__ sgf, float* __restrict__ sPf,
    int u0, int tid, int w, int lane, int kh)
{
#pragma unroll
    for (int k = 0; k < 2; k++) {
        int idx = tid + k * 512;
        int b = idx >> 5, c = idx & 31;
        sPf[b * 33 + c] = P[(size_t)b * Gz + (c >> 3) * Hz + u0 + (c & 7)];
    }

    const ulonglong2* h4 = (const ulonglong2*)hin;
    const int hoff = kh * 128;
    ulonglong2 hv[4];
#pragma unroll
    for (int j = 0; j < 4; j++) hv[j] = h4[hoff + j * 32 + lane];

    unsigned long long acc[2][4];
    dot4r(w2, hv, acc[0]);

#pragma unroll 2
    for (int b = 1; b < Bz; b++) {
#pragma unroll
        for (int j = 0; j < 4; j++) hv[j] = h4[b * 256 + hoff + j * 32 + lane];
        float m = reduce4(acc[(b - 1) & 1], lane);
        if (lane < 4) sgf[w * 132 + (b - 1) * 4 + lane] = m;
        dot4r(w2, hv, acc[b & 1]);
    }
    {
        float m = reduce4(acc[(Bz - 1) & 1], lane);
        if (lane < 4) sgf[w * 132 + (Bz - 1) * 4 + lane] = m;
    }
    __syncthreads();

    float newc = creg;
    if (tid < 256) {
        int ul = tid & 7, b = tid >> 3;
        const float* g0 = sgf + (2 * ul) * 132 + b * 4;
        const float* g1 = sgf + (2 * ul + 1) * 132 + b * 4;
        float gi = g0[0] + g1[0] + sPf[b * 33 +  0 + ul];
        float gf = g0[1] + g1[1] + sPf[b * 33 +  8 + ul];
        float gg = g0[2] + g1[2] + sPf[b * 33 + 16 + ul];
        float go = g0[3] + g1[3] + sPf[b * 33 + 24 + ul];
        float cc = sigm(gf) * creg + sigm(gi) * tanhf(gg);
        float hh = sigm(go) * tanhf(cc);
        hout[b * Hz + u0 + ul] = hh;
        if (ah_out) ah_out[b * Hz + u0 + ul] = __float2half_rn(hh);
        newc = cc;
    }
    return newc;
}

__device__ void latent_dev(int b, int tid,
                           const int* __restrict__ tokens, const float* __restrict__ hs,
                           const float* __restrict__ Wmu, const float* __restrict__ bmu,
                           const float* __restrict__ Wlv, const float* __restrict__ blv,
                           const float* __restrict__ eps,
                           const float* __restrict__ Wl2h, const float* __restrict__ bl2h,
                           float* __restrict__ out_mean, float* __restrict__ out_lv,
                           float* __restrict__ hd0,
                           int* __restrict__ scnt, float* __restrict__ smean,
                           float* __restrict__ slv, float* __restrict__ szv) {
    int cnt = 0;
    if (tid < Sz) cnt = (tokens[b * Sz + tid] != 0) ? 1 : 0;
    scnt[tid] = cnt;
    __syncthreads();
    for (int off = 256; off >= 1; off >>= 1) {
        if (tid < off) scnt[tid] += scnt[tid + off];
        __syncthreads();
    }
    int last = scnt[0] - 1;
    if (last < 0) last = 0;

    const float* lh = hs + (size_t)(last + 1) * Bz * Hz + (size_t)b * Hz;
    if (tid < 256) {
        int j = tid & 127;
        const float* Wr = ((tid < 128) ? Wmu : Wlv) + (size_t)j * Hz;
        float acc = 0.f;
        const float4* l4 = (const float4*)lh;
        const float4* w4 = (const float4*)Wr;
#pragma unroll 4
        for (int k = 0; k < Hz / 4; k++) {
            float4 a = l4[k];
            float4 ww = w4[k];
            acc += a.x * ww.x + a.y * ww.y + a.z * ww.z + a.w * ww.w;
        }
        if (tid < 128) smean[j] = acc + bmu[j];
        else           slv[j]   = acc + blv[j];
    }
    __syncthreads();

    if (tid < 128) {
        float m = smean[tid];
        float lv = slv[tid];
        out_mean[b * Lz + tid] = m;
        out_lv[b * Lz + tid] = lv;
        szv[tid] = m + eps[b * Lz + tid] * expf(0.5f * lv);
    }
    __syncthreads();

#pragma unroll
    for (int r = 0; r < 2; r++) {
        int u = tid + r * 512;
        float acc = bl2h[u];
        const float* wr = Wl2h + (size_t)u * Lz;
#pragma unroll 4
        for (int l = 0; l < Lz; l++) acc += szv[l] * wr[l];
        hd0[b * Hz + u] = acc;
    }
}

__global__ __launch_bounds__(512, 1)
void lstm_persistent(const float* __restrict__ Whh_e, const float* __restrict__ Whh_d,
                     const float* __restrict__ Pe, const float* __restrict__ Pd,
                     float* __restrict__ hse, float* __restrict__ hsd,
                     __half* __restrict__ Ah,
                     const int* __restrict__ tokens,
                     const float* __restrict__ Wmu, const float* __restrict__ bmu,
                     const float* __restrict__ Wlv, const float* __restrict__ blv,
                     const float* __restrict__ eps,
                     const float* __restrict__ Wl2h, const float* __restrict__ bl2h,
                     float* __restrict__ out_mean, float* __restrict__ out_lv) {
    const int tid = threadIdx.x;
    const int w = tid >> 5;
    const int lane = tid & 31;
    const int ul = w >> 1;
    const int kh = w & 1;
    const int u0 = blockIdx.x * 8;
    const int u = u0 + ul;

    __shared__ float sgf[16 * 132];
    __shared__ float sPf[32 * 33];
    __shared__ int   scnt[512];
    __shared__ float smean[128], slvs[128], szv[128];

    unsigned long long w2[4][4][2];
    load_w(Whh_e, u, lane, kh, w2);

    float creg = 0.f;
    unsigned epoch = 0;

    for (int t = 0; t < Sz; t++) {
        creg = lstm_step_p(w2, Pe + (size_t)t * Bz * Gz,
                           hse + (size_t)t * Bz * Hz,
                           hse + (size_t)(t + 1) * Bz * Hz,
                           (__half*)0,
                           creg, sgf, sPf, u0, tid, w, lane, kh);
        epoch++;
        grid_sync_(epoch * NBLK);
    }

    load_w(Whh_d, u, lane, kh, w2);
    if (blockIdx.x < 32) {
        latent_dev(blockIdx.x, tid, tokens, hse, Wmu, bmu, Wlv, blv, eps,
                   Wl2h, bl2h, out_mean, out_lv, hsd,
                   scnt, smean, slvs, szv);
    }
    epoch++;
    grid_sync_(epoch * NBLK);

    creg = 0.f;
    for (int t = 0; t < TDz; t++) {
        creg = lstm_step_p(w2, Pd + (size_t)t * Bz * Gz,
                           hsd + (size_t)t * Bz * Hz,
                           hsd + (size_t)(t + 1) * Bz * Hz,
                           Ah + (size_t)t * Bz * Hz,
                           creg, sgf, sPf, u0, tid, w, lane, kh);
        if (t < TDz - 1) {
            epoch++;
            grid_sync_(epoch * NBLK);
        }
    }
}

// ---------------- launch ----------------
extern "C" void kernel_launch(void* const* d_in, const int* in_sizes, int n_in,
                              void* d_out, int out_size) {
    const int*   tokens  = (const int*)d_in[0];
    const float* emb_enc = (const float*)d_in[1];
    const float* Wih_e   = (const float*)d_in[2];
    const float* Whh_e   = (const float*)d_in[3];
    const float* bih_e   = (const float*)d_in[4];
    const float* bhh_e   = (const float*)d_in[5];
    const float* W_mu    = (const float*)d_in[6];
    const float* b_mu    = (const float*)d_in[7];
    const float* W_lv    = (const float*)d_in[8];
    const float* b_lv    = (const float*)d_in[9];
    const float* emb_dec = (const float*)d_in[10];
    const float* W_l2h   = (const float*)d_in[11];
    const float* b_l2h   = (const float*)d_in[12];
    const float* Wih_d   = (const float*)d_in[13];
    const float* Whh_d   = (const float*)d_in[14];
    const float* bih_d   = (const float*)d_in[15];
    const float* bhh_d   = (const float*)d_in[16];
    const float* W_out   = (const float*)d_in[17];
    const float* b_out   = (const float*)d_in[18];
    const float* epsv    = (const float*)d_in[19];

    float* out = (float*)d_out;
    const size_t LOGITS = (size_t)Bz * TDz * Vz;
    float* out_logits = out;
    float* out_mean   = out + LOGITS;
    float* out_lv     = out + LOGITS + (size_t)Bz * Lz;

    float *p_Pe, *p_hse, *p_Pd, *p_hsd;
    __half *p_Wh, *p_Ah;
    __half *p_Xeh, *p_Xel, *p_Xdh, *p_Xdl;
    __half *p_Wieh, *p_Widh;
    cudaGetSymbolAddress((void**)&p_Pe,  g_Pe);
    cudaGetSymbolAddress((void**)&p_hse, g_hse);
    cudaGetSymbolAddress((void**)&p_Pd,  g_Pd);
    cudaGetSymbolAddress((void**)&p_hsd, g_hsd);
    cudaGetSymbolAddress((void**)&p_Wh,  g_Wh);
    cudaGetSymbolAddress((void**)&p_Ah,  g_Ah);
    cudaGetSymbolAddress((void**)&p_Xeh, g_Xeh);
    cudaGetSymbolAddress((void**)&p_Xel, g_Xel);
    cudaGetSymbolAddress((void**)&p_Xdh, g_Xdh);
    cudaGetSymbolAddress((void**)&p_Xdl, g_Xdl);
    cudaGetSymbolAddress((void**)&p_Wieh, g_Wieh);
    cudaGetSymbolAddress((void**)&p_Widh, g_Widh);

    cudaFuncSetAttribute(mma2_kernel<512>, cudaFuncAttributeMaxDynamicSharedMemorySize, SMEM_MMA2);
    cudaFuncSetAttribute(mma1_logits_kernel, cudaFuncAttributeMaxDynamicSharedMemorySize, SMEM_MMA1);

    // 1) zero encoder h0 slot; reset grid barrier
    init_kernel<<<64, 256>>>(p_hse, Bz * Hz);

    // 2) embeddings fused with fp16 split
    embed_split_kernel<<<1024, 256>>>(tokens, emb_enc, p_Xeh, p_Xel, Sz, 0);
    embed_split_kernel<<<1024, 256>>>(tokens, emb_dec, p_Xdh, p_Xdl, TDz, 1);

    // 2b) Wih fp16 converts
    convert_w_kernel<<<1024, 256>>>(Wih_e, p_Wieh, Gz * Ez / 4);
    convert_w_kernel<<<1024, 256>>>(Wih_d, p_Widh, Gz * Ez / 4);

    // 3) input projections via fp16 2-term mma (K=512)
    {
        dim3 grid(32, 32);
        mma2_kernel<512><<<grid, 256, SMEM_MMA2>>>(p_Xeh, p_Xel, p_Wieh,
                                                   bih_e, bhh_e, p_Pe, Gz);
        mma2_kernel<512><<<grid, 256, SMEM_MMA2>>>(p_Xdh, p_Xdl, p_Widh,
                                                   bih_d, bhh_d, p_Pd, Gz);
    }

    // 3b) W_out fp16 convert
    convert_w_kernel<<<4096, 256>>>(W_out, p_Wh, (int)((size_t)Vz * Hz / 4));

    // 4+5+6) recurrences + latent head; decoder epilogue emits fp16 Ah directly
    lstm_persistent<<<NBLK, 512>>>(Whh_e, Whh_d, p_Pe, p_Pd, p_hse, p_hsd, p_Ah,
                                   tokens, W_mu, b_mu, W_lv, b_lv, epsv,
                                   W_l2h, b_l2h, out_mean, out_lv);

    // 7) logits via single-term fp16 mma (K=1024)
    {
        dim3 grid(32, 250);
        mma1_logits_kernel<<<grid, 256, SMEM_MMA1>>>(p_Ah, p_Wh, b_out, out_logits);
    }
}

// round 15
// speedup vs baseline: 2.3950x; 1.6372x over previous
#include <cuda_runtime.h>
#include <cuda_bf16.h>
#include <cuda_fp16.h>
#include <math.h>
#include <stdint.h>

// Problem dims
#define Bz 32
#define Sz 128
#define Ez 512
#define Hz 1024
#define Gz 4096   // 4*H
#define Lz 128
#define Vz 32000
#define TDz 126   // S-2
#define NBLK 128  // persistent grid size

// ---------------- scratch (device globals; no runtime allocation) ----------------
__device__ float g_Pe[(size_t)Sz * Bz * Gz];
__device__ float g_Pd[(size_t)4096 * Gz];            // padded to 4096 rows
__device__ unsigned g_bar;
// fp16 state + weights
__device__ __half g_Ahe[(Sz + 1) * Bz * Hz];         // encoder h (slot 0 = zeros, BSS)
__device__ __half g_Ahd[4160 * Hz];                  // decoder h; slot0=hd0; rows beyond stay zero
__device__ __half g_Wh[(size_t)Vz * Hz];
__device__ __half g_Xeh[4096 * Ez];
__device__ __half g_Xel[4096 * Ez];
__device__ __half g_Xdh[4096 * Ez];                  // rows >= 4032 stay zero (BSS)
__device__ __half g_Xdl[4096 * Ez];
__device__ __half g_Wieh[Gz * Ez];
__device__ __half g_Widh[Gz * Ez];
__device__ __half g_WhheH[(size_t)Gz * Hz];
__device__ __half g_WhheL[(size_t)Gz * Hz];
__device__ __half g_WhhdH[(size_t)Gz * Hz];
__device__ __half g_WhhdL[(size_t)Gz * Hz];

// ---------------- helpers ----------------
__device__ __forceinline__ float sigm(float x) { return 1.0f / (1.0f + expf(-x)); }

__device__ __forceinline__ uint32_t smem_u32(const void* p) {
    uint32_t a;
    asm("{ .reg .u64 t; cvta.to.shared.u64 t, %1; cvt.u32.u64 %0, t; }" : "=r"(a) : "l"(p));
    return a;
}

#define LDSM4(d, addr) \
    asm volatile("ldmatrix.sync.aligned.m8n8.x4.shared.b16 {%0,%1,%2,%3}, [%4];" \
        : "=r"((d)[0]), "=r"((d)[1]), "=r"((d)[2]), "=r"((d)[3]) : "r"(addr))
#define LDSM2(d, addr) \
    asm volatile("ldmatrix.sync.aligned.m8n8.x2.shared.b16 {%0,%1}, [%2];" \
        : "=r"((d)[0]), "=r"((d)[1]) : "r"(addr))

#define MMAH16816(c, a, b) \
    asm volatile("mma.sync.aligned.m16n8k16.row.col.f32.f16.f16.f32 " \
        "{%0,%1,%2,%3}, {%4,%5,%6,%7}, {%8,%9}, {%0,%1,%2,%3};" \
        : "+f"((c)[0]), "+f"((c)[1]), "+f"((c)[2]), "+f"((c)[3]) \
        : "r"((a)[0]), "r"((a)[1]), "r"((a)[2]), "r"((a)[3]), "r"((b)[0]), "r"((b)[1]))

#define CP_ASYNC16(smaddr, gptr) \
    asm volatile("cp.async.cg.shared.global [%0], [%1], 16;" :: "r"(smaddr), "l"(gptr))
#define CP_COMMIT() asm volatile("cp.async.commit_group;" ::: "memory")
#define CP_WAIT0()  asm volatile("cp.async.wait_group 0;" ::: "memory")

// ---------------- grid barrier ----------------
__device__ __forceinline__ void grid_sync_(unsigned target) {
    __syncthreads();
    if (threadIdx.x == 0) {
        __threadfence();
        atomicAdd(&g_bar, 1u);
        unsigned v;
        do {
            asm volatile("ld.global.acquire.gpu.u32 %0, [%1];" : "=r"(v) : "l"(&g_bar));
        } while (v < target);
    }
    __syncthreads();
}

// ---------------- init (barrier reset only; h0 buffers are BSS-zero, never overwritten) ----------------
__global__ void init_kernel() {
    if (threadIdx.x == 0) g_bar = 0u;
}

// ---------------- embedding gather fused with fp16 hi/lo split ----------------
__global__ void embed_split_kernel(const int* __restrict__ tokens, const float* __restrict__ emb,
                                   __half* __restrict__ hi, __half* __restrict__ lo,
                                   int T, int toff) {
    int total4 = T * Bz * (Ez / 4);
    int i = blockIdx.x * blockDim.x + threadIdx.x;
    int stride = gridDim.x * blockDim.x;
    const int E4 = Ez / 4;
    for (; i < total4; i += stride) {
        int e4 = i % E4;
        int r  = i / E4;
        int b  = r % Bz;
        int t  = r / Bz;
        int tok = tokens[b * Sz + t + toff];
        float4 v = ((const float4*)(emb + (size_t)tok * Ez))[e4];
        __half h0 = __float2half_rn(v.x);
        __half h1 = __float2half_rn(v.y);
        __half h2 = __float2half_rn(v.z);
        __half h3 = __float2half_rn(v.w);
        __half2 ha; ha.x = h0; ha.y = h1;
        __half2 hb; hb.x = h2; hb.y = h3;
        ((__half2*)hi)[i * 2]     = ha;
        ((__half2*)hi)[i * 2 + 1] = hb;
        __half2 la, lb;
        la.x = __float2half_rn(v.x - __half2float(h0));
        la.y = __float2half_rn(v.y - __half2float(h1));
        lb.x = __float2half_rn(v.z - __half2float(h2));
        lb.y = __float2half_rn(v.w - __half2float(h3));
        ((__half2*)lo)[i * 2]     = la;
        ((__half2*)lo)[i * 2 + 1] = lb;
    }
}

// ---------------- fp16 converts ----------------
__global__ void convert_w_kernel(const float* __restrict__ W, __half* __restrict__ out, int n4) {
    int i = blockIdx.x * blockDim.x + threadIdx.x;
    int stride = gridDim.x * blockDim.x;
    for (; i < n4; i += stride) {
        float4 v = ((const float4*)W)[i];
        __half2 a; a.x = __float2half_rn(v.x); a.y = __float2half_rn(v.y);
        __half2 b; b.x = __float2half_rn(v.z); b.y = __float2half_rn(v.w);
        ((__half2*)out)[i * 2]     = a;
        ((__half2*)out)[i * 2 + 1] = b;
    }
}

__global__ void convert_w2_kernel(const float* __restrict__ W, __half* __restrict__ hi,
                                  __half* __restrict__ lo, int n4) {
    int i = blockIdx.x * blockDim.x + threadIdx.x;
    int stride = gridDim.x * blockDim.x;
    for (; i < n4; i += stride) {
        float4 v = ((const float4*)W)[i];
        __half h0 = __float2half_rn(v.x);
        __half h1 = __float2half_rn(v.y);
        __half h2 = __float2half_rn(v.z);
        __half h3 = __float2half_rn(v.w);
        __half2 ha; ha.x = h0; ha.y = h1;
        __half2 hb; hb.x = h2; hb.y = h3;
        ((__half2*)hi)[i * 2]     = ha;
        ((__half2*)hi)[i * 2 + 1] = hb;
        __half2 la, lb;
        la.x = __float2half_rn(v.x - __half2float(h0));
        la.y = __float2half_rn(v.y - __half2float(h1));
        lb.x = __float2half_rn(v.z - __half2float(h2));
        lb.y = __float2half_rn(v.w - __half2float(h3));
        ((__half2*)lo)[i * 2]     = la;
        ((__half2*)lo)[i * 2 + 1] = lb;
    }
}

// ---------------- fp16 2-term mma GEMM — input projections ----------------
#define SSTR   80
#define SA_HI  0
#define SA_LO  10240
#define SB_H2  20480
#define STAGE2 30720
#define SBIAS2 (2 * STAGE2)
#define SMEM_MMA2 (2 * STAGE2 + 512)

template <int KDIM>
__global__ __launch_bounds__(256, 2)
void mma2_kernel(const __half* __restrict__ Ahi, const __half* __restrict__ Alo,
                 const __half* __restrict__ Wh,
                 const float* __restrict__ bias1, const float* __restrict__ bias2,
                 float* __restrict__ out, int Nout) {
    extern __shared__ char smem[];
    const uint32_t sbase = smem_u32(smem);
    const int tid = threadIdx.x;
    const int w = tid >> 5, lane = tid & 31;
    const int mtile = blockIdx.x;
    const int ntile = blockIdx.y;
    const int wm = (w & 1) * 64;
    const int wn = (w >> 1) * 32;

    if (tid < 128)
        ((float*)(smem + SBIAS2))[tid] = bias1[ntile * 128 + tid] + bias2[ntile * 128 + tid];

    const int row = tid >> 2;
    const int ko  = (tid & 3) * 8;
    const __half* gA0h = Ahi + (size_t)(mtile * 128 + row) * KDIM + ko;
    const __half* gA1h = Ahi + (size_t)(mtile * 128 + row + 64) * KDIM + ko;
    const __half* gA0l = Alo + (size_t)(mtile * 128 + row) * KDIM + ko;
    const __half* gA1l = Alo + (size_t)(mtile * 128 + row + 64) * KDIM + ko;
    const __half* gB0  = Wh + (size_t)(ntile * 128 + row) * KDIM + ko;
    const __half* gB1  = Wh + (size_t)(ntile * 128 + row + 64) * KDIM + ko;
    const uint32_t s0 = sbase + row * SSTR + ko * 2;
    const uint32_t s1 = sbase + (row + 64) * SSTR + ko * 2;

    const uint32_t aLane = sbase + (uint32_t)(wm + (lane & 15)) * SSTR + (uint32_t)(lane >> 4) * 16;
    const uint32_t bLane = sbase + (uint32_t)(wn + (lane & 7) + ((lane >> 4) << 3)) * SSTR +
                           (uint32_t)((lane >> 3) & 1) * 16;

    float acc[4][4][4];
#pragma unroll
    for (int i = 0; i < 4; i++)
#pragma unroll
        for (int j = 0; j < 4; j++)
#pragma unroll
            for (int q = 0; q < 4; q++) acc[i][j][q] = 0.f;

    CP_ASYNC16(s0 + SA_HI, gA0h); CP_ASYNC16(s1 + SA_HI, gA1h);
    CP_ASYNC16(s0 + SA_LO, gA0l); CP_ASYNC16(s1 + SA_LO, gA1l);
    CP_ASYNC16(s0 + SB_H2, gB0);  CP_ASYNC16(s1 + SB_H2, gB1);
    CP_COMMIT();
    CP_WAIT0();
    __syncthreads();

    const int NT = KDIM / 32;
    for (int kt = 0; kt < NT; kt++) {
        const uint32_t stg = (uint32_t)(kt & 1) * STAGE2;

        if (kt < NT - 1) {
            const uint32_t nstg = (uint32_t)((kt + 1) & 1) * STAGE2;
            const int go = (kt + 1) * 32;
            CP_ASYNC16(s0 + nstg + SA_HI, gA0h + go); CP_ASYNC16(s1 + nstg + SA_HI, gA1h + go);
            CP_ASYNC16(s0 + nstg + SA_LO, gA0l + go); CP_ASYNC16(s1 + nstg + SA_LO, gA1l + go);
            CP_ASYNC16(s0 + nstg + SB_H2, gB0 + go);  CP_ASYNC16(s1 + nstg + SB_H2, gB1 + go);
            CP_COMMIT();
        }

#pragma unroll
        for (int ks = 0; ks < 2; ks++) {
            const uint32_t kofs = (uint32_t)ks * 32;
            uint32_t bH[4][2];
#pragma unroll
            for (int nb2 = 0; nb2 < 2; nb2++) {
                uint32_t bd = stg + bLane + (uint32_t)nb2 * (16 * SSTR) + kofs;
                uint32_t t4[4];
                LDSM4(t4, bd + SB_H2);
                bH[nb2 * 2][0] = t4[0]; bH[nb2 * 2][1] = t4[1];
                bH[nb2 * 2 + 1][0] = t4[2]; bH[nb2 * 2 + 1][1] = t4[3];
            }
#pragma unroll
            for (int ma = 0; ma < 4; ma++) {
                uint32_t ad = stg + aLane + (uint32_t)ma * (16 * SSTR) + kofs;
                uint32_t aH[4], aL[4];
                LDSM4(aH, ad + SA_HI);
                LDSM4(aL, ad + SA_LO);
#pragma unroll
                for (int nb = 0; nb < 4; nb++) {
                    MMAH16816(acc[ma][nb], aH, bH[nb]);
                    MMAH16816(acc[ma][nb], aL, bH[nb]);
                }
            }
        }

        CP_WAIT0();
        __syncthreads();
    }

    const float* sb = (const float*)(smem + SBIAS2);
#pragma unroll
    for (int ma = 0; ma < 4; ma++) {
        const int m0 = mtile * 128 + wm + ma * 16 + (lane >> 2);
#pragma unroll
        for (int nb = 0; nb < 4; nb++) {
            const int cl = wn + nb * 8 + (lane & 3) * 2;
            const float b0v = sb[cl], b1v = sb[cl + 1];
            const size_t col = (size_t)(ntile * 128 + cl);
            float2 v;
            v.x = acc[ma][nb][0] + b0v;
            v.y = acc[ma][nb][1] + b1v;
            *(float2*)(out + (size_t)m0 * Nout + col) = v;
            v.x = acc[ma][nb][2] + b0v;
            v.y = acc[ma][nb][3] + b1v;
            *(float2*)(out + (size_t)(m0 + 8) * Nout + col) = v;
        }
    }
}

// ---------------- fp16 single-term mma GEMM — logits ----------------
#define SA_1   0
#define SB_1   10240
#define STAGE1 20480
#define SBIAS1 (2 * STAGE1)
#define SMEM_MMA1 (2 * STAGE1 + 512)

__global__ __launch_bounds__(256, 2)
void mma1_logits_kernel(const __half* __restrict__ Ah, const __half* __restrict__ Wh,
                        const float* __restrict__ bias, float* __restrict__ out) {
    const int KDIM = Hz;
    extern __shared__ char smem[];
    const uint32_t sbase = smem_u32(smem);
    const int tid = threadIdx.x;
    const int w = tid >> 5, lane = tid & 31;
    const int mtile = blockIdx.x;
    const int ntile = blockIdx.y;
    const int wm = (w & 1) * 64;
    const int wn = (w >> 1) * 32;

    if (tid < 128) ((float*)(smem + SBIAS1))[tid] = bias[ntile * 128 + tid];

    const int row = tid >> 2;
    const int ko  = (tid & 3) * 8;
    const __half* gA0 = Ah + (size_t)(mtile * 128 + row) * KDIM + ko;
    const __half* gA1 = Ah + (size_t)(mtile * 128 + row + 64) * KDIM + ko;
    const __half* gB0 = Wh + (size_t)(ntile * 128 + row) * KDIM + ko;
    const __half* gB1 = Wh + (size_t)(ntile * 128 + row + 64) * KDIM + ko;
    const uint32_t s0 = sbase + row * SSTR + ko * 2;
    const uint32_t s1 = sbase + (row + 64) * SSTR + ko * 2;

    const uint32_t aLane = sbase + (uint32_t)(wm + (lane & 15)) * SSTR + (uint32_t)(lane >> 4) * 16;
    const uint32_t bLane = sbase + (uint32_t)(wn + (lane & 7) + ((lane >> 4) << 3)) * SSTR +
                           (uint32_t)((lane >> 3) & 1) * 16;

    float acc[4][4][4];
#pragma unroll
    for (int i = 0; i < 4; i++)
#pragma unroll
        for (int j = 0; j < 4; j++)
#pragma unroll
            for (int q = 0; q < 4; q++) acc[i][j][q] = 0.f;

    CP_ASYNC16(s0 + SA_1, gA0); CP_ASYNC16(s1 + SA_1, gA1);
    CP_ASYNC16(s0 + SB_1, gB0); CP_ASYNC16(s1 + SB_1, gB1);
    CP_COMMIT();
    CP_WAIT0();
    __syncthreads();

    const int NT = KDIM / 32;
    for (int kt = 0; kt < NT; kt++) {
        const uint32_t stg = (uint32_t)(kt & 1) * STAGE1;

        if (kt < NT - 1) {
            const uint32_t nstg = (uint32_t)((kt + 1) & 1) * STAGE1;
            const int go = (kt + 1) * 32;
            CP_ASYNC16(s0 + nstg + SA_1, gA0 + go); CP_ASYNC16(s1 + nstg + SA_1, gA1 + go);
            CP_ASYNC16(s0 + nstg + SB_1, gB0 + go); CP_ASYNC16(s1 + nstg + SB_1, gB1 + go);
            CP_COMMIT();
        }

#pragma unroll
        for (int ks = 0; ks < 2; ks++) {
            const uint32_t kofs = (uint32_t)ks * 32;
            uint32_t bH[4][2];
#pragma unroll
            for (int nb2 = 0; nb2 < 2; nb2++) {
                uint32_t bd = stg + bLane + (uint32_t)nb2 * (16 * SSTR) + kofs;
                uint32_t t4[4];
                LDSM4(t4, bd + SB_1);
                bH[nb2 * 2][0] = t4[0]; bH[nb2 * 2][1] = t4[1];
                bH[nb2 * 2 + 1][0] = t4[2]; bH[nb2 * 2 + 1][1] = t4[3];
            }
#pragma unroll
            for (int ma = 0; ma < 4; ma++) {
                uint32_t ad = stg + aLane + (uint32_t)ma * (16 * SSTR) + kofs;
                uint32_t aH[4];
                LDSM4(aH, ad + SA_1);
#pragma unroll
                for (int nb = 0; nb < 4; nb++) {
                    MMAH16816(acc[ma][nb], aH, bH[nb]);
                }
            }
        }

        CP_WAIT0();
        __syncthreads();
    }

    const float* sb = (const float*)(smem + SBIAS1);
#pragma unroll
    for (int ma = 0; ma < 4; ma++) {
        const int m0 = mtile * 128 + wm + ma * 16 + (lane >> 2);
#pragma unroll
        for (int nb = 0; nb < 4; nb++) {
            const int cl = wn + nb * 8 + (lane & 3) * 2;
            const float b0v = sb[cl], b1v = sb[cl + 1];
            const size_t col = (size_t)(ntile * 128 + cl);
            if (m0 < TDz * Bz) {
                int orow = (m0 & 31) * TDz + (m0 >> 5);
                float2 v;
                v.x = acc[ma][nb][0] + b0v;
                v.y = acc[ma][nb][1] + b1v;
                *(float2*)(out + (size_t)orow * Vz + col) = v;
            }
            const int m1 = m0 + 8;
            if (m1 < TDz * Bz) {
                int orow = (m1 & 31) * TDz + (m1 >> 5);
                float2 v;
                v.x = acc[ma][nb][2] + b0v;
                v.y = acc[ma][nb][3] + b1v;
                *(float2*)(out + (size_t)orow * Vz + col) = v;
            }
        }
    }
}

// ---------------- persistent LSTM: HMMA recurrence, smem-resident weights ----------------
// smem layout (bytes); rows are 2064B-strided (2048 data + 16 pad -> conflict-free ldmatrix)
#define ROWB   2064
#define SW_HI  0
#define SW_LO  66048
#define SH     132096
#define SGT    198144                 // float gates [32][33]
#define SPF    202368                 // float P [32*33]
#define SLAT   206592                 // latent scratch: int[512] + 3x float[128]
#define SMEM_LSTM (206592 + 2048 + 1536 + 64)

// load this block's 32 Whh rows (fp16 pre-split) into smem
__device__ __forceinline__ void load_whh_smem(const __half* __restrict__ WH,
                                              const __half* __restrict__ WL,
                                              char* smp, int u0, int w, int lane) {
#pragma unroll
    for (int rr = 0; rr < 2; rr++) {
        int n = w + rr * 16;                       // smem row 0..31
        size_t grow = ((size_t)(n >> 3) * Hz + u0 + (n & 7)) * Hz;
#pragma unroll
        for (int j = 0; j < 4; j++) {
            // conflict-free: lane*16B within a 512B j-chunk
            *(uint4*)(smp + SW_HI + n * ROWB + j * 512 + lane * 16) =
                *(const uint4*)(WH + grow + j * 256 + lane * 8);
            *(uint4*)(smp + SW_LO + n * ROWB + j * 512 + lane * 16) =
                *(const uint4*)(WL + grow + j * 256 + lane * 8);
        }
    }
}

// one LSTM step. gates = h @ (Whi+Wlo)^T via HMMA; c fp32 in registers; h emitted fp16.
__device__ __forceinline__ float lstm_step_mma(
    char* smp, uint32_t sbase,
    const float* __restrict__ P, const __half* __restrict__ hin,
    __half* __restrict__ hout, float creg,
    int u0, int tid, int w, int lane)
{
    // 1) cp.async h tile (32 x 1024 fp16) into smem
    {
        const __half* hs = hin;
#pragma unroll
        for (int rr = 0; rr < 2; rr++) {
            int n = w + rr * 16;
#pragma unroll
            for (int j = 0; j < 4; j++) {
                CP_ASYNC16(sbase + SH + n * ROWB + j * 512 + lane * 16,
                           hs + (size_t)n * Hz + j * 256 + lane * 8);
            }
        }
        CP_COMMIT();
    }
    // 2) P prefetch (plain loads; consumed after two syncthreads)
    {
        float* sPf = (float*)(smp + SPF);
#pragma unroll
        for (int k = 0; k < 2; k++) {
            int idx = tid + k * 512;
            int b = idx >> 5, c = idx & 31;
            sPf[b * 33 + c] = P[(size_t)b * Gz + (c >> 3) * Hz + u0 + (c & 7)];
        }
    }
    CP_WAIT0();
    __syncthreads();

    // 3) HMMA: warp -> (m-tile, n-tile, k-half)
    const int combo = w >> 1;
    const int mt = combo >> 2;       // 0..1
    const int nt = combo & 3;        // 0..3  (= gate index)
    const int kh = w & 1;

    float c4[4] = {0.f, 0.f, 0.f, 0.f};
    const uint32_t aBase = sbase + SH + (uint32_t)(mt * 16 + (lane & 15)) * ROWB +
                           (uint32_t)(lane >> 4) * 16;
    const uint32_t bRow = (uint32_t)(nt * 8 + (lane & 7)) * ROWB +
                          (uint32_t)((lane >> 3) & 1) * 16;

#pragma unroll 4
    for (int kt = kh * 32; kt < kh * 32 + 32; kt++) {
        const uint32_t ka = (uint32_t)kt * 32;
        uint32_t a[4];
        LDSM4(a, aBase + ka);
        uint32_t bh[2], bl[2];
        LDSM2(bh, sbase + SW_HI + bRow + ka);
        LDSM2(bl, sbase + SW_LO + bRow + ka);
        MMAH16816(c4, a, bh);
        MMAH16816(c4, a, bl);
    }

    // 4) k-half reduction via gates smem
    float* gt = (float*)(smp + SGT);
    const int mrow = mt * 16 + (lane >> 2);
    const int ncol = nt * 8 + (lane & 3) * 2;
    if (kh == 1) {
        gt[mrow * 33 + ncol]           = c4[0];
        gt[mrow * 33 + ncol + 1]       = c4[1];
        gt[(mrow + 8) * 33 + ncol]     = c4[2];
        gt[(mrow + 8) * 33 + ncol + 1] = c4[3];
    }
    __syncthreads();
    if (kh == 0) {
        gt[mrow * 33 + ncol]           += c4[0];
        gt[mrow * 33 + ncol + 1]       += c4[1];
        gt[(mrow + 8) * 33 + ncol]     += c4[2];
        gt[(mrow + 8) * 33 + ncol + 1] += c4[3];
    }
    __syncthreads();

    // 5) epilogue: tid<256 -> (ul = tid&7, b = tid>>3)
    float newc = creg;
    if (tid < 256) {
        const float* sPf = (const float*)(smp + SPF);
        int ul = tid & 7, b = tid >> 3;
        float gi = gt[b * 33 +  0 + ul] + sPf[b * 33 +  0 + ul];
        float gf = gt[b * 33 +  8 + ul] + sPf[b * 33 +  8 + ul];
        float gg = gt[b * 33 + 16 + ul] + sPf[b * 33 + 16 + ul];
        float go = gt[b * 33 + 24 + ul] + sPf[b * 33 + 24 + ul];
        float cc = sigm(gf) * creg + sigm(gi) * tanhf(gg);
        float hh = sigm(go) * tanhf(cc);
        hout[b * Hz + u0 + ul] = __float2half_rn(hh);
        newc = cc;
    }
    return newc;
}

// latent head (fp16 h input), 512 threads
__device__ void latent_dev(int b, int tid, char* smp,
                           const int* __restrict__ tokens, const __half* __restrict__ hs,
                           const float* __restrict__ Wmu, const float* __restrict__ bmu,
                           const float* __restrict__ Wlv, const float* __restrict__ blv,
                           const float* __restrict__ eps,
                           const float* __restrict__ Wl2h, const float* __restrict__ bl2h,
                           float* __restrict__ out_mean, float* __restrict__ out_lv,
                           __half* __restrict__ hd0) {
    int* scnt    = (int*)(smp + SLAT);
    float* smean = (float*)(smp + SLAT + 2048);
    float* slv   = smean + 128;
    float* szv   = slv + 128;

    int cnt = 0;
    if (tid < Sz) cnt = (tokens[b * Sz + tid] != 0) ? 1 : 0;
    scnt[tid] = cnt;
    __syncthreads();
    for (int off = 256; off >= 1; off >>= 1) {
        if (tid < off) scnt[tid] += scnt[tid + off];
        __syncthreads();
    }
    int last = scnt[0] - 1;
    if (last < 0) last = 0;

    const __half* lh = hs + (size_t)(last + 1) * Bz * Hz + (size_t)b * Hz;
    if (tid < 256) {
        int j = tid & 127;
        const float* Wr = ((tid < 128) ? Wmu : Wlv) + (size_t)j * Hz;
        float acc = 0.f;
        const __half2* l2 = (const __half2*)lh;
        const float2* w2 = (const float2*)Wr;
#pragma unroll 4
        for (int k = 0; k < Hz / 2; k++) {
            float2 a = __half22float2(l2[k]);
            float2 ww = w2[k];
            acc += a.x * ww.x + a.y * ww.y;
        }
        if (tid < 128) smean[j] = acc + bmu[j];
        else           slv[j]   = acc + blv[j];
    }
    __syncthreads();

    if (tid < 128) {
        float m = smean[tid];
        float lv = slv[tid];
        out_mean[b * Lz + tid] = m;
        out_lv[b * Lz + tid] = lv;
        szv[tid] = m + eps[b * Lz + tid] * expf(0.5f * lv);
    }
    __syncthreads();

#pragma unroll
    for (int r = 0; r < 2; r++) {
        int u = tid + r * 512;
        float acc = bl2h[u];
        const float* wr = Wl2h + (size_t)u * Lz;
#pragma unroll 4
        for (int l = 0; l < Lz; l++) acc += szv[l] * wr[l];
        hd0[b * Hz + u] = __float2half_rn(acc);
    }
}

__global__ __launch_bounds__(512, 1)
void lstm_persistent(const __half* __restrict__ WeH, const __half* __restrict__ WeL,
                     const __half* __restrict__ WdH, const __half* __restrict__ WdL,
                     const float* __restrict__ Pe, const float* __restrict__ Pd,
                     __half* __restrict__ Ahe, __half* __restrict__ Ahd,
                     const int* __restrict__ tokens,
                     const float* __restrict__ Wmu, const float* __restrict__ bmu,
                     const float* __restrict__ Wlv, const float* __restrict__ blv,
                     const float* __restrict__ eps,
                     const float* __restrict__ Wl2h, const float* __restrict__ bl2h,
                     float* __restrict__ out_mean, float* __restrict__ out_lv) {
    extern __shared__ char smp[];
    const uint32_t sbase = smem_u32(smp);
    const int tid = threadIdx.x;
    const int w = tid >> 5;
    const int lane = tid & 31;
    const int u0 = blockIdx.x * 8;

    load_whh_smem(WeH, WeL, smp, u0, w, lane);
    __syncthreads();

    float creg = 0.f;
    unsigned epoch = 0;

    // encoder: h(0) = Ahe slot 0 (BSS zeros, never written)
    for (int t = 0; t < Sz; t++) {
        creg = lstm_step_mma(smp, sbase, Pe + (size_t)t * Bz * Gz,
                             Ahe + (size_t)t * Bz * Hz,
                             Ahe + (size_t)(t + 1) * Bz * Hz,
                             creg, u0, tid, w, lane);
        epoch++;
        grid_sync_(epoch * NBLK);
    }

    // swap to decoder weights; blocks 0..31 compute the latent head (-> Ahd slot 0)
    load_whh_smem(WdH, WdL, smp, u0, w, lane);
    if (blockIdx.x < 32) {
        latent_dev(blockIdx.x, tid, smp, tokens, Ahe, Wmu, bmu, Wlv, blv, eps,
                   Wl2h, bl2h, out_mean, out_lv, Ahd);
    }
    epoch++;
    grid_sync_(epoch * NBLK);

    creg = 0.f;
    for (int t = 0; t < TDz; t++) {
        creg = lstm_step_mma(smp, sbase, Pd + (size_t)t * Bz * Gz,
                             Ahd + (size_t)t * Bz * Hz,
                             Ahd + (size_t)(t + 1) * Bz * Hz,
                             creg, u0, tid, w, lane);
        if (t < TDz - 1) {
            epoch++;
            grid_sync_(epoch * NBLK);
        }
    }
}

// ---------------- launch ----------------
extern "C" void kernel_launch(void* const* d_in, const int* in_sizes, int n_in,
                              void* d_out, int out_size) {
    const int*   tokens  = (const int*)d_in[0];
    const float* emb_enc = (const float*)d_in[1];
    const float* Wih_e   = (const float*)d_in[2];
    const float* Whh_e   = (const float*)d_in[3];
    const float* bih_e   = (const float*)d_in[4];
    const float* bhh_e   = (const float*)d_in[5];
    const float* W_mu    = (const float*)d_in[6];
    const float* b_mu    = (const float*)d_in[7];
    const float* W_lv    = (const float*)d_in[8];
    const float* b_lv    = (const float*)d_in[9];
    const float* emb_dec = (const float*)d_in[10];
    const float* W_l2h   = (const float*)d_in[11];
    const float* b_l2h   = (const float*)d_in[12];
    const float* Wih_d   = (const float*)d_in[13];
    const float* Whh_d   = (const float*)d_in[14];
    const float* bih_d   = (const float*)d_in[15];
    const float* bhh_d   = (const float*)d_in[16];
    const float* W_out   = (const float*)d_in[17];
    const float* b_out   = (const float*)d_in[18];
    const float* epsv    = (const float*)d_in[19];

    float* out = (float*)d_out;
    const size_t LOGITS = (size_t)Bz * TDz * Vz;
    float* out_logits = out;
    float* out_mean   = out + LOGITS;
    float* out_lv     = out + LOGITS + (size_t)Bz * Lz;

    float *p_Pe, *p_Pd;
    __half *p_Wh, *p_Ahe, *p_Ahd;
    __half *p_Xeh, *p_Xel, *p_Xdh, *p_Xdl;
    __half *p_Wieh, *p_Widh;
    __half *p_WeH, *p_WeL, *p_WdH, *p_WdL;
    cudaGetSymbolAddress((void**)&p_Pe,  g_Pe);
    cudaGetSymbolAddress((void**)&p_Pd,  g_Pd);
    cudaGetSymbolAddress((void**)&p_Wh,  g_Wh);
    cudaGetSymbolAddress((void**)&p_Ahe, g_Ahe);
    cudaGetSymbolAddress((void**)&p_Ahd, g_Ahd);
    cudaGetSymbolAddress((void**)&p_Xeh, g_Xeh);
    cudaGetSymbolAddress((void**)&p_Xel, g_Xel);
    cudaGetSymbolAddress((void**)&p_Xdh, g_Xdh);
    cudaGetSymbolAddress((void**)&p_Xdl, g_Xdl);
    cudaGetSymbolAddress((void**)&p_Wieh, g_Wieh);
    cudaGetSymbolAddress((void**)&p_Widh, g_Widh);
    cudaGetSymbolAddress((void**)&p_WeH, g_WhheH);
    cudaGetSymbolAddress((void**)&p_WeL, g_WhheL);
    cudaGetSymbolAddress((void**)&p_WdH, g_WhhdH);
    cudaGetSymbolAddress((void**)&p_WdL, g_WhhdL);

    cudaFuncSetAttribute(mma2_kernel<512>, cudaFuncAttributeMaxDynamicSharedMemorySize, SMEM_MMA2);
    cudaFuncSetAttribute(mma1_logits_kernel, cudaFuncAttributeMaxDynamicSharedMemorySize, SMEM_MMA1);
    cudaFuncSetAttribute(lstm_persistent, cudaFuncAttributeMaxDynamicSharedMemorySize, SMEM_LSTM);

    // 1) reset grid barrier
    init_kernel<<<1, 32>>>();

    // 2) embeddings fused with fp16 split
    embed_split_kernel<<<1024, 256>>>(tokens, emb_enc, p_Xeh, p_Xel, Sz, 0);
    embed_split_kernel<<<1024, 256>>>(tokens, emb_dec, p_Xdh, p_Xdl, TDz, 1);

    // 2b) weight converts: Wih single fp16; Whh fp16 2-split
    convert_w_kernel<<<1024, 256>>>(Wih_e, p_Wieh, Gz * Ez / 4);
    convert_w_kernel<<<1024, 256>>>(Wih_d, p_Widh, Gz * Ez / 4);
    convert_w2_kernel<<<1024, 256>>>(Whh_e, p_WeH, p_WeL, Gz * Hz / 4);
    convert_w2_kernel<<<1024, 256>>>(Whh_d, p_WdH, p_WdL, Gz * Hz / 4);

    // 3) input projections via fp16 2-term mma (K=512)
    {
        dim3 grid(32, 32);
        mma2_kernel<512><<<grid, 256, SMEM_MMA2>>>(p_Xeh, p_Xel, p_Wieh,
                                                   bih_e, bhh_e, p_Pe, Gz);
        mma2_kernel<512><<<grid, 256, SMEM_MMA2>>>(p_Xdh, p_Xdl, p_Widh,
                                                   bih_d, bhh_d, p_Pd, Gz);
    }

    // 3b) W_out fp16 convert
    convert_w_kernel<<<4096, 256>>>(W_out, p_Wh, (int)((size_t)Vz * Hz / 4));

    // 4+5+6) recurrences (HMMA) + latent head; decoder h IS the logits A matrix
    lstm_persistent<<<NBLK, 512, SMEM_LSTM>>>(p_WeH, p_WeL, p_WdH, p_WdL,
                                              p_Pe, p_Pd, p_Ahe, p_Ahd,
                                              tokens, W_mu, b_mu, W_lv, b_lv, epsv,
                                              W_l2h, b_l2h, out_mean, out_lv);

    // 7) logits via single-term fp16 mma (K=1024); A = decoder h slots 1..126
    {
        dim3 grid(32, 250);
        mma1_logits_kernel<<<grid, 256, SMEM_MMA1>>>(p_Ahd + (size_t)Bz * Hz, p_Wh,
                                                     b_out, out_logits);
    }
}

// round 16
// speedup vs baseline: 2.6321x; 1.0990x over previous
#include <cuda_runtime.h>
#include <cuda_bf16.h>
#include <cuda_fp16.h>
#include <math.h>
#include <stdint.h>

// Problem dims
#define Bz 32
#define Sz 128
#define Ez 512
#define Hz 1024
#define Gz 4096   // 4*H
#define Lz 128
#define Vz 32000
#define TDz 126   // S-2
#define NBLK 128  // persistent grid size

// ---------------- scratch (device globals; no runtime allocation) ----------------
__device__ float g_Pe[(size_t)Sz * Bz * Gz];
__device__ float g_Pd[(size_t)4096 * Gz];            // padded to 4096 rows
__device__ unsigned g_bar;
// fp16 state + weights
__device__ __half g_Ahe[(Sz + 1) * Bz * Hz];         // encoder h (slot 0 = zeros, BSS)
__device__ __half g_Ahd[4160 * Hz];                  // decoder h; slot0=hd0; tail rows stay zero
__device__ __half g_Wh[(size_t)Vz * Hz];
__device__ __half g_Xeh[4096 * Ez];
__device__ __half g_Xdh[4096 * Ez];                  // rows >= 4032 stay zero (BSS)
__device__ __half g_Wieh[Gz * Ez];
__device__ __half g_Widh[Gz * Ez];
__device__ __half g_WhheH[(size_t)Gz * Hz];
__device__ __half g_WhhdH[(size_t)Gz * Hz];

// ---------------- helpers ----------------
__device__ __forceinline__ float sigm(float x) { return 1.0f / (1.0f + expf(-x)); }

__device__ __forceinline__ uint32_t smem_u32(const void* p) {
    uint32_t a;
    asm("{ .reg .u64 t; cvta.to.shared.u64 t, %1; cvt.u32.u64 %0, t; }" : "=r"(a) : "l"(p));
    return a;
}

#define LDSM4(d, addr) \
    asm volatile("ldmatrix.sync.aligned.m8n8.x4.shared.b16 {%0,%1,%2,%3}, [%4];" \
        : "=r"((d)[0]), "=r"((d)[1]), "=r"((d)[2]), "=r"((d)[3]) : "r"(addr))
#define LDSM2(d, addr) \
    asm volatile("ldmatrix.sync.aligned.m8n8.x2.shared.b16 {%0,%1}, [%2];" \
        : "=r"((d)[0]), "=r"((d)[1]) : "r"(addr))

#define MMAH16816(c, a, b) \
    asm volatile("mma.sync.aligned.m16n8k16.row.col.f32.f16.f16.f32 " \
        "{%0,%1,%2,%3}, {%4,%5,%6,%7}, {%8,%9}, {%0,%1,%2,%3};" \
        : "+f"((c)[0]), "+f"((c)[1]), "+f"((c)[2]), "+f"((c)[3]) \
        : "r"((a)[0]), "r"((a)[1]), "r"((a)[2]), "r"((a)[3]), "r"((b)[0]), "r"((b)[1]))

#define CP_ASYNC16(smaddr, gptr) \
    asm volatile("cp.async.cg.shared.global [%0], [%1], 16;" :: "r"(smaddr), "l"(gptr))
#define CP_COMMIT() asm volatile("cp.async.commit_group;" ::: "memory")
#define CP_WAIT0()  asm volatile("cp.async.wait_group 0;" ::: "memory")

// ---------------- grid barrier ----------------
__device__ __forceinline__ void grid_sync_(unsigned target) {
    __syncthreads();
    if (threadIdx.x == 0) {
        __threadfence();
        atomicAdd(&g_bar, 1u);
        unsigned v;
        do {
            asm volatile("ld.global.acquire.gpu.u32 %0, [%1];" : "=r"(v) : "l"(&g_bar));
        } while (v < target);
    }
    __syncthreads();
}

// ---------------- init (barrier reset only) ----------------
__global__ void init_kernel() {
    if (threadIdx.x == 0) g_bar = 0u;
}

// ---------------- embedding gather -> fp16 ----------------
__global__ void embed_h_kernel(const int* __restrict__ tokens, const float* __restrict__ emb,
                               __half* __restrict__ hi, int T, int toff) {
    int total4 = T * Bz * (Ez / 4);
    int i = blockIdx.x * blockDim.x + threadIdx.x;
    int stride = gridDim.x * blockDim.x;
    const int E4 = Ez / 4;
    for (; i < total4; i += stride) {
        int e4 = i % E4;
        int r  = i / E4;
        int b  = r % Bz;
        int t  = r / Bz;
        int tok = tokens[b * Sz + t + toff];
        float4 v = ((const float4*)(emb + (size_t)tok * Ez))[e4];
        __half2 a; a.x = __float2half_rn(v.x); a.y = __float2half_rn(v.y);
        __half2 b2; b2.x = __float2half_rn(v.z); b2.y = __float2half_rn(v.w);
        ((__half2*)hi)[i * 2]     = a;
        ((__half2*)hi)[i * 2 + 1] = b2;
    }
}

// ---------------- fp16 convert ----------------
__global__ void convert_w_kernel(const float* __restrict__ W, __half* __restrict__ out, int n4) {
    int i = blockIdx.x * blockDim.x + threadIdx.x;
    int stride = gridDim.x * blockDim.x;
    for (; i < n4; i += stride) {
        float4 v = ((const float4*)W)[i];
        __half2 a; a.x = __float2half_rn(v.x); a.y = __float2half_rn(v.y);
        __half2 b; b.x = __float2half_rn(v.z); b.y = __float2half_rn(v.w);
        ((__half2*)out)[i * 2]     = a;
        ((__half2*)out)[i * 2 + 1] = b;
    }
}

// ---------------- fp16 single-term mma GEMM (proj + logits) ----------------
#define SSTR   80
#define SA_1   0
#define SB_1   10240
#define STAGE1 20480
#define SBIAS1 (2 * STAGE1)
#define SMEM_MMA1 (2 * STAGE1 + 512)

// MODE 0: logits — out[(b*TD+t)*Nout + n] = acc + bias1[n], guard m < TDz*Bz
// MODE 1: proj   — out[m*Nout + n] = acc + bias1[n] + bias2[n]
template <int KDIM, int MODE>
__global__ __launch_bounds__(256, 2)
void mma1_kernel(const __half* __restrict__ Ah, const __half* __restrict__ Wh,
                 const float* __restrict__ bias1, const float* __restrict__ bias2,
                 float* __restrict__ out, int Nout) {
    extern __shared__ char smem[];
    const uint32_t sbase = smem_u32(smem);
    const int tid = threadIdx.x;
    const int w = tid >> 5, lane = tid & 31;
    const int mtile = blockIdx.x;
    const int ntile = blockIdx.y;
    const int wm = (w & 1) * 64;
    const int wn = (w >> 1) * 32;

    if (tid < 128) {
        float bv = bias1[ntile * 128 + tid];
        if (MODE == 1) bv += bias2[ntile * 128 + tid];
        ((float*)(smem + SBIAS1))[tid] = bv;
    }

    const int row = tid >> 2;
    const int ko  = (tid & 3) * 8;
    const __half* gA0 = Ah + (size_t)(mtile * 128 + row) * KDIM + ko;
    const __half* gA1 = Ah + (size_t)(mtile * 128 + row + 64) * KDIM + ko;
    const __half* gB0 = Wh + (size_t)(ntile * 128 + row) * KDIM + ko;
    const __half* gB1 = Wh + (size_t)(ntile * 128 + row + 64) * KDIM + ko;
    const uint32_t s0 = sbase + row * SSTR + ko * 2;
    const uint32_t s1 = sbase + (row + 64) * SSTR + ko * 2;

    const uint32_t aLane = sbase + (uint32_t)(wm + (lane & 15)) * SSTR + (uint32_t)(lane >> 4) * 16;
    const uint32_t bLane = sbase + (uint32_t)(wn + (lane & 7) + ((lane >> 4) << 3)) * SSTR +
                           (uint32_t)((lane >> 3) & 1) * 16;

    float acc[4][4][4];
#pragma unroll
    for (int i = 0; i < 4; i++)
#pragma unroll
        for (int j = 0; j < 4; j++)
#pragma unroll
            for (int q = 0; q < 4; q++) acc[i][j][q] = 0.f;

    CP_ASYNC16(s0 + SA_1, gA0); CP_ASYNC16(s1 + SA_1, gA1);
    CP_ASYNC16(s0 + SB_1, gB0); CP_ASYNC16(s1 + SB_1, gB1);
    CP_COMMIT();
    CP_WAIT0();
    __syncthreads();

    const int NT = KDIM / 32;
    for (int kt = 0; kt < NT; kt++) {
        const uint32_t stg = (uint32_t)(kt & 1) * STAGE1;

        if (kt < NT - 1) {
            const uint32_t nstg = (uint32_t)((kt + 1) & 1) * STAGE1;
            const int go = (kt + 1) * 32;
            CP_ASYNC16(s0 + nstg + SA_1, gA0 + go); CP_ASYNC16(s1 + nstg + SA_1, gA1 + go);
            CP_ASYNC16(s0 + nstg + SB_1, gB0 + go); CP_ASYNC16(s1 + nstg + SB_1, gB1 + go);
            CP_COMMIT();
        }

#pragma unroll
        for (int ks = 0; ks < 2; ks++) {
            const uint32_t kofs = (uint32_t)ks * 32;
            uint32_t bH[4][2];
#pragma unroll
            for (int nb2 = 0; nb2 < 2; nb2++) {
                uint32_t bd = stg + bLane + (uint32_t)nb2 * (16 * SSTR) + kofs;
                uint32_t t4[4];
                LDSM4(t4, bd + SB_1);
                bH[nb2 * 2][0] = t4[0]; bH[nb2 * 2][1] = t4[1];
                bH[nb2 * 2 + 1][0] = t4[2]; bH[nb2 * 2 + 1][1] = t4[3];
            }
#pragma unroll
            for (int ma = 0; ma < 4; ma++) {
                uint32_t ad = stg + aLane + (uint32_t)ma * (16 * SSTR) + kofs;
                uint32_t aH[4];
                LDSM4(aH, ad + SA_1);
#pragma unroll
                for (int nb = 0; nb < 4; nb++) {
                    MMAH16816(acc[ma][nb], aH, bH[nb]);
                }
            }
        }

        CP_WAIT0();
        __syncthreads();
    }

    const float* sb = (const float*)(smem + SBIAS1);
#pragma unroll
    for (int ma = 0; ma < 4; ma++) {
        const int m0 = mtile * 128 + wm + ma * 16 + (lane >> 2);
#pragma unroll
        for (int nb = 0; nb < 4; nb++) {
            const int cl = wn + nb * 8 + (lane & 3) * 2;
            const float b0v = sb[cl], b1v = sb[cl + 1];
            const size_t col = (size_t)(ntile * 128 + cl);
            if (MODE == 0) {
                if (m0 < TDz * Bz) {
                    int orow = (m0 & 31) * TDz + (m0 >> 5);
                    float2 v;
                    v.x = acc[ma][nb][0] + b0v;
                    v.y = acc[ma][nb][1] + b1v;
                    *(float2*)(out + (size_t)orow * Nout + col) = v;
                }
                const int m1 = m0 + 8;
                if (m1 < TDz * Bz) {
                    int orow = (m1 & 31) * TDz + (m1 >> 5);
                    float2 v;
                    v.x = acc[ma][nb][2] + b0v;
                    v.y = acc[ma][nb][3] + b1v;
                    *(float2*)(out + (size_t)orow * Nout + col) = v;
                }
            } else {
                float2 v;
                v.x = acc[ma][nb][0] + b0v;
                v.y = acc[ma][nb][1] + b1v;
                *(float2*)(out + (size_t)m0 * Nout + col) = v;
                v.x = acc[ma][nb][2] + b0v;
                v.y = acc[ma][nb][3] + b1v;
                *(float2*)(out + (size_t)(m0 + 8) * Nout + col) = v;
            }
        }
    }
}

// ---------------- persistent LSTM: HMMA recurrence, single-fp16 smem weights ----------------
// smem layout (bytes); rows 2064B-strided (2048 data + 16 pad -> conflict-free ldmatrix)
#define ROWB   2064
#define SW     0
#define SH     66048
#define SGT    132096                 // float gates [32][33]
#define SPF    136320                 // float P [32*33]
#define SLAT   140544                 // latent scratch
#define SMEM_LSTM (140544 + 2048 + 1536 + 64)

__device__ __forceinline__ void load_whh_smem(const __half* __restrict__ WH,
                                              char* smp, int u0, int w, int lane) {
#pragma unroll
    for (int rr = 0; rr < 2; rr++) {
        int n = w + rr * 16;                       // smem row 0..31
        size_t grow = ((size_t)(n >> 3) * Hz + u0 + (n & 7)) * Hz;
#pragma unroll
        for (int j = 0; j < 4; j++) {
            *(uint4*)(smp + SW + n * ROWB + j * 512 + lane * 16) =
                *(const uint4*)(WH + grow + j * 256 + lane * 8);
        }
    }
}

// one LSTM step. gates = h @ Whh^T via HMMA; c fp32 in registers; h emitted fp16.
__device__ __forceinline__ float lstm_step_mma(
    char* smp, uint32_t sbase,
    const float* __restrict__ P, const __half* __restrict__ hin,
    __half* __restrict__ hout, float creg,
    int u0, int tid, int w, int lane)
{
    // 1) cp.async h tile (32 x 1024 fp16) into smem
    {
#pragma unroll
        for (int rr = 0; rr < 2; rr++) {
            int n = w + rr * 16;
#pragma unroll
            for (int j = 0; j < 4; j++) {
                CP_ASYNC16(sbase + SH + n * ROWB + j * 512 + lane * 16,
                           hin + (size_t)n * Hz + j * 256 + lane * 8);
            }
        }
        CP_COMMIT();
    }
    // 2) P prefetch
    {
        float* sPf = (float*)(smp + SPF);
#pragma unroll
        for (int k = 0; k < 2; k++) {
            int idx = tid + k * 512;
            int b = idx >> 5, c = idx & 31;
            sPf[b * 33 + c] = P[(size_t)b * Gz + (c >> 3) * Hz + u0 + (c & 7)];
        }
    }
    CP_WAIT0();
    __syncthreads();

    // 3) HMMA: warp -> (m-tile, n-tile, k-half)
    const int combo = w >> 1;
    const int mt = combo >> 2;       // 0..1
    const int nt = combo & 3;        // 0..3  (= gate index)
    const int kh = w & 1;

    float c4[4] = {0.f, 0.f, 0.f, 0.f};
    const uint32_t aBase = sbase + SH + (uint32_t)(mt * 16 + (lane & 15)) * ROWB +
                           (uint32_t)(lane >> 4) * 16;
    const uint32_t bRow = (uint32_t)(nt * 8 + (lane & 7)) * ROWB +
                          (uint32_t)((lane >> 3) & 1) * 16;

#pragma unroll 4
    for (int kt = kh * 32; kt < kh * 32 + 32; kt++) {
        const uint32_t ka = (uint32_t)kt * 32;
        uint32_t a[4];
        LDSM4(a, aBase + ka);
        uint32_t bh[2];
        LDSM2(bh, sbase + SW + bRow + ka);
        MMAH16816(c4, a, bh);
    }

    // 4) k-half reduction via gates smem
    float* gt = (float*)(smp + SGT);
    const int mrow = mt * 16 + (lane >> 2);
    const int ncol = nt * 8 + (lane & 3) * 2;
    if (kh == 1) {
        gt[mrow * 33 + ncol]           = c4[0];
        gt[mrow * 33 + ncol + 1]       = c4[1];
        gt[(mrow + 8) * 33 + ncol]     = c4[2];
        gt[(mrow + 8) * 33 + ncol + 1] = c4[3];
    }
    __syncthreads();
    if (kh == 0) {
        gt[mrow * 33 + ncol]           += c4[0];
        gt[mrow * 33 + ncol + 1]       += c4[1];
        gt[(mrow + 8) * 33 + ncol]     += c4[2];
        gt[(mrow + 8) * 33 + ncol + 1] += c4[3];
    }
    __syncthreads();

    // 5) epilogue: tid<256 -> (ul = tid&7, b = tid>>3)
    float newc = creg;
    if (tid < 256) {
        const float* sPf = (const float*)(smp + SPF);
        int ul = tid & 7, b = tid >> 3;
        float gi = gt[b * 33 +  0 + ul] + sPf[b * 33 +  0 + ul];
        float gf = gt[b * 33 +  8 + ul] + sPf[b * 33 +  8 + ul];
        float gg = gt[b * 33 + 16 + ul] + sPf[b * 33 + 16 + ul];
        float go = gt[b * 33 + 24 + ul] + sPf[b * 33 + 24 + ul];
        float cc = sigm(gf) * creg + sigm(gi) * tanhf(gg);
        float hh = sigm(go) * tanhf(cc);
        hout[b * Hz + u0 + ul] = __float2half_rn(hh);
        newc = cc;
    }
    return newc;
}

// latent head (fp16 h input), 512 threads
__device__ void latent_dev(int b, int tid, char* smp,
                           const int* __restrict__ tokens, const __half* __restrict__ hs,
                           const float* __restrict__ Wmu, const float* __restrict__ bmu,
                           const float* __restrict__ Wlv, const float* __restrict__ blv,
                           const float* __restrict__ eps,
                           const float* __restrict__ Wl2h, const float* __restrict__ bl2h,
                           float* __restrict__ out_mean, float* __restrict__ out_lv,
                           __half* __restrict__ hd0) {
    int* scnt    = (int*)(smp + SLAT);
    float* smean = (float*)(smp + SLAT + 2048);
    float* slv   = smean + 128;
    float* szv   = slv + 128;

    int cnt = 0;
    if (tid < Sz) cnt = (tokens[b * Sz + tid] != 0) ? 1 : 0;
    scnt[tid] = cnt;
    __syncthreads();
    for (int off = 256; off >= 1; off >>= 1) {
        if (tid < off) scnt[tid] += scnt[tid + off];
        __syncthreads();
    }
    int last = scnt[0] - 1;
    if (last < 0) last = 0;

    const __half* lh = hs + (size_t)(last + 1) * Bz * Hz + (size_t)b * Hz;
    if (tid < 256) {
        int j = tid & 127;
        const float* Wr = ((tid < 128) ? Wmu : Wlv) + (size_t)j * Hz;
        float acc = 0.f;
        const __half2* l2 = (const __half2*)lh;
        const float2* w2 = (const float2*)Wr;
#pragma unroll 4
        for (int k = 0; k < Hz / 2; k++) {
            float2 a = __half22float2(l2[k]);
            float2 ww = w2[k];
            acc += a.x * ww.x + a.y * ww.y;
        }
        if (tid < 128) smean[j] = acc + bmu[j];
        else           slv[j]   = acc + blv[j];
    }
    __syncthreads();

    if (tid < 128) {
        float m = smean[tid];
        float lv = slv[tid];
        out_mean[b * Lz + tid] = m;
        out_lv[b * Lz + tid] = lv;
        szv[tid] = m + eps[b * Lz + tid] * expf(0.5f * lv);
    }
    __syncthreads();

#pragma unroll
    for (int r = 0; r < 2; r++) {
        int u = tid + r * 512;
        float acc = bl2h[u];
        const float* wr = Wl2h + (size_t)u * Lz;
#pragma unroll 4
        for (int l = 0; l < Lz; l++) acc += szv[l] * wr[l];
        hd0[b * Hz + u] = __float2half_rn(acc);
    }
}

__global__ __launch_bounds__(512, 1)
void lstm_persistent(const __half* __restrict__ WeH, const __half* __restrict__ WdH,
                     const float* __restrict__ Pe, const float* __restrict__ Pd,
                     __half* __restrict__ Ahe, __half* __restrict__ Ahd,
                     const int* __restrict__ tokens,
                     const float* __restrict__ Wmu, const float* __restrict__ bmu,
                     const float* __restrict__ Wlv, const float* __restrict__ blv,
                     const float* __restrict__ eps,
                     const float* __restrict__ Wl2h, const float* __restrict__ bl2h,
                     float* __restrict__ out_mean, float* __restrict__ out_lv) {
    extern __shared__ char smp[];
    const uint32_t sbase = smem_u32(smp);
    const int tid = threadIdx.x;
    const int w = tid >> 5;
    const int lane = tid & 31;
    const int u0 = blockIdx.x * 8;

    load_whh_smem(WeH, smp, u0, w, lane);
    __syncthreads();

    float creg = 0.f;
    unsigned epoch = 0;

    for (int t = 0; t < Sz; t++) {
        creg = lstm_step_mma(smp, sbase, Pe + (size_t)t * Bz * Gz,
                             Ahe + (size_t)t * Bz * Hz,
                             Ahe + (size_t)(t + 1) * Bz * Hz,
                             creg, u0, tid, w, lane);
        epoch++;
        grid_sync_(epoch * NBLK);
    }

    load_whh_smem(WdH, smp, u0, w, lane);
    if (blockIdx.x < 32) {
        latent_dev(blockIdx.x, tid, smp, tokens, Ahe, Wmu, bmu, Wlv, blv, eps,
                   Wl2h, bl2h, out_mean, out_lv, Ahd);
    }
    epoch++;
    grid_sync_(epoch * NBLK);

    creg = 0.f;
    for (int t = 0; t < TDz; t++) {
        creg = lstm_step_mma(smp, sbase, Pd + (size_t)t * Bz * Gz,
                             Ahd + (size_t)t * Bz * Hz,
                             Ahd + (size_t)(t + 1) * Bz * Hz,
                             creg, u0, tid, w, lane);
        if (t < TDz - 1) {
            epoch++;
            grid_sync_(epoch * NBLK);
        }
    }
}

// ---------------- launch ----------------
extern "C" void kernel_launch(void* const* d_in, const int* in_sizes, int n_in,
                              void* d_out, int out_size) {
    const int*   tokens  = (const int*)d_in[0];
    const float* emb_enc = (const float*)d_in[1];
    const float* Wih_e   = (const float*)d_in[2];
    const float* Whh_e   = (const float*)d_in[3];
    const float* bih_e   = (const float*)d_in[4];
    const float* bhh_e   = (const float*)d_in[5];
    const float* W_mu    = (const float*)d_in[6];
    const float* b_mu    = (const float*)d_in[7];
    const float* W_lv    = (const float*)d_in[8];
    const float* b_lv    = (const float*)d_in[9];
    const float* emb_dec = (const float*)d_in[10];
    const float* W_l2h   = (const float*)d_in[11];
    const float* b_l2h   = (const float*)d_in[12];
    const float* Wih_d   = (const float*)d_in[13];
    const float* Whh_d   = (const float*)d_in[14];
    const float* bih_d   = (const float*)d_in[15];
    const float* bhh_d   = (const float*)d_in[16];
    const float* W_out   = (const float*)d_in[17];
    const float* b_out   = (const float*)d_in[18];
    const float* epsv    = (const float*)d_in[19];

    float* out = (float*)d_out;
    const size_t LOGITS = (size_t)Bz * TDz * Vz;
    float* out_logits = out;
    float* out_mean   = out + LOGITS;
    float* out_lv     = out + LOGITS + (size_t)Bz * Lz;

    float *p_Pe, *p_Pd;
    __half *p_Wh, *p_Ahe, *p_Ahd;
    __half *p_Xeh, *p_Xdh;
    __half *p_Wieh, *p_Widh;
    __half *p_WeH, *p_WdH;
    cudaGetSymbolAddress((void**)&p_Pe,  g_Pe);
    cudaGetSymbolAddress((void**)&p_Pd,  g_Pd);
    cudaGetSymbolAddress((void**)&p_Wh,  g_Wh);
    cudaGetSymbolAddress((void**)&p_Ahe, g_Ahe);
    cudaGetSymbolAddress((void**)&p_Ahd, g_Ahd);
    cudaGetSymbolAddress((void**)&p_Xeh, g_Xeh);
    cudaGetSymbolAddress((void**)&p_Xdh, g_Xdh);
    cudaGetSymbolAddress((void**)&p_Wieh, g_Wieh);
    cudaGetSymbolAddress((void**)&p_Widh, g_Widh);
    cudaGetSymbolAddress((void**)&p_WeH, g_WhheH);
    cudaGetSymbolAddress((void**)&p_WdH, g_WhhdH);

    cudaFuncSetAttribute(mma1_kernel<512, 1>, cudaFuncAttributeMaxDynamicSharedMemorySize, SMEM_MMA1);
    cudaFuncSetAttribute(mma1_kernel<1024, 0>, cudaFuncAttributeMaxDynamicSharedMemorySize, SMEM_MMA1);
    cudaFuncSetAttribute(lstm_persistent, cudaFuncAttributeMaxDynamicSharedMemorySize, SMEM_LSTM);

    // 1) reset grid barrier
    init_kernel<<<1, 32>>>();

    // 2) embeddings -> fp16
    embed_h_kernel<<<1024, 256>>>(tokens, emb_enc, p_Xeh, Sz, 0);
    embed_h_kernel<<<1024, 256>>>(tokens, emb_dec, p_Xdh, TDz, 1);

    // 2b) weight converts (all single fp16)
    convert_w_kernel<<<1024, 256>>>(Wih_e, p_Wieh, Gz * Ez / 4);
    convert_w_kernel<<<1024, 256>>>(Wih_d, p_Widh, Gz * Ez / 4);
    convert_w_kernel<<<1024, 256>>>(Whh_e, p_WeH, Gz * Hz / 4);
    convert_w_kernel<<<1024, 256>>>(Whh_d, p_WdH, Gz * Hz / 4);

    // 3) input projections via single-term fp16 mma (K=512)
    {
        dim3 grid(32, 32);
        mma1_kernel<512, 1><<<grid, 256, SMEM_MMA1>>>(p_Xeh, p_Wieh,
                                                      bih_e, bhh_e, p_Pe, Gz);
        mma1_kernel<512, 1><<<grid, 256, SMEM_MMA1>>>(p_Xdh, p_Widh,
                                                      bih_d, bhh_d, p_Pd, Gz);
    }

    // 3b) W_out fp16 convert
    convert_w_kernel<<<4096, 256>>>(W_out, p_Wh, (int)((size_t)Vz * Hz / 4));

    // 4+5+6) recurrences (HMMA, single-fp16 weights) + latent head
    lstm_persistent<<<NBLK, 512, SMEM_LSTM>>>(p_WeH, p_WdH,
                                              p_Pe, p_Pd, p_Ahe, p_Ahd,
                                              tokens, W_mu, b_mu, W_lv, b_lv, epsv,
                                              W_l2h, b_l2h, out_mean, out_lv);

    // 7) logits via single-term fp16 mma (K=1024); A = decoder h slots 1..126
    {
        dim3 grid(32, 250);
        mma1_kernel<1024, 0><<<grid, 256, SMEM_MMA1>>>(p_Ahd + (size_t)Bz * Hz, p_Wh,
                                                       b_out, b_out, out_logits, Vz);
    }
}